// round 2
// baseline (speedup 1.0000x reference)
#include <cuda_runtime.h>
#include <math.h>

// Problem constants
constexpr int B_   = 2;
constexpr int S_   = 2048;
constexpr int D_   = 2048;
constexpr int H_   = 32;
constexpr int HKV_ = 8;
constexpr int DH_  = 64;
constexpr int G_   = 4;
constexpr int M_   = B_ * S_;      // 4096 rows
constexpr int KVD_ = HKV_ * DH_;   // 512

// Scratch (allocation-free rule: __device__ globals)
__device__ float g_q[M_ * D_];     // 33.5 MB
__device__ float g_k[M_ * KVD_];   //  8.4 MB
__device__ float g_v[M_ * KVD_];   //  8.4 MB
__device__ float g_ctx[M_ * D_];   // 33.5 MB

// ---------------------------------------------------------------------------
// SGEMM: C[M,N] = A[M,K] @ W[K,N] + bias[N]
// 128x128 block tile, BK=16, 256 threads, 8x8 register tile per thread.
// ---------------------------------------------------------------------------
__global__ __launch_bounds__(256)
void sgemm_bias_kernel(const float* __restrict__ A, const float* __restrict__ W,
                       const float* __restrict__ bias, float* __restrict__ C,
                       int Mdim, int Ndim, int Kdim)
{
    constexpr int BM = 128, BN = 128, BK = 16;
    __shared__ float As[BK][BM + 4];   // stored transposed (k-major)
    __shared__ float Bs[BK][BN];

    const int tid = threadIdx.x;
    const int bm = blockIdx.y * BM;
    const int bn = blockIdx.x * BN;

    const int tr = tid / 16;          // 0..15  -> rows tr*8..tr*8+7
    const int tc = tid % 16;          // 0..15  -> cols tc*8..tc*8+7

    // A tile loads: 128 rows x 16 cols; each thread: 2x float4
    const int arow  = tid / 4;        // 0..63
    const int acol4 = (tid % 4) * 4;  // 0,4,8,12
    // B tile loads: 16 rows x 128 cols; each thread: 2x float4
    const int brow  = tid / 32;       // 0..7
    const int bcol4 = (tid % 32) * 4; // 0..124

    float acc[8][8];
    #pragma unroll
    for (int i = 0; i < 8; i++)
        #pragma unroll
        for (int j = 0; j < 8; j++) acc[i][j] = 0.0f;

    for (int k0 = 0; k0 < Kdim; k0 += BK) {
        #pragma unroll
        for (int it = 0; it < 2; ++it) {
            int r = arow + it * 64;
            float4 va = *reinterpret_cast<const float4*>(&A[(size_t)(bm + r) * Kdim + k0 + acol4]);
            As[acol4 + 0][r] = va.x;
            As[acol4 + 1][r] = va.y;
            As[acol4 + 2][r] = va.z;
            As[acol4 + 3][r] = va.w;
        }
        #pragma unroll
        for (int it = 0; it < 2; ++it) {
            int r = brow + it * 8;
            *reinterpret_cast<float4*>(&Bs[r][bcol4]) =
                *reinterpret_cast<const float4*>(&W[(size_t)(k0 + r) * Ndim + bn + bcol4]);
        }
        __syncthreads();

        #pragma unroll
        for (int k = 0; k < BK; ++k) {
            float ra[8], rb[8];
            #pragma unroll
            for (int i = 0; i < 8; i++) ra[i] = As[k][tr * 8 + i];
            #pragma unroll
            for (int j = 0; j < 8; j++) rb[j] = Bs[k][tc * 8 + j];
            #pragma unroll
            for (int i = 0; i < 8; i++)
                #pragma unroll
                for (int j = 0; j < 8; j++) acc[i][j] += ra[i] * rb[j];
        }
        __syncthreads();
    }

    #pragma unroll
    for (int i = 0; i < 8; i++) {
        int row = bm + tr * 8 + i;
        #pragma unroll
        for (int j = 0; j < 8; j += 4) {
            int col = bn + tc * 8 + j;
            float4 v;
            v.x = acc[i][j + 0] + bias[col + 0];
            v.y = acc[i][j + 1] + bias[col + 1];
            v.z = acc[i][j + 2] + bias[col + 2];
            v.w = acc[i][j + 3] + bias[col + 3];
            *reinterpret_cast<float4*>(&C[(size_t)row * Ndim + col]) = v;
        }
    }
}

// ---------------------------------------------------------------------------
// Flash attention (GQA): per block = one (b, head) x 64 query rows.
// Online softmax in exp2 domain. 256 threads, 4x4 patch per thread with
// stride-16 column mapping (conflict-free shared reads).
// ---------------------------------------------------------------------------
__global__ __launch_bounds__(256)
void gqa_attn_kernel()
{
    extern __shared__ float sm[];
    float* Qs  = sm;               // [64][65]  Qs[r][d]
    float* Kst = Qs  + 64 * 65;    // [64][65]  Kst[d][c]  (K transposed)
    float* Vs  = Kst + 64 * 65;    // [64][65]  Vs[c][d]
    float* Ps  = Vs  + 64 * 65;    // [64][65]  Ps[r][c]

    const int bh  = blockIdx.y;    // 0..63
    const int b   = bh / H_;
    const int h   = bh % H_;
    const int kvh = h / G_;
    const int m0  = blockIdx.x * 64;

    const int tid = threadIdx.x;
    const int ty  = tid / 16;      // row group: rows ty + 16*i
    const int tx  = tid % 16;      // col group: cols tx + 16*j

    // Load Q tile (coalesced; conflict-free shared writes)
    for (int e = tid; e < 64 * 64; e += 256) {
        int r = e >> 6, d = e & 63;
        Qs[r * 65 + d] = g_q[(size_t)(b * S_ + m0 + r) * D_ + h * DH_ + d];
    }

    float m_i[4], l_i[4], o[4][4];
    #pragma unroll
    for (int i = 0; i < 4; i++) {
        m_i[i] = -INFINITY;
        l_i[i] = 0.0f;
        #pragma unroll
        for (int j = 0; j < 4; j++) o[i][j] = 0.0f;
    }

    // scale * log2(e): softmax(s) == softmax2(s * log2e) with exp2
    const float sscale = 0.125f * 1.44269504088896f;

    for (int n0 = 0; n0 < S_; n0 += 64) {
        // Load K (transposed into Kst) and V
        for (int e = tid; e < 64 * 64; e += 256) {
            int c = e >> 6, d = e & 63;
            float kv = g_k[(size_t)(b * S_ + n0 + c) * KVD_ + kvh * DH_ + d];
            float vv = g_v[(size_t)(b * S_ + n0 + c) * KVD_ + kvh * DH_ + d];
            Kst[d * 65 + c] = kv;
            Vs[c * 65 + d]  = vv;
        }
        __syncthreads();

        // Scores: acc[i][j] = sum_d Q[r][d] * K[c][d]
        float acc[4][4];
        #pragma unroll
        for (int i = 0; i < 4; i++)
            #pragma unroll
            for (int j = 0; j < 4; j++) acc[i][j] = 0.0f;

        for (int d = 0; d < 64; ++d) {
            float qa[4], kb[4];
            #pragma unroll
            for (int i = 0; i < 4; i++) qa[i] = Qs[(ty + 16 * i) * 65 + d];
            #pragma unroll
            for (int j = 0; j < 4; j++) kb[j] = Kst[d * 65 + tx + 16 * j];
            #pragma unroll
            for (int i = 0; i < 4; i++)
                #pragma unroll
                for (int j = 0; j < 4; j++) acc[i][j] += qa[i] * kb[j];
        }

        // Online softmax per row (rows of one group live in 16 consecutive lanes)
        #pragma unroll
        for (int i = 0; i < 4; i++) {
            float mx = acc[i][0];
            #pragma unroll
            for (int j = 1; j < 4; j++) mx = fmaxf(mx, acc[i][j]);
            mx *= sscale;
            #pragma unroll
            for (int w = 8; w >= 1; w >>= 1)
                mx = fmaxf(mx, __shfl_xor_sync(0xffffffffu, mx, w));

            float mnew = fmaxf(m_i[i], mx);
            float corr = exp2f(m_i[i] - mnew);
            float rs = 0.0f;
            #pragma unroll
            for (int j = 0; j < 4; j++) {
                float p = exp2f(acc[i][j] * sscale - mnew);
                Ps[(ty + 16 * i) * 65 + tx + 16 * j] = p;
                rs += p;
            }
            #pragma unroll
            for (int w = 8; w >= 1; w >>= 1)
                rs += __shfl_xor_sync(0xffffffffu, rs, w);

            l_i[i] = l_i[i] * corr + rs;
            m_i[i] = mnew;
            #pragma unroll
            for (int j = 0; j < 4; j++) o[i][j] *= corr;
        }
        __syncthreads();

        // O += P @ V
        for (int c = 0; c < 64; ++c) {
            float pv[4], vv[4];
            #pragma unroll
            for (int i = 0; i < 4; i++) pv[i] = Ps[(ty + 16 * i) * 65 + c];
            #pragma unroll
            for (int j = 0; j < 4; j++) vv[j] = Vs[c * 65 + tx + 16 * j];
            #pragma unroll
            for (int i = 0; i < 4; i++)
                #pragma unroll
                for (int j = 0; j < 4; j++) o[i][j] += pv[i] * vv[j];
        }
        __syncthreads();
    }

    // Write context (merged head layout: col = h*DH + d)
    #pragma unroll
    for (int i = 0; i < 4; i++) {
        float inv_l = 1.0f / l_i[i];
        int row = b * S_ + m0 + ty + 16 * i;
        #pragma unroll
        for (int j = 0; j < 4; j++) {
            g_ctx[(size_t)row * D_ + h * DH_ + tx + 16 * j] = o[i][j] * inv_l;
        }
    }
}

// ---------------------------------------------------------------------------
// Launch
// ---------------------------------------------------------------------------
extern "C" void kernel_launch(void* const* d_in, const int* in_sizes, int n_in,
                              void* d_out, int out_size)
{
    const float* x  = (const float*)d_in[0];
    const float* Wq = (const float*)d_in[1];
    const float* bq = (const float*)d_in[2];
    const float* Wk = (const float*)d_in[3];
    const float* bk = (const float*)d_in[4];
    const float* Wv = (const float*)d_in[5];
    const float* bv = (const float*)d_in[6];
    const float* Wo = (const float*)d_in[7];
    const float* bo = (const float*)d_in[8];
    float* out = (float*)d_out;

    float *q, *k, *v, *ctx;
    cudaGetSymbolAddress((void**)&q,   g_q);
    cudaGetSymbolAddress((void**)&k,   g_k);
    cudaGetSymbolAddress((void**)&v,   g_v);
    cudaGetSymbolAddress((void**)&ctx, g_ctx);

    const size_t attn_smem = 4 * 64 * 65 * sizeof(float);  // 66,560 B
    cudaFuncSetAttribute(gqa_attn_kernel,
                         cudaFuncAttributeMaxDynamicSharedMemorySize,
                         (int)attn_smem);

    dim3 blk(256);

    // Q projection: [4096,2048] = x @ Wq + bq
    sgemm_bias_kernel<<<dim3(D_ / 128, M_ / 128), blk>>>(x, Wq, bq, q, M_, D_, D_);
    // K projection: [4096,512]
    sgemm_bias_kernel<<<dim3(KVD_ / 128, M_ / 128), blk>>>(x, Wk, bk, k, M_, KVD_, D_);
    // V projection: [4096,512]
    sgemm_bias_kernel<<<dim3(KVD_ / 128, M_ / 128), blk>>>(x, Wv, bv, v, M_, KVD_, D_);

    // Attention: grid (S/64 query tiles, B*H heads)
    gqa_attn_kernel<<<dim3(S_ / 64, B_ * H_), blk, attn_smem>>>();

    // Output projection: out = ctx @ Wo + bo
    sgemm_bias_kernel<<<dim3(D_ / 128, M_ / 128), blk>>>(ctx, Wo, bo, out, M_, D_, D_);
}

// round 4
// speedup vs baseline: 1.3321x; 1.3321x over previous
#include <cuda_runtime.h>
#include <cuda_bf16.h>
#include <cstdint>
#include <math.h>

// Problem constants
constexpr int B_   = 2;
constexpr int S_   = 2048;
constexpr int D_   = 2048;
constexpr int H_   = 32;
constexpr int HKV_ = 8;
constexpr int DH_  = 64;
constexpr int G_   = 4;
constexpr int M_   = B_ * S_;      // 4096 rows
constexpr int KVD_ = HKV_ * DH_;   // 512

// Scratch (__device__ globals: allocation-free rule)
__device__ float g_q[M_ * D_];
__device__ float g_k[M_ * KVD_];
__device__ float g_v[M_ * KVD_];
__device__ float g_ctx[M_ * D_];

// bf16 split (hi|lo along K) operands
__device__ __nv_bfloat16 g_xc  [M_   * 2 * D_];   // [4096][4096]
__device__ __nv_bfloat16 g_ctxc[M_   * 2 * D_];
__device__ __nv_bfloat16 g_wqt [D_   * 2 * D_];   // [2048][4096]  (N,K)-major
__device__ __nv_bfloat16 g_wkt [KVD_ * 2 * D_];   // [512][4096]
__device__ __nv_bfloat16 g_wvt [KVD_ * 2 * D_];
__device__ __nv_bfloat16 g_wot [D_   * 2 * D_];

__device__ __forceinline__ uint32_t smem_u32_of(const void* p) {
    uint32_t a;
    asm("{ .reg .u64 t; cvta.to.shared.u64 t, %1; cvt.u32.u64 %0, t; }" : "=r"(a) : "l"(p));
    return a;
}

// ---------------------------------------------------------------------------
// Conversion kernels (hi/lo bf16 split)
// ---------------------------------------------------------------------------
__global__ void convert_rows_kernel(const float* __restrict__ src,
                                    __nv_bfloat16* __restrict__ dst, int total, int K)
{
    for (int i = blockIdx.x * blockDim.x + threadIdx.x; i < total;
         i += gridDim.x * blockDim.x) {
        int m = i / K, k = i - m * K;
        float x = src[i];
        __nv_bfloat16 h = __float2bfloat16(x);
        float lo = x - __bfloat162float(h);
        dst[(size_t)m * 2 * K + k]     = h;
        dst[(size_t)m * 2 * K + K + k] = __float2bfloat16(lo);
    }
}

// W [K,N] f32 row-major  ->  Wt [N, 2K] bf16 (hi | lo)
__global__ void convert_transpose_kernel(const float* __restrict__ W,
                                         __nv_bfloat16* __restrict__ Wt, int K, int N)
{
    __shared__ float tile[32][33];
    int k0 = blockIdx.y * 32, n0 = blockIdx.x * 32;
    int tx = threadIdx.x, ty = threadIdx.y;          // (32, 8)
    #pragma unroll
    for (int dy = 0; dy < 32; dy += 8)
        tile[ty + dy][tx] = W[(size_t)(k0 + ty + dy) * N + n0 + tx];
    __syncthreads();
    #pragma unroll
    for (int dy = 0; dy < 32; dy += 8) {
        int n = n0 + ty + dy;
        float x = tile[tx][ty + dy];
        __nv_bfloat16 h = __float2bfloat16(x);
        Wt[(size_t)n * 2 * K + k0 + tx]     = h;
        Wt[(size_t)n * 2 * K + K + k0 + tx] = __float2bfloat16(x - __bfloat162float(h));
    }
}

// ---------------------------------------------------------------------------
// HMMA GEMM: C[4096, Ndim] = A'(split) @ Wt'(split)^T + bias
// mma.sync m16n8k16 bf16. CTA 128x128, 8 warps (2x4), warp tile 64x32.
// BK=32, 4-stage cp.async pipeline. K' = 3*2048 = 6144 (split-3 scheme).
// ---------------------------------------------------------------------------
constexpr int GSTAGES    = 4;
constexpr int A_ROW_B    = 80;                  // 64B data + 16B pad per 32-elem row
constexpr int TILE_B     = 128 * A_ROW_B;       // 10240
constexpr int STAGE_B    = 2 * TILE_B;          // A + B = 20480
constexpr int GEMM_SMEM  = GSTAGES * STAGE_B;   // 81920
constexpr int GEMM_NKC   = 192;                 // 6144 / 32

__device__ __forceinline__ void ldsm_x4(uint32_t (&r)[4], uint32_t addr) {
    asm volatile("ldmatrix.sync.aligned.m8n8.x4.shared.b16 {%0,%1,%2,%3}, [%4];"
                 : "=r"(r[0]), "=r"(r[1]), "=r"(r[2]), "=r"(r[3]) : "r"(addr));
}
__device__ __forceinline__ void mma16816(float (&c)[4], const uint32_t (&a)[4],
                                         uint32_t b0, uint32_t b1) {
    asm volatile(
        "mma.sync.aligned.m16n8k16.row.col.f32.bf16.bf16.f32 "
        "{%0,%1,%2,%3}, {%4,%5,%6,%7}, {%8,%9}, {%0,%1,%2,%3};"
        : "+f"(c[0]), "+f"(c[1]), "+f"(c[2]), "+f"(c[3])
        : "r"(a[0]), "r"(a[1]), "r"(a[2]), "r"(a[3]), "r"(b0), "r"(b1));
}

__global__ __launch_bounds__(256, 1)
void gemm_mma_kernel(const __nv_bfloat16* __restrict__ A,
                     const __nv_bfloat16* __restrict__ Bt,
                     const float* __restrict__ bias,
                     float* __restrict__ C, int Ndim)
{
    extern __shared__ __align__(128) char smem[];
    const uint32_t smem_b = smem_u32_of(smem);
    const int tid  = threadIdx.x;
    const int lane = tid & 31, wid = tid >> 5;
    const int warp_m = wid & 1;        // 0..1 -> 64 rows each
    const int warp_n = wid >> 1;       // 0..3 -> 32 cols each
    const int bm = blockIdx.y * 128;
    const int bn = blockIdx.x * 128;

    float acc[4][4][4];
    #pragma unroll
    for (int i = 0; i < 4; i++)
        #pragma unroll
        for (int j = 0; j < 4; j++)
            #pragma unroll
            for (int e = 0; e < 4; e++) acc[i][j][e] = 0.0f;

    auto load_stage = [&](int kc) {
        int slot = kc & (GSTAGES - 1);
        int seg = kc / 64, within = (kc & 63) * 32;
        int a_col = within + ((seg == 1) ? 2048 : 0);   // seg0,2: hi ; seg1: lo
        int w_col = within + ((seg == 2) ? 2048 : 0);   // seg0,1: hi ; seg2: lo
        uint32_t sA = smem_b + slot * STAGE_B;
        uint32_t sB = sA + TILE_B;
        #pragma unroll
        for (int it = 0; it < 2; it++) {
            int idx = tid + it * 256;                    // 512 chunks
            int r = idx >> 2, c = idx & 3;
            const void* ga = A  + (size_t)(bm + r) * 4096 + a_col + c * 8;
            const void* gb = Bt + (size_t)(bn + r) * 4096 + w_col + c * 8;
            uint32_t so = r * A_ROW_B + c * 16;
            asm volatile("cp.async.cg.shared.global [%0], [%1], 16;"
                         :: "r"(sA + so), "l"(ga));
            asm volatile("cp.async.cg.shared.global [%0], [%1], 16;"
                         :: "r"(sB + so), "l"(gb));
        }
    };

    #pragma unroll
    for (int s = 0; s < GSTAGES - 1; s++) {
        load_stage(s);
        asm volatile("cp.async.commit_group;");
    }

    // ldmatrix lane addressing (constant across iters)
    const int a_row_in = lane & 15;            // row within 16-row frag
    const int a_ksel   = (lane >> 4) * 16;     // +0 / +16 bytes (k 0/8)
    const int b_sel    = (lane >> 3) & 3;
    const int b_row_in = ((b_sel >> 1) << 3) + (lane & 7);  // n within 16
    const int b_ksel   = (b_sel & 1) * 16;                  // +0 / +16 bytes

    for (int kc = 0; kc < GEMM_NKC; kc++) {
        asm volatile("cp.async.wait_group %0;" :: "n"(GSTAGES - 2));
        __syncthreads();
        if (kc + GSTAGES - 1 < GEMM_NKC) load_stage(kc + GSTAGES - 1);
        asm volatile("cp.async.commit_group;");

        int slot = kc & (GSTAGES - 1);
        uint32_t sA = smem_b + slot * STAGE_B + (warp_m * 64) * A_ROW_B;
        uint32_t sB = smem_b + slot * STAGE_B + TILE_B + (warp_n * 32) * A_ROW_B;

        #pragma unroll
        for (int kk = 0; kk < 2; kk++) {               // two k16 per BK=32
            uint32_t kbyte = kk * 32;
            uint32_t afr[4][4];
            #pragma unroll
            for (int fm = 0; fm < 4; fm++)
                ldsm_x4(afr[fm], sA + (fm * 16 + a_row_in) * A_ROW_B + kbyte + a_ksel);
            #pragma unroll
            for (int fn2 = 0; fn2 < 2; fn2++) {        // n 0-15 / 16-31
                uint32_t bfr[4];
                ldsm_x4(bfr, sB + (fn2 * 16 + b_row_in) * A_ROW_B + kbyte + b_ksel);
                #pragma unroll
                for (int fm = 0; fm < 4; fm++) {
                    mma16816(acc[fm][fn2 * 2 + 0], afr[fm], bfr[0], bfr[1]);
                    mma16816(acc[fm][fn2 * 2 + 1], afr[fm], bfr[2], bfr[3]);
                }
            }
        }
    }

    // Epilogue: registers -> gmem with bias
    const int row0 = bm + warp_m * 64 + (lane >> 2);
    const int col0 = bn + warp_n * 32 + (lane & 3) * 2;
    #pragma unroll
    for (int fm = 0; fm < 4; fm++) {
        #pragma unroll
        for (int fn = 0; fn < 4; fn++) {
            int c = col0 + fn * 8;
            float b0 = bias[c], b1 = bias[c + 1];
            int r0 = row0 + fm * 16;
            float2 v0 = make_float2(acc[fm][fn][0] + b0, acc[fm][fn][1] + b1);
            float2 v1 = make_float2(acc[fm][fn][2] + b0, acc[fm][fn][3] + b1);
            *(float2*)(C + (size_t)r0 * Ndim + c)       = v0;
            *(float2*)(C + (size_t)(r0 + 8) * Ndim + c) = v1;
        }
    }
}

// ---------------------------------------------------------------------------
// Flash attention (GQA), fp32 SIMT (unchanged; next round's target)
// ---------------------------------------------------------------------------
__global__ __launch_bounds__(256)
void gqa_attn_kernel()
{
    extern __shared__ float sm[];
    float* Qs  = sm;
    float* Kst = Qs  + 64 * 65;
    float* Vs  = Kst + 64 * 65;
    float* Ps  = Vs  + 64 * 65;

    const int bh  = blockIdx.y;
    const int b   = bh / H_;
    const int h   = bh % H_;
    const int kvh = h / G_;
    const int m0  = blockIdx.x * 64;

    const int tid = threadIdx.x;
    const int ty  = tid / 16;
    const int tx  = tid % 16;

    for (int e = tid; e < 64 * 64; e += 256) {
        int r = e >> 6, d = e & 63;
        Qs[r * 65 + d] = g_q[(size_t)(b * S_ + m0 + r) * D_ + h * DH_ + d];
    }

    float m_i[4], l_i[4], o[4][4];
    #pragma unroll
    for (int i = 0; i < 4; i++) {
        m_i[i] = -INFINITY;
        l_i[i] = 0.0f;
        #pragma unroll
        for (int j = 0; j < 4; j++) o[i][j] = 0.0f;
    }

    const float sscale = 0.125f * 1.44269504088896f;

    for (int n0 = 0; n0 < S_; n0 += 64) {
        for (int e = tid; e < 64 * 64; e += 256) {
            int c = e >> 6, d = e & 63;
            float kv = g_k[(size_t)(b * S_ + n0 + c) * KVD_ + kvh * DH_ + d];
            float vv = g_v[(size_t)(b * S_ + n0 + c) * KVD_ + kvh * DH_ + d];
            Kst[d * 65 + c] = kv;
            Vs[c * 65 + d]  = vv;
        }
        __syncthreads();

        float acc[4][4];
        #pragma unroll
        for (int i = 0; i < 4; i++)
            #pragma unroll
            for (int j = 0; j < 4; j++) acc[i][j] = 0.0f;

        for (int d = 0; d < 64; ++d) {
            float qa[4], kb[4];
            #pragma unroll
            for (int i = 0; i < 4; i++) qa[i] = Qs[(ty + 16 * i) * 65 + d];
            #pragma unroll
            for (int j = 0; j < 4; j++) kb[j] = Kst[d * 65 + tx + 16 * j];
            #pragma unroll
            for (int i = 0; i < 4; i++)
                #pragma unroll
                for (int j = 0; j < 4; j++) acc[i][j] += qa[i] * kb[j];
        }

        #pragma unroll
        for (int i = 0; i < 4; i++) {
            float mx = acc[i][0];
            #pragma unroll
            for (int j = 1; j < 4; j++) mx = fmaxf(mx, acc[i][j]);
            mx *= sscale;
            #pragma unroll
            for (int w = 8; w >= 1; w >>= 1)
                mx = fmaxf(mx, __shfl_xor_sync(0xffffffffu, mx, w));

            float mnew = fmaxf(m_i[i], mx);
            float corr = exp2f(m_i[i] - mnew);
            float rs = 0.0f;
            #pragma unroll
            for (int j = 0; j < 4; j++) {
                float p = exp2f(acc[i][j] * sscale - mnew);
                Ps[(ty + 16 * i) * 65 + tx + 16 * j] = p;
                rs += p;
            }
            #pragma unroll
            for (int w = 8; w >= 1; w >>= 1)
                rs += __shfl_xor_sync(0xffffffffu, rs, w);

            l_i[i] = l_i[i] * corr + rs;
            m_i[i] = mnew;
            #pragma unroll
            for (int j = 0; j < 4; j++) o[i][j] *= corr;
        }
        __syncthreads();

        for (int c = 0; c < 64; ++c) {
            float pv[4], vv[4];
            #pragma unroll
            for (int i = 0; i < 4; i++) pv[i] = Ps[(ty + 16 * i) * 65 + c];
            #pragma unroll
            for (int j = 0; j < 4; j++) vv[j] = Vs[c * 65 + tx + 16 * j];
            #pragma unroll
            for (int i = 0; i < 4; i++)
                #pragma unroll
                for (int j = 0; j < 4; j++) o[i][j] += pv[i] * vv[j];
        }
        __syncthreads();
    }

    #pragma unroll
    for (int i = 0; i < 4; i++) {
        float inv_l = 1.0f / l_i[i];
        int row = b * S_ + m0 + ty + 16 * i;
        #pragma unroll
        for (int j = 0; j < 4; j++)
            g_ctx[(size_t)row * D_ + h * DH_ + tx + 16 * j] = o[i][j] * inv_l;
    }
}

// ---------------------------------------------------------------------------
// Launch
// ---------------------------------------------------------------------------
extern "C" void kernel_launch(void* const* d_in, const int* in_sizes, int n_in,
                              void* d_out, int out_size)
{
    const float* x  = (const float*)d_in[0];
    const float* Wq = (const float*)d_in[1];
    const float* bq = (const float*)d_in[2];
    const float* Wk = (const float*)d_in[3];
    const float* bk = (const float*)d_in[4];
    const float* Wv = (const float*)d_in[5];
    const float* bv = (const float*)d_in[6];
    const float* Wo = (const float*)d_in[7];
    const float* bo = (const float*)d_in[8];
    float* out = (float*)d_out;

    float *q, *k, *v, *ctx;
    __nv_bfloat16 *xc, *ctxc, *wqt, *wkt, *wvt, *wot;
    cudaGetSymbolAddress((void**)&q,    g_q);
    cudaGetSymbolAddress((void**)&k,    g_k);
    cudaGetSymbolAddress((void**)&v,    g_v);
    cudaGetSymbolAddress((void**)&ctx,  g_ctx);
    cudaGetSymbolAddress((void**)&xc,   g_xc);
    cudaGetSymbolAddress((void**)&ctxc, g_ctxc);
    cudaGetSymbolAddress((void**)&wqt,  g_wqt);
    cudaGetSymbolAddress((void**)&wkt,  g_wkt);
    cudaGetSymbolAddress((void**)&wvt,  g_wvt);
    cudaGetSymbolAddress((void**)&wot,  g_wot);

    cudaFuncSetAttribute(gemm_mma_kernel,
                         cudaFuncAttributeMaxDynamicSharedMemorySize, GEMM_SMEM);
    const size_t attn_smem = 4 * 64 * 65 * sizeof(float);
    cudaFuncSetAttribute(gqa_attn_kernel,
                         cudaFuncAttributeMaxDynamicSharedMemorySize, (int)attn_smem);

    // hi/lo conversions
    convert_rows_kernel<<<2048, 256>>>(x, xc, M_ * D_, D_);
    convert_transpose_kernel<<<dim3(D_ / 32,   D_ / 32), dim3(32, 8)>>>(Wq, wqt, D_, D_);
    convert_transpose_kernel<<<dim3(KVD_ / 32, D_ / 32), dim3(32, 8)>>>(Wk, wkt, D_, KVD_);
    convert_transpose_kernel<<<dim3(KVD_ / 32, D_ / 32), dim3(32, 8)>>>(Wv, wvt, D_, KVD_);
    convert_transpose_kernel<<<dim3(D_ / 32,   D_ / 32), dim3(32, 8)>>>(Wo, wot, D_, D_);

    // projections on tensor cores (HMMA)
    gemm_mma_kernel<<<dim3(D_ / 128,   M_ / 128), 256, GEMM_SMEM>>>(xc, wqt, bq, q, D_);
    gemm_mma_kernel<<<dim3(KVD_ / 128, M_ / 128), 256, GEMM_SMEM>>>(xc, wkt, bk, k, KVD_);
    gemm_mma_kernel<<<dim3(KVD_ / 128, M_ / 128), 256, GEMM_SMEM>>>(xc, wvt, bv, v, KVD_);

    // attention
    gqa_attn_kernel<<<dim3(S_ / 64, B_ * H_), 256, attn_smem>>>();

    // output projection
    convert_rows_kernel<<<2048, 256>>>(ctx, ctxc, M_ * D_, D_);
    gemm_mma_kernel<<<dim3(D_ / 128, M_ / 128), 256, GEMM_SMEM>>>(ctxc, wot, bo, out, D_);
}

// round 6
// speedup vs baseline: 2.4668x; 1.8518x over previous
#include <cuda_runtime.h>
#include <cuda_bf16.h>
#include <cuda_fp16.h>
#include <cstdint>
#include <math.h>

// Problem constants
constexpr int B_   = 2;
constexpr int S_   = 2048;
constexpr int D_   = 2048;
constexpr int H_   = 32;
constexpr int HKV_ = 8;
constexpr int DH_  = 64;
constexpr int G_   = 4;
constexpr int M_   = B_ * S_;      // 4096 rows
constexpr int KVD_ = HKV_ * DH_;   // 512

// Scratch (__device__ globals: allocation-free rule)
__device__ float g_q[M_ * D_];
__device__ float g_k[M_ * KVD_];
__device__ float g_v[M_ * KVD_];
__device__ float g_ctx[M_ * D_];

// bf16 split (hi|lo along K) GEMM operands
__device__ __nv_bfloat16 g_xc  [M_   * 2 * D_];
__device__ __nv_bfloat16 g_ctxc[M_   * 2 * D_];
__device__ __nv_bfloat16 g_wqt [D_   * 2 * D_];
__device__ __nv_bfloat16 g_wkt [KVD_ * 2 * D_];
__device__ __nv_bfloat16 g_wvt [KVD_ * 2 * D_];
__device__ __nv_bfloat16 g_wot [KVD_ * 0 + D_ * 2 * D_];

// attention operands
__device__ __nv_bfloat16 g_qb[B_ * H_   * S_ * 128];      // [b,h][m][hi64|lo64] bf16
__device__ __nv_bfloat16 g_kb[B_ * HKV_ * S_ * 128];      // [b,kvh][n][hi64|lo64] bf16
__device__ __half        g_vt[B_ * HKV_ * 64 * 2 * S_];   // [b,kvh][d][hi: n=0..S | lo: S..2S] fp16

__device__ __forceinline__ uint32_t smem_u32_of(const void* p) {
    uint32_t a;
    asm("{ .reg .u64 t; cvta.to.shared.u64 t, %1; cvt.u32.u64 %0, t; }" : "=r"(a) : "l"(p));
    return a;
}
__device__ __forceinline__ void ldsm_x4(uint32_t (&r)[4], uint32_t addr) {
    asm volatile("ldmatrix.sync.aligned.m8n8.x4.shared.b16 {%0,%1,%2,%3}, [%4];"
                 : "=r"(r[0]), "=r"(r[1]), "=r"(r[2]), "=r"(r[3]) : "r"(addr));
}
__device__ __forceinline__ void mma16816(float (&c)[4], const uint32_t (&a)[4],
                                         uint32_t b0, uint32_t b1) {
    asm volatile(
        "mma.sync.aligned.m16n8k16.row.col.f32.bf16.bf16.f32 "
        "{%0,%1,%2,%3}, {%4,%5,%6,%7}, {%8,%9}, {%0,%1,%2,%3};"
        : "+f"(c[0]), "+f"(c[1]), "+f"(c[2]), "+f"(c[3])
        : "r"(a[0]), "r"(a[1]), "r"(a[2]), "r"(a[3]), "r"(b0), "r"(b1));
}
__device__ __forceinline__ void mma16816h(float (&c)[4], const uint32_t (&a)[4],
                                          uint32_t b0, uint32_t b1) {
    asm volatile(
        "mma.sync.aligned.m16n8k16.row.col.f32.f16.f16.f32 "
        "{%0,%1,%2,%3}, {%4,%5,%6,%7}, {%8,%9}, {%0,%1,%2,%3};"
        : "+f"(c[0]), "+f"(c[1]), "+f"(c[2]), "+f"(c[3])
        : "r"(a[0]), "r"(a[1]), "r"(a[2]), "r"(a[3]), "r"(b0), "r"(b1));
}
__device__ __forceinline__ void cp16(uint32_t dst, const void* src) {
    asm volatile("cp.async.cg.shared.global [%0], [%1], 16;" :: "r"(dst), "l"(src));
}

// ---------------------------------------------------------------------------
// Conversion kernels
// ---------------------------------------------------------------------------
__global__ void convert_rows_kernel(const float* __restrict__ src,
                                    __nv_bfloat16* __restrict__ dst, int total, int K)
{
    for (int i = blockIdx.x * blockDim.x + threadIdx.x; i < total;
         i += gridDim.x * blockDim.x) {
        int m = i / K, k = i - m * K;
        float x = src[i];
        __nv_bfloat16 h = __float2bfloat16(x);
        float lo = x - __bfloat162float(h);
        dst[(size_t)m * 2 * K + k]     = h;
        dst[(size_t)m * 2 * K + K + k] = __float2bfloat16(lo);
    }
}

__global__ void convert_transpose_kernel(const float* __restrict__ W,
                                         __nv_bfloat16* __restrict__ Wt, int K, int N)
{
    __shared__ float tile[32][33];
    int k0 = blockIdx.y * 32, n0 = blockIdx.x * 32;
    int tx = threadIdx.x, ty = threadIdx.y;
    #pragma unroll
    for (int dy = 0; dy < 32; dy += 8)
        tile[ty + dy][tx] = W[(size_t)(k0 + ty + dy) * N + n0 + tx];
    __syncthreads();
    #pragma unroll
    for (int dy = 0; dy < 32; dy += 8) {
        int n = n0 + ty + dy;
        float x = tile[tx][ty + dy];
        __nv_bfloat16 h = __float2bfloat16(x);
        Wt[(size_t)n * 2 * K + k0 + tx]     = h;
        Wt[(size_t)n * 2 * K + K + k0 + tx] = __float2bfloat16(x - __bfloat162float(h));
    }
}

__global__ void convert_qb_kernel()
{
    int total = B_ * H_ * S_ * 64;
    for (int i = blockIdx.x * blockDim.x + threadIdx.x; i < total;
         i += gridDim.x * blockDim.x) {
        int d = i & 63, rest = i >> 6;
        int m = rest & (S_ - 1);
        int bh = rest >> 11;
        int b = bh >> 5, h = bh & 31;
        float x = g_q[((size_t)(b * S_ + m)) * D_ + h * 64 + d];
        __nv_bfloat16 hi = __float2bfloat16(x);
        g_qb[((size_t)bh * S_ + m) * 128 + d]      = hi;
        g_qb[((size_t)bh * S_ + m) * 128 + 64 + d] =
            __float2bfloat16(x - __bfloat162float(hi));
    }
}

__global__ void convert_kb_kernel()
{
    int total = B_ * HKV_ * S_ * 64;
    for (int i = blockIdx.x * blockDim.x + threadIdx.x; i < total;
         i += gridDim.x * blockDim.x) {
        int d = i & 63, rest = i >> 6;
        int n = rest & (S_ - 1);
        int bk = rest >> 11;
        int b = bk >> 3, kvh = bk & 7;
        float x = g_k[((size_t)(b * S_ + n)) * KVD_ + kvh * 64 + d];
        __nv_bfloat16 hi = __float2bfloat16(x);
        g_kb[((size_t)bk * S_ + n) * 128 + d]      = hi;
        g_kb[((size_t)bk * S_ + n) * 128 + 64 + d] =
            __float2bfloat16(x - __bfloat162float(hi));
    }
}

// g_v f32 [b*S+n][kvh*64+d] -> g_vt fp16 [bk][d][hi: n | lo: S+n]  (transpose + split-2)
__global__ void convert_vt_kernel()
{
    __shared__ float tile[32][33];
    int n0 = blockIdx.x * 32, d0 = blockIdx.y * 32;
    int bk = blockIdx.z;
    int b = bk >> 3, kvh = bk & 7;
    int tx = threadIdx.x, ty = threadIdx.y;
    #pragma unroll
    for (int dy = 0; dy < 32; dy += 8)
        tile[ty + dy][tx] = g_v[((size_t)(b * S_ + n0 + ty + dy)) * KVD_ + kvh * 64 + d0 + tx];
    __syncthreads();
    #pragma unroll
    for (int dy = 0; dy < 32; dy += 8) {
        int d = d0 + ty + dy;
        float x = tile[tx][ty + dy];
        __half hi = __float2half_rn(x);
        size_t base = ((size_t)bk * 64 + d) * (2 * S_);
        g_vt[base + n0 + tx]      = hi;
        g_vt[base + S_ + n0 + tx] = __float2half_rn(x - __half2float(hi));
    }
}

// ---------------------------------------------------------------------------
// HMMA GEMM (validated R4)
// ---------------------------------------------------------------------------
constexpr int GSTAGES    = 4;
constexpr int A_ROW_B    = 80;
constexpr int TILE_B     = 128 * A_ROW_B;
constexpr int STAGE_B    = 2 * TILE_B;
constexpr int GEMM_SMEM  = GSTAGES * STAGE_B;   // 81920
constexpr int GEMM_NKC   = 192;

__global__ __launch_bounds__(256, 1)
void gemm_mma_kernel(const __nv_bfloat16* __restrict__ A,
                     const __nv_bfloat16* __restrict__ Bt,
                     const float* __restrict__ bias,
                     float* __restrict__ C, int Ndim)
{
    extern __shared__ __align__(128) char smem[];
    const uint32_t smem_b = smem_u32_of(smem);
    const int tid  = threadIdx.x;
    const int lane = tid & 31, wid = tid >> 5;
    const int warp_m = wid & 1;
    const int warp_n = wid >> 1;
    const int bm = blockIdx.y * 128;
    const int bn = blockIdx.x * 128;

    float acc[4][4][4];
    #pragma unroll
    for (int i = 0; i < 4; i++)
        #pragma unroll
        for (int j = 0; j < 4; j++)
            #pragma unroll
            for (int e = 0; e < 4; e++) acc[i][j][e] = 0.0f;

    auto load_stage = [&](int kc) {
        int slot = kc & (GSTAGES - 1);
        int seg = kc / 64, within = (kc & 63) * 32;
        int a_col = within + ((seg == 1) ? 2048 : 0);
        int w_col = within + ((seg == 2) ? 2048 : 0);
        uint32_t sA = smem_b + slot * STAGE_B;
        uint32_t sB = sA + TILE_B;
        #pragma unroll
        for (int it = 0; it < 2; it++) {
            int idx = tid + it * 256;
            int r = idx >> 2, c = idx & 3;
            cp16(sA + r * A_ROW_B + c * 16, A  + (size_t)(bm + r) * 4096 + a_col + c * 8);
            cp16(sB + r * A_ROW_B + c * 16, Bt + (size_t)(bn + r) * 4096 + w_col + c * 8);
        }
    };

    #pragma unroll
    for (int s = 0; s < GSTAGES - 1; s++) {
        load_stage(s);
        asm volatile("cp.async.commit_group;");
    }

    const int a_row_in = lane & 15;
    const int a_ksel   = (lane >> 4) * 16;
    const int b_sel    = (lane >> 3) & 3;
    const int b_row_in = ((b_sel >> 1) << 3) + (lane & 7);
    const int b_ksel   = (b_sel & 1) * 16;

    for (int kc = 0; kc < GEMM_NKC; kc++) {
        asm volatile("cp.async.wait_group %0;" :: "n"(GSTAGES - 2));
        __syncthreads();
        if (kc + GSTAGES - 1 < GEMM_NKC) load_stage(kc + GSTAGES - 1);
        asm volatile("cp.async.commit_group;");

        int slot = kc & (GSTAGES - 1);
        uint32_t sA = smem_b + slot * STAGE_B + (warp_m * 64) * A_ROW_B;
        uint32_t sB = smem_b + slot * STAGE_B + TILE_B + (warp_n * 32) * A_ROW_B;

        #pragma unroll
        for (int kk = 0; kk < 2; kk++) {
            uint32_t kbyte = kk * 32;
            uint32_t afr[4][4];
            #pragma unroll
            for (int fm = 0; fm < 4; fm++)
                ldsm_x4(afr[fm], sA + (fm * 16 + a_row_in) * A_ROW_B + kbyte + a_ksel);
            #pragma unroll
            for (int fn2 = 0; fn2 < 2; fn2++) {
                uint32_t bfr[4];
                ldsm_x4(bfr, sB + (fn2 * 16 + b_row_in) * A_ROW_B + kbyte + b_ksel);
                #pragma unroll
                for (int fm = 0; fm < 4; fm++) {
                    mma16816(acc[fm][fn2 * 2 + 0], afr[fm], bfr[0], bfr[1]);
                    mma16816(acc[fm][fn2 * 2 + 1], afr[fm], bfr[2], bfr[3]);
                }
            }
        }
    }

    const int row0 = bm + warp_m * 64 + (lane >> 2);
    const int col0 = bn + warp_n * 32 + (lane & 3) * 2;
    #pragma unroll
    for (int fm = 0; fm < 4; fm++) {
        #pragma unroll
        for (int fn = 0; fn < 4; fn++) {
            int c = col0 + fn * 8;
            float b0 = bias[c], b1 = bias[c + 1];
            int r0 = row0 + fm * 16;
            float2 v0 = make_float2(acc[fm][fn][0] + b0, acc[fm][fn][1] + b1);
            float2 v1 = make_float2(acc[fm][fn][2] + b0, acc[fm][fn][3] + b1);
            *(float2*)(C + (size_t)r0 * Ndim + c)       = v0;
            *(float2*)(C + (size_t)(r0 + 8) * Ndim + c) = v1;
        }
    }
}

// ---------------------------------------------------------------------------
// Flash attention on mma.sync. CTA = 128 q-rows x (b,h). 8 warps x 16 rows.
// QK: bf16 split-3 (exact scores). PV: P fp16, V fp16 split-2 (V exact).
// ---------------------------------------------------------------------------
constexpr int ANB     = S_ / 64;        // 32 k-blocks
constexpr int QROW    = 272;
constexpr int KROW    = 272;
constexpr int VROW    = 144;
constexpr int QBYTES  = 128 * QROW;     // 34816
constexpr int KTILE   = 64 * KROW;      // 17408
constexpr int VTILE   = 128 * VROW;     // 18432 (hi rows 0-63, lo rows 64-127)
constexpr int ASTG    = KTILE + VTILE;  // 35840
constexpr int ATT_SMEM = QBYTES + 3 * ASTG;  // 142336

__global__ __launch_bounds__(256)
void attn_mma_kernel()
{
    extern __shared__ __align__(128) char smem[];
    const uint32_t sb = smem_u32_of(smem);
    const int tid  = threadIdx.x;
    const int lane = tid & 31, wid = tid >> 5;

    const int bh  = blockIdx.y;
    const int b   = bh >> 5;
    const int h   = bh & 31;
    const int kvh = h >> 2;
    const int bk  = b * HKV_ + kvh;
    const int m0  = blockIdx.x * 128;

    const __nv_bfloat16* qbase = g_qb + ((size_t)bh * S_ + m0) * 128;
    const __nv_bfloat16* kbase = g_kb + ((size_t)bk * S_) * 128;
    const __half*        vbase = g_vt + ((size_t)bk * 64) * (size_t)(2 * S_);

    #pragma unroll
    for (int it = 0; it < 8; it++) {
        int idx = tid + it * 256;
        int r = idx >> 4, c = idx & 15;
        cp16(sb + r * QROW + c * 16, qbase + (size_t)r * 128 + c * 8);
    }
    asm volatile("cp.async.commit_group;");

    auto load_stage = [&](int kbi) {
        int slot = kbi % 3;
        int n0 = kbi * 64;
        uint32_t sK = sb + QBYTES + slot * ASTG;
        uint32_t sV = sK + KTILE;
        #pragma unroll
        for (int it = 0; it < 4; it++) {
            int idx = tid + it * 256;
            int r = idx >> 4, c = idx & 15;
            cp16(sK + r * KROW + c * 16, kbase + (size_t)(n0 + r) * 128 + c * 8);
        }
        #pragma unroll
        for (int it = 0; it < 4; it++) {
            int idx = tid + it * 256;             // 1024 chunks: hi rows 0-63, lo 64-127
            int r = idx >> 3, c = idx & 7;
            const __half* src = vbase + (size_t)(r & 63) * (2 * S_)
                                + ((r >> 6) ? S_ : 0) + n0 + c * 8;
            cp16(sV + r * VROW + c * 16, src);
        }
    };
    load_stage(0); asm volatile("cp.async.commit_group;");
    load_stage(1); asm volatile("cp.async.commit_group;");

    asm volatile("cp.async.wait_group 2;");
    __syncthreads();

    const int a_row_in = lane & 15;
    const int a_ksel   = (lane >> 4) * 16;
    const int b_sel    = (lane >> 3) & 3;
    const int b_row_in = ((b_sel >> 1) << 3) + (lane & 7);
    const int b_ksel   = (b_sel & 1) * 16;

    uint32_t qhi[4][4], qlo[4][4];
    {
        uint32_t qa = sb + (wid * 16 + a_row_in) * QROW + a_ksel;
        #pragma unroll
        for (int kf = 0; kf < 4; kf++) {
            ldsm_x4(qhi[kf], qa + kf * 32);
            ldsm_x4(qlo[kf], qa + 128 + kf * 32);
        }
    }

    float o[8][4];
    #pragma unroll
    for (int f = 0; f < 8; f++)
        #pragma unroll
        for (int e = 0; e < 4; e++) o[f][e] = 0.0f;
    float m0r = -INFINITY, m1r = -INFINITY, l0r = 0.0f, l1r = 0.0f;

    const float sscale = 0.125f * 1.44269504088896f;

    for (int kbi = 0; kbi < ANB; kbi++) {
        if (kbi == ANB - 1) { asm volatile("cp.async.wait_group 0;"); }
        else                { asm volatile("cp.async.wait_group 1;"); }
        __syncthreads();
        if (kbi + 2 < ANB) {
            load_stage(kbi + 2);
            asm volatile("cp.async.commit_group;");
        }

        const uint32_t sK = sb + QBYTES + (kbi % 3) * ASTG;
        const uint32_t sV = sK + KTILE;

        // ---- scores (bf16 split-3 -> exact fp32) ----
        float sc[8][4];
        #pragma unroll
        for (int f = 0; f < 8; f++)
            #pragma unroll
            for (int e = 0; e < 4; e++) sc[f][e] = 0.0f;

        #pragma unroll
        for (int kf = 0; kf < 4; kf++) {
            #pragma unroll
            for (int fn2 = 0; fn2 < 4; fn2++) {
                uint32_t bfr[4];
                ldsm_x4(bfr, sK + (fn2 * 16 + b_row_in) * KROW + kf * 32 + b_ksel);
                mma16816(sc[fn2 * 2 + 0], qhi[kf], bfr[0], bfr[1]);
                mma16816(sc[fn2 * 2 + 1], qhi[kf], bfr[2], bfr[3]);
                mma16816(sc[fn2 * 2 + 0], qlo[kf], bfr[0], bfr[1]);
                mma16816(sc[fn2 * 2 + 1], qlo[kf], bfr[2], bfr[3]);
            }
            #pragma unroll
            for (int fn2 = 0; fn2 < 4; fn2++) {
                uint32_t bfr[4];
                ldsm_x4(bfr, sK + (fn2 * 16 + b_row_in) * KROW + 128 + kf * 32 + b_ksel);
                mma16816(sc[fn2 * 2 + 0], qhi[kf], bfr[0], bfr[1]);
                mma16816(sc[fn2 * 2 + 1], qhi[kf], bfr[2], bfr[3]);
            }
        }

        // ---- online softmax ----
        #pragma unroll
        for (int f = 0; f < 8; f++)
            #pragma unroll
            for (int e = 0; e < 4; e++) sc[f][e] *= sscale;

        float mx0 = -INFINITY, mx1 = -INFINITY;
        #pragma unroll
        for (int f = 0; f < 8; f++) {
            mx0 = fmaxf(mx0, fmaxf(sc[f][0], sc[f][1]));
            mx1 = fmaxf(mx1, fmaxf(sc[f][2], sc[f][3]));
        }
        mx0 = fmaxf(mx0, __shfl_xor_sync(0xffffffffu, mx0, 1));
        mx0 = fmaxf(mx0, __shfl_xor_sync(0xffffffffu, mx0, 2));
        mx1 = fmaxf(mx1, __shfl_xor_sync(0xffffffffu, mx1, 1));
        mx1 = fmaxf(mx1, __shfl_xor_sync(0xffffffffu, mx1, 2));

        float mn0 = fmaxf(m0r, mx0), mn1 = fmaxf(m1r, mx1);
        float c0 = exp2f(m0r - mn0), c1 = exp2f(m1r - mn1);

        float rs0 = 0.0f, rs1 = 0.0f;
        #pragma unroll
        for (int f = 0; f < 8; f++) {
            sc[f][0] = exp2f(sc[f][0] - mn0); rs0 += sc[f][0];
            sc[f][1] = exp2f(sc[f][1] - mn0); rs0 += sc[f][1];
            sc[f][2] = exp2f(sc[f][2] - mn1); rs1 += sc[f][2];
            sc[f][3] = exp2f(sc[f][3] - mn1); rs1 += sc[f][3];
        }
        rs0 += __shfl_xor_sync(0xffffffffu, rs0, 1);
        rs0 += __shfl_xor_sync(0xffffffffu, rs0, 2);
        rs1 += __shfl_xor_sync(0xffffffffu, rs1, 1);
        rs1 += __shfl_xor_sync(0xffffffffu, rs1, 2);

        l0r = l0r * c0 + rs0;
        l1r = l1r * c1 + rs1;
        m0r = mn0; m1r = mn1;
        #pragma unroll
        for (int f = 0; f < 8; f++) {
            o[f][0] *= c0; o[f][1] *= c0;
            o[f][2] *= c1; o[f][3] *= c1;
        }

        // ---- PV: P fp16, V fp16 hi (rows 0-63) + lo (rows 64-127) ----
        #pragma unroll
        for (int j = 0; j < 4; j++) {
            uint32_t a[4];
            __half2 t;
            t = __floats2half2_rn(sc[2 * j][0],     sc[2 * j][1]);     a[0] = *(uint32_t*)&t;
            t = __floats2half2_rn(sc[2 * j][2],     sc[2 * j][3]);     a[1] = *(uint32_t*)&t;
            t = __floats2half2_rn(sc[2 * j + 1][0], sc[2 * j + 1][1]); a[2] = *(uint32_t*)&t;
            t = __floats2half2_rn(sc[2 * j + 1][2], sc[2 * j + 1][3]); a[3] = *(uint32_t*)&t;
            #pragma unroll
            for (int fn2 = 0; fn2 < 4; fn2++) {
                uint32_t base = sV + (fn2 * 16 + b_row_in) * VROW + j * 32 + b_ksel;
                uint32_t bfr[4];
                ldsm_x4(bfr, base);
                mma16816h(o[fn2 * 2 + 0], a, bfr[0], bfr[1]);
                mma16816h(o[fn2 * 2 + 1], a, bfr[2], bfr[3]);
                ldsm_x4(bfr, base + 64 * VROW);
                mma16816h(o[fn2 * 2 + 0], a, bfr[0], bfr[1]);
                mma16816h(o[fn2 * 2 + 1], a, bfr[2], bfr[3]);
            }
        }
    }

    // ---- epilogue -> g_ctx f32 ----
    const float inv0 = 1.0f / l0r, inv1 = 1.0f / l1r;
    const int rowb = m0 + wid * 16 + (lane >> 2);
    const int colb = h * 64 + 2 * (lane & 3);
    float* ctx = g_ctx + (size_t)(b * S_) * D_;
    #pragma unroll
    for (int f = 0; f < 8; f++) {
        int col = colb + 8 * f;
        *(float2*)(ctx + (size_t)rowb * D_ + col) =
            make_float2(o[f][0] * inv0, o[f][1] * inv0);
        *(float2*)(ctx + (size_t)(rowb + 8) * D_ + col) =
            make_float2(o[f][2] * inv1, o[f][3] * inv1);
    }
}

// ---------------------------------------------------------------------------
// Launch
// ---------------------------------------------------------------------------
extern "C" void kernel_launch(void* const* d_in, const int* in_sizes, int n_in,
                              void* d_out, int out_size)
{
    const float* x  = (const float*)d_in[0];
    const float* Wq = (const float*)d_in[1];
    const float* bq = (const float*)d_in[2];
    const float* Wk = (const float*)d_in[3];
    const float* bk = (const float*)d_in[4];
    const float* Wv = (const float*)d_in[5];
    const float* bv = (const float*)d_in[6];
    const float* Wo = (const float*)d_in[7];
    const float* bo = (const float*)d_in[8];
    float* out = (float*)d_out;

    float *q, *k, *v, *ctx;
    __nv_bfloat16 *xc, *ctxc, *wqt, *wkt, *wvt, *wot;
    cudaGetSymbolAddress((void**)&q,    g_q);
    cudaGetSymbolAddress((void**)&k,    g_k);
    cudaGetSymbolAddress((void**)&v,    g_v);
    cudaGetSymbolAddress((void**)&ctx,  g_ctx);
    cudaGetSymbolAddress((void**)&xc,   g_xc);
    cudaGetSymbolAddress((void**)&ctxc, g_ctxc);
    cudaGetSymbolAddress((void**)&wqt,  g_wqt);
    cudaGetSymbolAddress((void**)&wkt,  g_wkt);
    cudaGetSymbolAddress((void**)&wvt,  g_wvt);
    cudaGetSymbolAddress((void**)&wot,  g_wot);

    cudaFuncSetAttribute(gemm_mma_kernel,
                         cudaFuncAttributeMaxDynamicSharedMemorySize, GEMM_SMEM);
    cudaFuncSetAttribute(attn_mma_kernel,
                         cudaFuncAttributeMaxDynamicSharedMemorySize, ATT_SMEM);

    // hi/lo conversions for projections
    convert_rows_kernel<<<2048, 256>>>(x, xc, M_ * D_, D_);
    convert_transpose_kernel<<<dim3(D_ / 32,   D_ / 32), dim3(32, 8)>>>(Wq, wqt, D_, D_);
    convert_transpose_kernel<<<dim3(KVD_ / 32, D_ / 32), dim3(32, 8)>>>(Wk, wkt, D_, KVD_);
    convert_transpose_kernel<<<dim3(KVD_ / 32, D_ / 32), dim3(32, 8)>>>(Wv, wvt, D_, KVD_);
    convert_transpose_kernel<<<dim3(D_ / 32,   D_ / 32), dim3(32, 8)>>>(Wo, wot, D_, D_);

    // projections (HMMA)
    gemm_mma_kernel<<<dim3(D_ / 128,   M_ / 128), 256, GEMM_SMEM>>>(xc, wqt, bq, q, D_);
    gemm_mma_kernel<<<dim3(KVD_ / 128, M_ / 128), 256, GEMM_SMEM>>>(xc, wkt, bk, k, KVD_);
    gemm_mma_kernel<<<dim3(KVD_ / 128, M_ / 128), 256, GEMM_SMEM>>>(xc, wvt, bv, v, KVD_);

    // attention operand prep
    convert_qb_kernel<<<2048, 256>>>();
    convert_kb_kernel<<<1024, 256>>>();
    convert_vt_kernel<<<dim3(S_ / 32, 2, B_ * HKV_), dim3(32, 8)>>>();

    // attention (HMMA)
    attn_mma_kernel<<<dim3(S_ / 128, B_ * H_), 256, ATT_SMEM>>>();

    // output projection
    convert_rows_kernel<<<2048, 256>>>(ctx, ctxc, M_ * D_, D_);
    gemm_mma_kernel<<<dim3(D_ / 128, M_ / 128), 256, GEMM_SMEM>>>(ctxc, wot, bo, out, D_);
}

// round 8
// speedup vs baseline: 2.9748x; 1.2059x over previous
#include <cuda_runtime.h>
#include <cuda_bf16.h>
#include <cuda_fp16.h>
#include <cstdint>
#include <math.h>

// Problem constants
constexpr int B_   = 2;
constexpr int S_   = 2048;
constexpr int D_   = 2048;
constexpr int H_   = 32;
constexpr int HKV_ = 8;
constexpr int DH_  = 64;
constexpr int G_   = 4;
constexpr int M_   = B_ * S_;      // 4096 rows
constexpr int KVD_ = HKV_ * DH_;   // 512

// Scratch (__device__ globals: allocation-free rule)
__device__ float g_q[M_ * D_];
__device__ float g_k[M_ * KVD_];
__device__ float g_v[M_ * KVD_];
__device__ float g_ctx[M_ * D_];

// bf16 split (hi|lo along K) GEMM operands
__device__ __nv_bfloat16 g_xc  [M_   * 2 * D_];
__device__ __nv_bfloat16 g_ctxc[M_   * 2 * D_];
__device__ __nv_bfloat16 g_wqt [D_   * 2 * D_];
__device__ __nv_bfloat16 g_wkt [KVD_ * 2 * D_];
__device__ __nv_bfloat16 g_wvt [KVD_ * 2 * D_];
__device__ __nv_bfloat16 g_wot [D_   * 2 * D_];

// attention operands
__device__ __nv_bfloat16 g_qb[B_ * H_   * S_ * 128];  // [b,h][m][hi64|lo64] bf16
__device__ __nv_bfloat16 g_kb[B_ * HKV_ * S_ * 128];  // [b,kvh][n][hi64|lo64] bf16
__device__ __half        g_vt[B_ * HKV_ * 64 * S_];   // [b,kvh][d][n] fp16 (V^T)

__device__ __forceinline__ uint32_t smem_u32_of(const void* p) {
    uint32_t a;
    asm("{ .reg .u64 t; cvta.to.shared.u64 t, %1; cvt.u32.u64 %0, t; }" : "=r"(a) : "l"(p));
    return a;
}
__device__ __forceinline__ void ldsm_x4(uint32_t (&r)[4], uint32_t addr) {
    asm volatile("ldmatrix.sync.aligned.m8n8.x4.shared.b16 {%0,%1,%2,%3}, [%4];"
                 : "=r"(r[0]), "=r"(r[1]), "=r"(r[2]), "=r"(r[3]) : "r"(addr));
}
__device__ __forceinline__ void mma16816(float (&c)[4], const uint32_t (&a)[4],
                                         uint32_t b0, uint32_t b1) {
    asm volatile(
        "mma.sync.aligned.m16n8k16.row.col.f32.bf16.bf16.f32 "
        "{%0,%1,%2,%3}, {%4,%5,%6,%7}, {%8,%9}, {%0,%1,%2,%3};"
        : "+f"(c[0]), "+f"(c[1]), "+f"(c[2]), "+f"(c[3])
        : "r"(a[0]), "r"(a[1]), "r"(a[2]), "r"(a[3]), "r"(b0), "r"(b1));
}
__device__ __forceinline__ void mma16816h(float (&c)[4], const uint32_t (&a)[4],
                                          uint32_t b0, uint32_t b1) {
    asm volatile(
        "mma.sync.aligned.m16n8k16.row.col.f32.f16.f16.f32 "
        "{%0,%1,%2,%3}, {%4,%5,%6,%7}, {%8,%9}, {%0,%1,%2,%3};"
        : "+f"(c[0]), "+f"(c[1]), "+f"(c[2]), "+f"(c[3])
        : "r"(a[0]), "r"(a[1]), "r"(a[2]), "r"(a[3]), "r"(b0), "r"(b1));
}
__device__ __forceinline__ void cp16(uint32_t dst, const void* src) {
    asm volatile("cp.async.cg.shared.global [%0], [%1], 16;" :: "r"(dst), "l"(src));
}

// ---------------------------------------------------------------------------
// Conversion kernels
// ---------------------------------------------------------------------------
__global__ void convert_rows_kernel(const float* __restrict__ src,
                                    __nv_bfloat16* __restrict__ dst, int total, int K)
{
    for (int i = blockIdx.x * blockDim.x + threadIdx.x; i < total;
         i += gridDim.x * blockDim.x) {
        int m = i / K, k = i - m * K;
        float x = src[i];
        __nv_bfloat16 h = __float2bfloat16(x);
        float lo = x - __bfloat162float(h);
        dst[(size_t)m * 2 * K + k]     = h;
        dst[(size_t)m * 2 * K + K + k] = __float2bfloat16(lo);
    }
}

__global__ void convert_transpose_kernel(const float* __restrict__ W,
                                         __nv_bfloat16* __restrict__ Wt, int K, int N)
{
    __shared__ float tile[32][33];
    int k0 = blockIdx.y * 32, n0 = blockIdx.x * 32;
    int tx = threadIdx.x, ty = threadIdx.y;
    #pragma unroll
    for (int dy = 0; dy < 32; dy += 8)
        tile[ty + dy][tx] = W[(size_t)(k0 + ty + dy) * N + n0 + tx];
    __syncthreads();
    #pragma unroll
    for (int dy = 0; dy < 32; dy += 8) {
        int n = n0 + ty + dy;
        float x = tile[tx][ty + dy];
        __nv_bfloat16 h = __float2bfloat16(x);
        Wt[(size_t)n * 2 * K + k0 + tx]     = h;
        Wt[(size_t)n * 2 * K + K + k0 + tx] = __float2bfloat16(x - __bfloat162float(h));
    }
}

__global__ void convert_qb_kernel()
{
    int total = B_ * H_ * S_ * 64;
    for (int i = blockIdx.x * blockDim.x + threadIdx.x; i < total;
         i += gridDim.x * blockDim.x) {
        int d = i & 63, rest = i >> 6;
        int m = rest & (S_ - 1);
        int bh = rest >> 11;
        int b = bh >> 5, h = bh & 31;
        float x = g_q[((size_t)(b * S_ + m)) * D_ + h * 64 + d];
        __nv_bfloat16 hi = __float2bfloat16(x);
        g_qb[((size_t)bh * S_ + m) * 128 + d]      = hi;
        g_qb[((size_t)bh * S_ + m) * 128 + 64 + d] =
            __float2bfloat16(x - __bfloat162float(hi));
    }
}

__global__ void convert_kb_kernel()
{
    int total = B_ * HKV_ * S_ * 64;
    for (int i = blockIdx.x * blockDim.x + threadIdx.x; i < total;
         i += gridDim.x * blockDim.x) {
        int d = i & 63, rest = i >> 6;
        int n = rest & (S_ - 1);
        int bk = rest >> 11;
        int b = bk >> 3, kvh = bk & 7;
        float x = g_k[((size_t)(b * S_ + n)) * KVD_ + kvh * 64 + d];
        __nv_bfloat16 hi = __float2bfloat16(x);
        g_kb[((size_t)bk * S_ + n) * 128 + d]      = hi;
        g_kb[((size_t)bk * S_ + n) * 128 + 64 + d] =
            __float2bfloat16(x - __bfloat162float(hi));
    }
}

// g_v f32 [b*S+n][kvh*64+d] -> g_vt fp16 [bk][d][n]  (transpose)
__global__ void convert_vt_kernel()
{
    __shared__ float tile[32][33];
    int n0 = blockIdx.x * 32, d0 = blockIdx.y * 32;
    int bk = blockIdx.z;
    int b = bk >> 3, kvh = bk & 7;
    int tx = threadIdx.x, ty = threadIdx.y;
    #pragma unroll
    for (int dy = 0; dy < 32; dy += 8)
        tile[ty + dy][tx] = g_v[((size_t)(b * S_ + n0 + ty + dy)) * KVD_ + kvh * 64 + d0 + tx];
    __syncthreads();
    #pragma unroll
    for (int dy = 0; dy < 32; dy += 8) {
        int d = d0 + ty + dy;
        g_vt[((size_t)bk * 64 + d) * S_ + n0 + tx] = __float2half_rn(tile[tx][ty + dy]);
    }
}

// ---------------------------------------------------------------------------
// HMMA GEMM, templated on BN (128 validated in R4; 256 = same mappings,
// warp tile 64x64, mma/ldsm ratio 4, A-traffic halved)
// ---------------------------------------------------------------------------
constexpr int A_ROW_B   = 80;                 // 64B data + 16B pad per 32-elem row
constexpr int A_TILE_B  = 128 * A_ROW_B;      // 10240
constexpr int GEMM_NKC  = 192;                // 6144 / 32

template<int BN>
__global__ __launch_bounds__(256, 1)
void gemm_mma_kernel(const __nv_bfloat16* __restrict__ A,
                     const __nv_bfloat16* __restrict__ Bt,
                     const float* __restrict__ bias,
                     float* __restrict__ C, int Ndim)
{
    constexpr int COLS_W = BN / 4;            // 64 or 32 cols per warp
    constexpr int NF2    = COLS_W / 16;       // 4 or 2
    constexpr int B_TILE = BN * A_ROW_B;
    constexpr int STAGE  = A_TILE_B + B_TILE;

    extern __shared__ __align__(128) char smem[];
    const uint32_t smem_b = smem_u32_of(smem);
    const int tid  = threadIdx.x;
    const int lane = tid & 31, wid = tid >> 5;
    const int warp_m = wid & 1;
    const int warp_n = wid >> 1;
    const int bm = blockIdx.y * 128;
    const int bn = blockIdx.x * BN;

    float acc[4][2 * NF2][4];
    #pragma unroll
    for (int i = 0; i < 4; i++)
        #pragma unroll
        for (int j = 0; j < 2 * NF2; j++)
            #pragma unroll
            for (int e = 0; e < 4; e++) acc[i][j][e] = 0.0f;

    auto load_stage = [&](int kc) {
        int slot = kc & 3;
        int seg = kc / 64, within = (kc & 63) * 32;
        int a_col = within + ((seg == 1) ? 2048 : 0);
        int w_col = within + ((seg == 2) ? 2048 : 0);
        uint32_t sA = smem_b + slot * STAGE;
        uint32_t sB = sA + A_TILE_B;
        #pragma unroll
        for (int it = 0; it < 2; it++) {
            int idx = tid + it * 256;
            int r = idx >> 2, c = idx & 3;
            cp16(sA + r * A_ROW_B + c * 16, A + (size_t)(bm + r) * 4096 + a_col + c * 8);
        }
        #pragma unroll
        for (int it = 0; it < BN / 64; it++) {
            int idx = tid + it * 256;
            int r = idx >> 2, c = idx & 3;
            cp16(sB + r * A_ROW_B + c * 16, Bt + (size_t)(bn + r) * 4096 + w_col + c * 8);
        }
    };

    #pragma unroll
    for (int s = 0; s < 3; s++) {
        load_stage(s);
        asm volatile("cp.async.commit_group;");
    }

    const int a_row_in = lane & 15;
    const int a_ksel   = (lane >> 4) * 16;
    const int b_sel    = (lane >> 3) & 3;
    const int b_row_in = ((b_sel >> 1) << 3) + (lane & 7);
    const int b_ksel   = (b_sel & 1) * 16;

    for (int kc = 0; kc < GEMM_NKC; kc++) {
        asm volatile("cp.async.wait_group 2;");
        __syncthreads();
        if (kc + 3 < GEMM_NKC) load_stage(kc + 3);
        asm volatile("cp.async.commit_group;");

        int slot = kc & 3;
        uint32_t sA = smem_b + slot * STAGE + (warp_m * 64) * A_ROW_B;
        uint32_t sB = smem_b + slot * STAGE + A_TILE_B + (warp_n * COLS_W) * A_ROW_B;

        #pragma unroll
        for (int kk = 0; kk < 2; kk++) {
            uint32_t kbyte = kk * 32;
            uint32_t afr[4][4];
            #pragma unroll
            for (int fm = 0; fm < 4; fm++)
                ldsm_x4(afr[fm], sA + (fm * 16 + a_row_in) * A_ROW_B + kbyte + a_ksel);
            #pragma unroll
            for (int fn2 = 0; fn2 < NF2; fn2++) {
                uint32_t bfr[4];
                ldsm_x4(bfr, sB + (fn2 * 16 + b_row_in) * A_ROW_B + kbyte + b_ksel);
                #pragma unroll
                for (int fm = 0; fm < 4; fm++) {
                    mma16816(acc[fm][fn2 * 2 + 0], afr[fm], bfr[0], bfr[1]);
                    mma16816(acc[fm][fn2 * 2 + 1], afr[fm], bfr[2], bfr[3]);
                }
            }
        }
    }

    const int row0 = bm + warp_m * 64 + (lane >> 2);
    const int col0 = bn + warp_n * COLS_W + (lane & 3) * 2;
    #pragma unroll
    for (int fm = 0; fm < 4; fm++) {
        #pragma unroll
        for (int fn = 0; fn < 2 * NF2; fn++) {
            int c = col0 + fn * 8;
            float b0 = bias[c], b1 = bias[c + 1];
            int r0 = row0 + fm * 16;
            float2 v0 = make_float2(acc[fm][fn][0] + b0, acc[fm][fn][1] + b1);
            float2 v1 = make_float2(acc[fm][fn][2] + b0, acc[fm][fn][3] + b1);
            *(float2*)(C + (size_t)r0 * Ndim + c)       = v0;
            *(float2*)(C + (size_t)(r0 + 8) * Ndim + c) = v1;
        }
    }
}

constexpr int GEMM_SMEM_256 = 4 * (A_TILE_B + 256 * A_ROW_B);  // 122880
constexpr int GEMM_SMEM_128 = 4 * (A_TILE_B + 128 * A_ROW_B);  // 81920

// ---------------------------------------------------------------------------
// Flash attention on mma.sync. CTA = 128 q-rows x (b,h). 8 warps x 16 rows.
// QK: bf16 split-3 (exact scores). PV: P fp16, V fp16 single.
// ---------------------------------------------------------------------------
constexpr int ANB     = S_ / 64;        // 32 k-blocks
constexpr int QROW    = 272;
constexpr int KROW    = 272;
constexpr int VROW    = 144;
constexpr int QBYTES  = 128 * QROW;     // 34816
constexpr int KTILE   = 64 * KROW;      // 17408
constexpr int VTILE   = 64 * VROW;      // 9216
constexpr int ASTG    = KTILE + VTILE;  // 26624
constexpr int ATT_SMEM = QBYTES + 3 * ASTG;  // 114688

__global__ __launch_bounds__(256)
void attn_mma_kernel()
{
    extern __shared__ __align__(128) char smem[];
    const uint32_t sb = smem_u32_of(smem);
    const int tid  = threadIdx.x;
    const int lane = tid & 31, wid = tid >> 5;

    const int bh  = blockIdx.y;
    const int b   = bh >> 5;
    const int h   = bh & 31;
    const int kvh = h >> 2;
    const int bk  = b * HKV_ + kvh;
    const int m0  = blockIdx.x * 128;

    const __nv_bfloat16* qbase = g_qb + ((size_t)bh * S_ + m0) * 128;
    const __nv_bfloat16* kbase = g_kb + ((size_t)bk * S_) * 128;
    const __half*        vbase = g_vt + ((size_t)bk * 64) * (size_t)S_;

    #pragma unroll
    for (int it = 0; it < 8; it++) {
        int idx = tid + it * 256;
        int r = idx >> 4, c = idx & 15;
        cp16(sb + r * QROW + c * 16, qbase + (size_t)r * 128 + c * 8);
    }
    asm volatile("cp.async.commit_group;");

    auto load_stage = [&](int kbi) {
        int slot = kbi % 3;
        int n0 = kbi * 64;
        uint32_t sK = sb + QBYTES + slot * ASTG;
        uint32_t sV = sK + KTILE;
        #pragma unroll
        for (int it = 0; it < 4; it++) {
            int idx = tid + it * 256;
            int r = idx >> 4, c = idx & 15;
            cp16(sK + r * KROW + c * 16, kbase + (size_t)(n0 + r) * 128 + c * 8);
        }
        #pragma unroll
        for (int it = 0; it < 2; it++) {
            int idx = tid + it * 256;
            int r = idx >> 3, c = idx & 7;
            cp16(sV + r * VROW + c * 16, vbase + (size_t)r * S_ + n0 + c * 8);
        }
    };
    load_stage(0); asm volatile("cp.async.commit_group;");
    load_stage(1); asm volatile("cp.async.commit_group;");

    asm volatile("cp.async.wait_group 2;");
    __syncthreads();

    const int a_row_in = lane & 15;
    const int a_ksel   = (lane >> 4) * 16;
    const int b_sel    = (lane >> 3) & 3;
    const int b_row_in = ((b_sel >> 1) << 3) + (lane & 7);
    const int b_ksel   = (b_sel & 1) * 16;

    uint32_t qhi[4][4], qlo[4][4];
    {
        uint32_t qa = sb + (wid * 16 + a_row_in) * QROW + a_ksel;
        #pragma unroll
        for (int kf = 0; kf < 4; kf++) {
            ldsm_x4(qhi[kf], qa + kf * 32);
            ldsm_x4(qlo[kf], qa + 128 + kf * 32);
        }
    }

    float o[8][4];
    #pragma unroll
    for (int f = 0; f < 8; f++)
        #pragma unroll
        for (int e = 0; e < 4; e++) o[f][e] = 0.0f;
    float m0r = -INFINITY, m1r = -INFINITY, l0r = 0.0f, l1r = 0.0f;

    const float sscale = 0.125f * 1.44269504088896f;

    for (int kbi = 0; kbi < ANB; kbi++) {
        if (kbi == ANB - 1) { asm volatile("cp.async.wait_group 0;"); }
        else                { asm volatile("cp.async.wait_group 1;"); }
        __syncthreads();
        if (kbi + 2 < ANB) {
            load_stage(kbi + 2);
            asm volatile("cp.async.commit_group;");
        }

        const uint32_t sK = sb + QBYTES + (kbi % 3) * ASTG;
        const uint32_t sV = sK + KTILE;

        // ---- scores (bf16 split-3 -> exact fp32) ----
        float sc[8][4];
        #pragma unroll
        for (int f = 0; f < 8; f++)
            #pragma unroll
            for (int e = 0; e < 4; e++) sc[f][e] = 0.0f;

        #pragma unroll
        for (int kf = 0; kf < 4; kf++) {
            #pragma unroll
            for (int fn2 = 0; fn2 < 4; fn2++) {
                uint32_t bfr[4];
                ldsm_x4(bfr, sK + (fn2 * 16 + b_row_in) * KROW + kf * 32 + b_ksel);
                mma16816(sc[fn2 * 2 + 0], qhi[kf], bfr[0], bfr[1]);
                mma16816(sc[fn2 * 2 + 1], qhi[kf], bfr[2], bfr[3]);
                mma16816(sc[fn2 * 2 + 0], qlo[kf], bfr[0], bfr[1]);
                mma16816(sc[fn2 * 2 + 1], qlo[kf], bfr[2], bfr[3]);
            }
            #pragma unroll
            for (int fn2 = 0; fn2 < 4; fn2++) {
                uint32_t bfr[4];
                ldsm_x4(bfr, sK + (fn2 * 16 + b_row_in) * KROW + 128 + kf * 32 + b_ksel);
                mma16816(sc[fn2 * 2 + 0], qhi[kf], bfr[0], bfr[1]);
                mma16816(sc[fn2 * 2 + 1], qhi[kf], bfr[2], bfr[3]);
            }
        }

        // ---- online softmax ----
        #pragma unroll
        for (int f = 0; f < 8; f++)
            #pragma unroll
            for (int e = 0; e < 4; e++) sc[f][e] *= sscale;

        float mx0 = -INFINITY, mx1 = -INFINITY;
        #pragma unroll
        for (int f = 0; f < 8; f++) {
            mx0 = fmaxf(mx0, fmaxf(sc[f][0], sc[f][1]));
            mx1 = fmaxf(mx1, fmaxf(sc[f][2], sc[f][3]));
        }
        mx0 = fmaxf(mx0, __shfl_xor_sync(0xffffffffu, mx0, 1));
        mx0 = fmaxf(mx0, __shfl_xor_sync(0xffffffffu, mx0, 2));
        mx1 = fmaxf(mx1, __shfl_xor_sync(0xffffffffu, mx1, 1));
        mx1 = fmaxf(mx1, __shfl_xor_sync(0xffffffffu, mx1, 2));

        float mn0 = fmaxf(m0r, mx0), mn1 = fmaxf(m1r, mx1);
        float c0 = exp2f(m0r - mn0), c1 = exp2f(m1r - mn1);

        float rs0 = 0.0f, rs1 = 0.0f;
        #pragma unroll
        for (int f = 0; f < 8; f++) {
            sc[f][0] = exp2f(sc[f][0] - mn0); rs0 += sc[f][0];
            sc[f][1] = exp2f(sc[f][1] - mn0); rs0 += sc[f][1];
            sc[f][2] = exp2f(sc[f][2] - mn1); rs1 += sc[f][2];
            sc[f][3] = exp2f(sc[f][3] - mn1); rs1 += sc[f][3];
        }
        rs0 += __shfl_xor_sync(0xffffffffu, rs0, 1);
        rs0 += __shfl_xor_sync(0xffffffffu, rs0, 2);
        rs1 += __shfl_xor_sync(0xffffffffu, rs1, 1);
        rs1 += __shfl_xor_sync(0xffffffffu, rs1, 2);

        l0r = l0r * c0 + rs0;
        l1r = l1r * c1 + rs1;
        m0r = mn0; m1r = mn1;
        #pragma unroll
        for (int f = 0; f < 8; f++) {
            o[f][0] *= c0; o[f][1] *= c0;
            o[f][2] *= c1; o[f][3] *= c1;
        }

        // ---- PV: P fp16, V fp16 single ----
        #pragma unroll
        for (int j = 0; j < 4; j++) {
            uint32_t a[4];
            __half2 t;
            t = __floats2half2_rn(sc[2 * j][0],     sc[2 * j][1]);     a[0] = *(uint32_t*)&t;
            t = __floats2half2_rn(sc[2 * j][2],     sc[2 * j][3]);     a[1] = *(uint32_t*)&t;
            t = __floats2half2_rn(sc[2 * j + 1][0], sc[2 * j + 1][1]); a[2] = *(uint32_t*)&t;
            t = __floats2half2_rn(sc[2 * j + 1][2], sc[2 * j + 1][3]); a[3] = *(uint32_t*)&t;
            #pragma unroll
            for (int fn2 = 0; fn2 < 4; fn2++) {
                uint32_t bfr[4];
                ldsm_x4(bfr, sV + (fn2 * 16 + b_row_in) * VROW + j * 32 + b_ksel);
                mma16816h(o[fn2 * 2 + 0], a, bfr[0], bfr[1]);
                mma16816h(o[fn2 * 2 + 1], a, bfr[2], bfr[3]);
            }
        }
    }

    // ---- epilogue -> g_ctx f32 ----
    const float inv0 = 1.0f / l0r, inv1 = 1.0f / l1r;
    const int rowb = m0 + wid * 16 + (lane >> 2);
    const int colb = h * 64 + 2 * (lane & 3);
    float* ctx = g_ctx + (size_t)(b * S_) * D_;
    #pragma unroll
    for (int f = 0; f < 8; f++) {
        int col = colb + 8 * f;
        *(float2*)(ctx + (size_t)rowb * D_ + col) =
            make_float2(o[f][0] * inv0, o[f][1] * inv0);
        *(float2*)(ctx + (size_t)(rowb + 8) * D_ + col) =
            make_float2(o[f][2] * inv1, o[f][3] * inv1);
    }
}

// ---------------------------------------------------------------------------
// Launch
// ---------------------------------------------------------------------------
extern "C" void kernel_launch(void* const* d_in, const int* in_sizes, int n_in,
                              void* d_out, int out_size)
{
    const float* x  = (const float*)d_in[0];
    const float* Wq = (const float*)d_in[1];
    const float* bq = (const float*)d_in[2];
    const float* Wk = (const float*)d_in[3];
    const float* bk = (const float*)d_in[4];
    const float* Wv = (const float*)d_in[5];
    const float* bv = (const float*)d_in[6];
    const float* Wo = (const float*)d_in[7];
    const float* bo = (const float*)d_in[8];
    float* out = (float*)d_out;

    float *q, *k, *v, *ctx;
    __nv_bfloat16 *xc, *ctxc, *wqt, *wkt, *wvt, *wot;
    cudaGetSymbolAddress((void**)&q,    g_q);
    cudaGetSymbolAddress((void**)&k,    g_k);
    cudaGetSymbolAddress((void**)&v,    g_v);
    cudaGetSymbolAddress((void**)&ctx,  g_ctx);
    cudaGetSymbolAddress((void**)&xc,   g_xc);
    cudaGetSymbolAddress((void**)&ctxc, g_ctxc);
    cudaGetSymbolAddress((void**)&wqt,  g_wqt);
    cudaGetSymbolAddress((void**)&wkt,  g_wkt);
    cudaGetSymbolAddress((void**)&wvt,  g_wvt);
    cudaGetSymbolAddress((void**)&wot,  g_wot);

    cudaFuncSetAttribute(gemm_mma_kernel<256>,
                         cudaFuncAttributeMaxDynamicSharedMemorySize, GEMM_SMEM_256);
    cudaFuncSetAttribute(gemm_mma_kernel<128>,
                         cudaFuncAttributeMaxDynamicSharedMemorySize, GEMM_SMEM_128);
    cudaFuncSetAttribute(attn_mma_kernel,
                         cudaFuncAttributeMaxDynamicSharedMemorySize, ATT_SMEM);

    // hi/lo conversions for projections
    convert_rows_kernel<<<2048, 256>>>(x, xc, M_ * D_, D_);
    convert_transpose_kernel<<<dim3(D_ / 32,   D_ / 32), dim3(32, 8)>>>(Wq, wqt, D_, D_);
    convert_transpose_kernel<<<dim3(KVD_ / 32, D_ / 32), dim3(32, 8)>>>(Wk, wkt, D_, KVD_);
    convert_transpose_kernel<<<dim3(KVD_ / 32, D_ / 32), dim3(32, 8)>>>(Wv, wvt, D_, KVD_);
    convert_transpose_kernel<<<dim3(D_ / 32,   D_ / 32), dim3(32, 8)>>>(Wo, wot, D_, D_);

    // projections (HMMA): Q big tile; K,V narrow
    gemm_mma_kernel<256><<<dim3(D_ / 256,   M_ / 128), 256, GEMM_SMEM_256>>>(xc, wqt, bq, q, D_);
    gemm_mma_kernel<128><<<dim3(KVD_ / 128, M_ / 128), 256, GEMM_SMEM_128>>>(xc, wkt, bk, k, KVD_);
    gemm_mma_kernel<128><<<dim3(KVD_ / 128, M_ / 128), 256, GEMM_SMEM_128>>>(xc, wvt, bv, v, KVD_);

    // attention operand prep
    convert_qb_kernel<<<2048, 256>>>();
    convert_kb_kernel<<<1024, 256>>>();
    convert_vt_kernel<<<dim3(S_ / 32, 2, B_ * HKV_), dim3(32, 8)>>>();

    // attention (HMMA)
    attn_mma_kernel<<<dim3(S_ / 128, B_ * H_), 256, ATT_SMEM>>>();

    // output projection (big tile)
    convert_rows_kernel<<<2048, 256>>>(ctx, ctxc, M_ * D_, D_);
    gemm_mma_kernel<256><<<dim3(D_ / 256, M_ / 128), 256, GEMM_SMEM_256>>>(ctxc, wot, bo, out, D_);
}

// round 9
// speedup vs baseline: 3.3938x; 1.1408x over previous
#include <cuda_runtime.h>
#include <cuda_bf16.h>
#include <cuda_fp16.h>
#include <cstdint>
#include <math.h>

// Problem constants
constexpr int B_   = 2;
constexpr int S_   = 2048;
constexpr int D_   = 2048;
constexpr int H_   = 32;
constexpr int HKV_ = 8;
constexpr int DH_  = 64;
constexpr int M_   = B_ * S_;      // 4096 rows
constexpr int KVD_ = HKV_ * DH_;   // 512

// bf16 split (hi|lo along K) GEMM operands (__device__ globals: allocation-free rule)
__device__ __nv_bfloat16 g_xc  [M_   * 2 * D_];
__device__ __nv_bfloat16 g_ctxc[M_   * 2 * D_];
__device__ __nv_bfloat16 g_wqt [D_   * 2 * D_];
__device__ __nv_bfloat16 g_wkt [KVD_ * 2 * D_];
__device__ __nv_bfloat16 g_wvt [KVD_ * 2 * D_];
__device__ __nv_bfloat16 g_wot [D_   * 2 * D_];

// attention operands (written directly by GEMM epilogues)
__device__ __nv_bfloat16 g_qb[B_ * H_   * S_ * 128];  // [b,h][m][hi64|lo64] bf16
__device__ __nv_bfloat16 g_kb[B_ * HKV_ * S_ * 128];  // [b,kvh][n][hi64|lo64] bf16
__device__ __half        g_vt[B_ * HKV_ * 64 * S_];   // [b,kvh][d][n] fp16 (V^T)

__device__ __forceinline__ uint32_t smem_u32_of(const void* p) {
    uint32_t a;
    asm("{ .reg .u64 t; cvta.to.shared.u64 t, %1; cvt.u32.u64 %0, t; }" : "=r"(a) : "l"(p));
    return a;
}
__device__ __forceinline__ void ldsm_x4(uint32_t (&r)[4], uint32_t addr) {
    asm volatile("ldmatrix.sync.aligned.m8n8.x4.shared.b16 {%0,%1,%2,%3}, [%4];"
                 : "=r"(r[0]), "=r"(r[1]), "=r"(r[2]), "=r"(r[3]) : "r"(addr));
}
__device__ __forceinline__ void mma16816(float (&c)[4], const uint32_t (&a)[4],
                                         uint32_t b0, uint32_t b1) {
    asm volatile(
        "mma.sync.aligned.m16n8k16.row.col.f32.bf16.bf16.f32 "
        "{%0,%1,%2,%3}, {%4,%5,%6,%7}, {%8,%9}, {%0,%1,%2,%3};"
        : "+f"(c[0]), "+f"(c[1]), "+f"(c[2]), "+f"(c[3])
        : "r"(a[0]), "r"(a[1]), "r"(a[2]), "r"(a[3]), "r"(b0), "r"(b1));
}
__device__ __forceinline__ void mma16816h(float (&c)[4], const uint32_t (&a)[4],
                                          uint32_t b0, uint32_t b1) {
    asm volatile(
        "mma.sync.aligned.m16n8k16.row.col.f32.f16.f16.f32 "
        "{%0,%1,%2,%3}, {%4,%5,%6,%7}, {%8,%9}, {%0,%1,%2,%3};"
        : "+f"(c[0]), "+f"(c[1]), "+f"(c[2]), "+f"(c[3])
        : "r"(a[0]), "r"(a[1]), "r"(a[2]), "r"(a[3]), "r"(b0), "r"(b1));
}
__device__ __forceinline__ void cp16(uint32_t dst, const void* src) {
    asm volatile("cp.async.cg.shared.global [%0], [%1], 16;" :: "r"(dst), "l"(src));
}
__device__ __forceinline__ __nv_bfloat162 bf16_pair_hi(float a, float b,
                                                       float& la, float& lb) {
    __nv_bfloat16 ha = __float2bfloat16(a), hb = __float2bfloat16(b);
    la = a - __bfloat162float(ha);
    lb = b - __bfloat162float(hb);
    return __nv_bfloat162(ha, hb);
}

// ---------------------------------------------------------------------------
// Conversion kernels (inputs only)
// ---------------------------------------------------------------------------
__global__ void convert_rows_kernel(const float* __restrict__ src,
                                    __nv_bfloat16* __restrict__ dst, int total, int K)
{
    for (int i = blockIdx.x * blockDim.x + threadIdx.x; i < total;
         i += gridDim.x * blockDim.x) {
        int m = i / K, k = i - m * K;
        float x = src[i];
        __nv_bfloat16 h = __float2bfloat16(x);
        float lo = x - __bfloat162float(h);
        dst[(size_t)m * 2 * K + k]     = h;
        dst[(size_t)m * 2 * K + K + k] = __float2bfloat16(lo);
    }
}

__global__ void convert_transpose_kernel(const float* __restrict__ W,
                                         __nv_bfloat16* __restrict__ Wt, int K, int N)
{
    __shared__ float tile[32][33];
    int k0 = blockIdx.y * 32, n0 = blockIdx.x * 32;
    int tx = threadIdx.x, ty = threadIdx.y;
    #pragma unroll
    for (int dy = 0; dy < 32; dy += 8)
        tile[ty + dy][tx] = W[(size_t)(k0 + ty + dy) * N + n0 + tx];
    __syncthreads();
    #pragma unroll
    for (int dy = 0; dy < 32; dy += 8) {
        int n = n0 + ty + dy;
        float x = tile[tx][ty + dy];
        __nv_bfloat16 h = __float2bfloat16(x);
        Wt[(size_t)n * 2 * K + k0 + tx]     = h;
        Wt[(size_t)n * 2 * K + K + k0 + tx] = __float2bfloat16(x - __bfloat162float(h));
    }
}

// ---------------------------------------------------------------------------
// HMMA GEMM, BK=64 per stage, 3-stage cp.async, fused epilogues.
// MODE: 0 = f32+bias -> C ; 1 = bf16 hi/lo -> g_qb ; 2 = -> g_kb ; 3 = fp16^T -> g_vt
// ---------------------------------------------------------------------------
constexpr int A_ROW_B  = 144;                 // 128B data + 16B pad (144%128=16: conflict-free)
constexpr int A_TILE_B = 128 * A_ROW_B;       // 18432
constexpr int GEMM_NKC = 96;                  // 6144 / 64

template<int BN, int MODE>
__global__ __launch_bounds__(256, 1)
void gemm_mma_kernel(const __nv_bfloat16* __restrict__ A,
                     const __nv_bfloat16* __restrict__ Bt,
                     const float* __restrict__ bias,
                     float* __restrict__ C, int Ndim)
{
    constexpr int COLS_W = BN / 4;
    constexpr int NF2    = COLS_W / 16;
    constexpr int B_TILE = BN * A_ROW_B;
    constexpr int STAGE  = A_TILE_B + B_TILE;

    extern __shared__ __align__(128) char smem[];
    const uint32_t smem_b = smem_u32_of(smem);
    const int tid  = threadIdx.x;
    const int lane = tid & 31, wid = tid >> 5;
    const int warp_m = wid & 1;
    const int warp_n = wid >> 1;
    const int bm = blockIdx.y * 128;
    const int bn = blockIdx.x * BN;

    float acc[4][2 * NF2][4];
    #pragma unroll
    for (int i = 0; i < 4; i++)
        #pragma unroll
        for (int j = 0; j < 2 * NF2; j++)
            #pragma unroll
            for (int e = 0; e < 4; e++) acc[i][j][e] = 0.0f;

    auto load_stage = [&](int kc) {
        int slot = kc % 3;
        int seg = kc >> 5, within = (kc & 31) * 64;
        int a_col = within + ((seg == 1) ? 2048 : 0);
        int w_col = within + ((seg == 2) ? 2048 : 0);
        uint32_t sA = smem_b + slot * STAGE;
        uint32_t sB = sA + A_TILE_B;
        #pragma unroll
        for (int it = 0; it < 4; it++) {
            int idx = tid + it * 256;
            int r = idx >> 3, c = idx & 7;
            cp16(sA + r * A_ROW_B + c * 16, A + (size_t)(bm + r) * 4096 + a_col + c * 8);
        }
        #pragma unroll
        for (int it = 0; it < BN / 32; it++) {
            int idx = tid + it * 256;
            int r = idx >> 3, c = idx & 7;
            cp16(sB + r * A_ROW_B + c * 16, Bt + (size_t)(bn + r) * 4096 + w_col + c * 8);
        }
    };

    load_stage(0); asm volatile("cp.async.commit_group;");
    load_stage(1); asm volatile("cp.async.commit_group;");

    const int a_row_in = lane & 15;
    const int a_ksel   = (lane >> 4) * 16;
    const int b_sel    = (lane >> 3) & 3;
    const int b_row_in = ((b_sel >> 1) << 3) + (lane & 7);
    const int b_ksel   = (b_sel & 1) * 16;

    for (int kc = 0; kc < GEMM_NKC; kc++) {
        asm volatile("cp.async.wait_group 1;");
        __syncthreads();
        if (kc + 2 < GEMM_NKC) {
            load_stage(kc + 2);
            asm volatile("cp.async.commit_group;");
        }

        int slot = kc % 3;
        uint32_t sA = smem_b + slot * STAGE + (warp_m * 64) * A_ROW_B;
        uint32_t sB = smem_b + slot * STAGE + A_TILE_B + (warp_n * COLS_W) * A_ROW_B;

        #pragma unroll
        for (int kk = 0; kk < 4; kk++) {
            uint32_t kbyte = kk * 32;
            uint32_t afr[4][4];
            #pragma unroll
            for (int fm = 0; fm < 4; fm++)
                ldsm_x4(afr[fm], sA + (fm * 16 + a_row_in) * A_ROW_B + kbyte + a_ksel);
            #pragma unroll
            for (int fn2 = 0; fn2 < NF2; fn2++) {
                uint32_t bfr[4];
                ldsm_x4(bfr, sB + (fn2 * 16 + b_row_in) * A_ROW_B + kbyte + b_ksel);
                #pragma unroll
                for (int fm = 0; fm < 4; fm++) {
                    mma16816(acc[fm][fn2 * 2 + 0], afr[fm], bfr[0], bfr[1]);
                    mma16816(acc[fm][fn2 * 2 + 1], afr[fm], bfr[2], bfr[3]);
                }
            }
        }
    }

    // ---- fused epilogue ----
    const int row0 = bm + warp_m * 64 + (lane >> 2);
    const int col0 = bn + warp_n * COLS_W + (lane & 3) * 2;
    #pragma unroll
    for (int fm = 0; fm < 4; fm++) {
        #pragma unroll
        for (int fn = 0; fn < 2 * NF2; fn++) {
            const int c = col0 + fn * 8;
            const float b0 = bias[c], b1 = bias[c + 1];
            const int r0 = row0 + fm * 16;
            float w[2][2] = {{acc[fm][fn][0] + b0, acc[fm][fn][1] + b1},
                             {acc[fm][fn][2] + b0, acc[fm][fn][3] + b1}};
            if (MODE == 0) {
                *(float2*)(C + (size_t)r0 * Ndim + c)       = make_float2(w[0][0], w[0][1]);
                *(float2*)(C + (size_t)(r0 + 8) * Ndim + c) = make_float2(w[1][0], w[1][1]);
            } else if (MODE == 1 || MODE == 2) {
                constexpr int NH = (MODE == 1) ? 32 : 8;
                __nv_bfloat16* dst = (MODE == 1) ? g_qb : g_kb;
                const int hh = c >> 6, d = c & 63;
                #pragma unroll
                for (int rr = 0; rr < 2; rr++) {
                    int r = r0 + rr * 8;
                    int b = r >> 11, mm = r & 2047;
                    float l0, l1;
                    __nv_bfloat162 hi = bf16_pair_hi(w[rr][0], w[rr][1], l0, l1);
                    size_t base = ((size_t)(b * NH + hh) * 2048 + mm) * 128 + d;
                    *(__nv_bfloat162*)(dst + base)      = hi;
                    *(__nv_bfloat162*)(dst + base + 64) = __nv_bfloat162(
                        __float2bfloat16(l0), __float2bfloat16(l1));
                }
            } else {  // MODE 3: V^T fp16
                const int kvh = c >> 6, d = c & 63;
                #pragma unroll
                for (int rr = 0; rr < 2; rr++) {
                    int r = r0 + rr * 8;
                    int b = r >> 11, mm = r & 2047;
                    size_t base = ((size_t)(b * 8 + kvh) * 64 + d) * 2048 + mm;
                    g_vt[base]        = __float2half_rn(w[rr][0]);
                    g_vt[base + 2048] = __float2half_rn(w[rr][1]);
                }
            }
        }
    }
}

constexpr int GEMM_SMEM_256 = 3 * (A_TILE_B + 256 * A_ROW_B);  // 165888
constexpr int GEMM_SMEM_128 = 3 * (A_TILE_B + 128 * A_ROW_B);  // 110592

// ---------------------------------------------------------------------------
// Flash attention on mma.sync (validated R8), epilogue fused to ctxc hi/lo.
// ---------------------------------------------------------------------------
constexpr int ANB     = S_ / 64;
constexpr int QROW    = 272;
constexpr int KROW    = 272;
constexpr int VROW    = 144;
constexpr int QBYTES  = 128 * QROW;
constexpr int KTILE   = 64 * KROW;
constexpr int VTILE   = 64 * VROW;
constexpr int ASTG    = KTILE + VTILE;
constexpr int ATT_SMEM = QBYTES + 3 * ASTG;  // 114688

__global__ __launch_bounds__(256)
void attn_mma_kernel()
{
    extern __shared__ __align__(128) char smem[];
    const uint32_t sb = smem_u32_of(smem);
    const int tid  = threadIdx.x;
    const int lane = tid & 31, wid = tid >> 5;

    const int bh  = blockIdx.y;
    const int b   = bh >> 5;
    const int h   = bh & 31;
    const int kvh = h >> 2;
    const int bk  = b * HKV_ + kvh;
    const int m0  = blockIdx.x * 128;

    const __nv_bfloat16* qbase = g_qb + ((size_t)bh * S_ + m0) * 128;
    const __nv_bfloat16* kbase = g_kb + ((size_t)bk * S_) * 128;
    const __half*        vbase = g_vt + ((size_t)bk * 64) * (size_t)S_;

    #pragma unroll
    for (int it = 0; it < 8; it++) {
        int idx = tid + it * 256;
        int r = idx >> 4, c = idx & 15;
        cp16(sb + r * QROW + c * 16, qbase + (size_t)r * 128 + c * 8);
    }
    asm volatile("cp.async.commit_group;");

    auto load_stage = [&](int kbi) {
        int slot = kbi % 3;
        int n0 = kbi * 64;
        uint32_t sK = sb + QBYTES + slot * ASTG;
        uint32_t sV = sK + KTILE;
        #pragma unroll
        for (int it = 0; it < 4; it++) {
            int idx = tid + it * 256;
            int r = idx >> 4, c = idx & 15;
            cp16(sK + r * KROW + c * 16, kbase + (size_t)(n0 + r) * 128 + c * 8);
        }
        #pragma unroll
        for (int it = 0; it < 2; it++) {
            int idx = tid + it * 256;
            int r = idx >> 3, c = idx & 7;
            cp16(sV + r * VROW + c * 16, vbase + (size_t)r * S_ + n0 + c * 8);
        }
    };
    load_stage(0); asm volatile("cp.async.commit_group;");
    load_stage(1); asm volatile("cp.async.commit_group;");

    asm volatile("cp.async.wait_group 2;");
    __syncthreads();

    const int a_row_in = lane & 15;
    const int a_ksel   = (lane >> 4) * 16;
    const int b_sel    = (lane >> 3) & 3;
    const int b_row_in = ((b_sel >> 1) << 3) + (lane & 7);
    const int b_ksel   = (b_sel & 1) * 16;

    uint32_t qhi[4][4], qlo[4][4];
    {
        uint32_t qa = sb + (wid * 16 + a_row_in) * QROW + a_ksel;
        #pragma unroll
        for (int kf = 0; kf < 4; kf++) {
            ldsm_x4(qhi[kf], qa + kf * 32);
            ldsm_x4(qlo[kf], qa + 128 + kf * 32);
        }
    }

    float o[8][4];
    #pragma unroll
    for (int f = 0; f < 8; f++)
        #pragma unroll
        for (int e = 0; e < 4; e++) o[f][e] = 0.0f;
    float m0r = -INFINITY, m1r = -INFINITY, l0r = 0.0f, l1r = 0.0f;

    const float sscale = 0.125f * 1.44269504088896f;

    for (int kbi = 0; kbi < ANB; kbi++) {
        if (kbi == ANB - 1) { asm volatile("cp.async.wait_group 0;"); }
        else                { asm volatile("cp.async.wait_group 1;"); }
        __syncthreads();
        if (kbi + 2 < ANB) {
            load_stage(kbi + 2);
            asm volatile("cp.async.commit_group;");
        }

        const uint32_t sK = sb + QBYTES + (kbi % 3) * ASTG;
        const uint32_t sV = sK + KTILE;

        float sc[8][4];
        #pragma unroll
        for (int f = 0; f < 8; f++)
            #pragma unroll
            for (int e = 0; e < 4; e++) sc[f][e] = 0.0f;

        #pragma unroll
        for (int kf = 0; kf < 4; kf++) {
            #pragma unroll
            for (int fn2 = 0; fn2 < 4; fn2++) {
                uint32_t bfr[4];
                ldsm_x4(bfr, sK + (fn2 * 16 + b_row_in) * KROW + kf * 32 + b_ksel);
                mma16816(sc[fn2 * 2 + 0], qhi[kf], bfr[0], bfr[1]);
                mma16816(sc[fn2 * 2 + 1], qhi[kf], bfr[2], bfr[3]);
                mma16816(sc[fn2 * 2 + 0], qlo[kf], bfr[0], bfr[1]);
                mma16816(sc[fn2 * 2 + 1], qlo[kf], bfr[2], bfr[3]);
            }
            #pragma unroll
            for (int fn2 = 0; fn2 < 4; fn2++) {
                uint32_t bfr[4];
                ldsm_x4(bfr, sK + (fn2 * 16 + b_row_in) * KROW + 128 + kf * 32 + b_ksel);
                mma16816(sc[fn2 * 2 + 0], qhi[kf], bfr[0], bfr[1]);
                mma16816(sc[fn2 * 2 + 1], qhi[kf], bfr[2], bfr[3]);
            }
        }

        #pragma unroll
        for (int f = 0; f < 8; f++)
            #pragma unroll
            for (int e = 0; e < 4; e++) sc[f][e] *= sscale;

        float mx0 = -INFINITY, mx1 = -INFINITY;
        #pragma unroll
        for (int f = 0; f < 8; f++) {
            mx0 = fmaxf(mx0, fmaxf(sc[f][0], sc[f][1]));
            mx1 = fmaxf(mx1, fmaxf(sc[f][2], sc[f][3]));
        }
        mx0 = fmaxf(mx0, __shfl_xor_sync(0xffffffffu, mx0, 1));
        mx0 = fmaxf(mx0, __shfl_xor_sync(0xffffffffu, mx0, 2));
        mx1 = fmaxf(mx1, __shfl_xor_sync(0xffffffffu, mx1, 1));
        mx1 = fmaxf(mx1, __shfl_xor_sync(0xffffffffu, mx1, 2));

        float mn0 = fmaxf(m0r, mx0), mn1 = fmaxf(m1r, mx1);
        float c0 = exp2f(m0r - mn0), c1 = exp2f(m1r - mn1);

        float rs0 = 0.0f, rs1 = 0.0f;
        #pragma unroll
        for (int f = 0; f < 8; f++) {
            sc[f][0] = exp2f(sc[f][0] - mn0); rs0 += sc[f][0];
            sc[f][1] = exp2f(sc[f][1] - mn0); rs0 += sc[f][1];
            sc[f][2] = exp2f(sc[f][2] - mn1); rs1 += sc[f][2];
            sc[f][3] = exp2f(sc[f][3] - mn1); rs1 += sc[f][3];
        }
        rs0 += __shfl_xor_sync(0xffffffffu, rs0, 1);
        rs0 += __shfl_xor_sync(0xffffffffu, rs0, 2);
        rs1 += __shfl_xor_sync(0xffffffffu, rs1, 1);
        rs1 += __shfl_xor_sync(0xffffffffu, rs1, 2);

        l0r = l0r * c0 + rs0;
        l1r = l1r * c1 + rs1;
        m0r = mn0; m1r = mn1;
        #pragma unroll
        for (int f = 0; f < 8; f++) {
            o[f][0] *= c0; o[f][1] *= c0;
            o[f][2] *= c1; o[f][3] *= c1;
        }

        #pragma unroll
        for (int j = 0; j < 4; j++) {
            uint32_t a[4];
            __half2 t;
            t = __floats2half2_rn(sc[2 * j][0],     sc[2 * j][1]);     a[0] = *(uint32_t*)&t;
            t = __floats2half2_rn(sc[2 * j][2],     sc[2 * j][3]);     a[1] = *(uint32_t*)&t;
            t = __floats2half2_rn(sc[2 * j + 1][0], sc[2 * j + 1][1]); a[2] = *(uint32_t*)&t;
            t = __floats2half2_rn(sc[2 * j + 1][2], sc[2 * j + 1][3]); a[3] = *(uint32_t*)&t;
            #pragma unroll
            for (int fn2 = 0; fn2 < 4; fn2++) {
                uint32_t bfr[4];
                ldsm_x4(bfr, sV + (fn2 * 16 + b_row_in) * VROW + j * 32 + b_ksel);
                mma16816h(o[fn2 * 2 + 0], a, bfr[0], bfr[1]);
                mma16816h(o[fn2 * 2 + 1], a, bfr[2], bfr[3]);
            }
        }
    }

    // ---- epilogue: write ctxc bf16 hi/lo directly ----
    const float inv0 = 1.0f / l0r, inv1 = 1.0f / l1r;
    const int rowg = b * S_ + m0 + wid * 16 + (lane >> 2);
    const int colb = h * 64 + 2 * (lane & 3);
    #pragma unroll
    for (int f = 0; f < 8; f++) {
        int col = colb + 8 * f;
        float v0 = o[f][0] * inv0, v1 = o[f][1] * inv0;
        float v2 = o[f][2] * inv1, v3 = o[f][3] * inv1;
        float l0, l1;
        __nv_bfloat162 hi0 = bf16_pair_hi(v0, v1, l0, l1);
        *(__nv_bfloat162*)(g_ctxc + (size_t)rowg * 4096 + col) = hi0;
        *(__nv_bfloat162*)(g_ctxc + (size_t)rowg * 4096 + 2048 + col) =
            __nv_bfloat162(__float2bfloat16(l0), __float2bfloat16(l1));
        __nv_bfloat162 hi1 = bf16_pair_hi(v2, v3, l0, l1);
        *(__nv_bfloat162*)(g_ctxc + (size_t)(rowg + 8) * 4096 + col) = hi1;
        *(__nv_bfloat162*)(g_ctxc + (size_t)(rowg + 8) * 4096 + 2048 + col) =
            __nv_bfloat162(__float2bfloat16(l0), __float2bfloat16(l1));
    }
}

// ---------------------------------------------------------------------------
// Launch
// ---------------------------------------------------------------------------
extern "C" void kernel_launch(void* const* d_in, const int* in_sizes, int n_in,
                              void* d_out, int out_size)
{
    const float* x  = (const float*)d_in[0];
    const float* Wq = (const float*)d_in[1];
    const float* bq = (const float*)d_in[2];
    const float* Wk = (const float*)d_in[3];
    const float* bk = (const float*)d_in[4];
    const float* Wv = (const float*)d_in[5];
    const float* bv = (const float*)d_in[6];
    const float* Wo = (const float*)d_in[7];
    const float* bo = (const float*)d_in[8];
    float* out = (float*)d_out;

    __nv_bfloat16 *xc, *ctxc, *wqt, *wkt, *wvt, *wot;
    cudaGetSymbolAddress((void**)&xc,   g_xc);
    cudaGetSymbolAddress((void**)&ctxc, g_ctxc);
    cudaGetSymbolAddress((void**)&wqt,  g_wqt);
    cudaGetSymbolAddress((void**)&wkt,  g_wkt);
    cudaGetSymbolAddress((void**)&wvt,  g_wvt);
    cudaGetSymbolAddress((void**)&wot,  g_wot);

    cudaFuncSetAttribute(gemm_mma_kernel<256, 1>,
                         cudaFuncAttributeMaxDynamicSharedMemorySize, GEMM_SMEM_256);
    cudaFuncSetAttribute(gemm_mma_kernel<128, 2>,
                         cudaFuncAttributeMaxDynamicSharedMemorySize, GEMM_SMEM_128);
    cudaFuncSetAttribute(gemm_mma_kernel<128, 3>,
                         cudaFuncAttributeMaxDynamicSharedMemorySize, GEMM_SMEM_128);
    cudaFuncSetAttribute(gemm_mma_kernel<256, 0>,
                         cudaFuncAttributeMaxDynamicSharedMemorySize, GEMM_SMEM_256);
    cudaFuncSetAttribute(attn_mma_kernel,
                         cudaFuncAttributeMaxDynamicSharedMemorySize, ATT_SMEM);

    // input conversions
    convert_rows_kernel<<<2048, 256>>>(x, xc, M_ * D_, D_);
    convert_transpose_kernel<<<dim3(D_ / 32,   D_ / 32), dim3(32, 8)>>>(Wq, wqt, D_, D_);
    convert_transpose_kernel<<<dim3(KVD_ / 32, D_ / 32), dim3(32, 8)>>>(Wk, wkt, D_, KVD_);
    convert_transpose_kernel<<<dim3(KVD_ / 32, D_ / 32), dim3(32, 8)>>>(Wv, wvt, D_, KVD_);
    convert_transpose_kernel<<<dim3(D_ / 32,   D_ / 32), dim3(32, 8)>>>(Wo, wot, D_, D_);

    // projections with fused attention-layout epilogues
    gemm_mma_kernel<256, 1><<<dim3(D_ / 256,   M_ / 128), 256, GEMM_SMEM_256>>>(
        xc, wqt, bq, nullptr, D_);
    gemm_mma_kernel<128, 2><<<dim3(KVD_ / 128, M_ / 128), 256, GEMM_SMEM_128>>>(
        xc, wkt, bk, nullptr, KVD_);
    gemm_mma_kernel<128, 3><<<dim3(KVD_ / 128, M_ / 128), 256, GEMM_SMEM_128>>>(
        xc, wvt, bv, nullptr, KVD_);

    // attention (writes ctxc hi/lo directly)
    attn_mma_kernel<<<dim3(S_ / 128, B_ * H_), 256, ATT_SMEM>>>();

    // output projection
    gemm_mma_kernel<256, 0><<<dim3(D_ / 256, M_ / 128), 256, GEMM_SMEM_256>>>(
        ctxc, wot, bo, out, D_);
}

// round 10
// speedup vs baseline: 3.4595x; 1.0194x over previous
#include <cuda_runtime.h>
#include <cuda_bf16.h>
#include <cuda_fp16.h>
#include <cstdint>
#include <math.h>

// Problem constants
constexpr int B_   = 2;
constexpr int S_   = 2048;
constexpr int D_   = 2048;
constexpr int H_   = 32;
constexpr int HKV_ = 8;
constexpr int DH_  = 64;
constexpr int M_   = B_ * S_;      // 4096 rows
constexpr int KVD_ = HKV_ * DH_;   // 512
constexpr int NQKV = D_ + 2 * KVD_; // 3072

// bf16 split (hi|lo along K) GEMM operands (__device__ globals: allocation-free rule)
__device__ __nv_bfloat16 g_xc   [M_ * 2 * D_];
__device__ __nv_bfloat16 g_ctxc [M_ * 2 * D_];
__device__ __nv_bfloat16 g_wqkvt[NQKV * 2 * D_];   // rows: 0..2047 Wq | 2048..2559 Wk | 2560..3071 Wv
__device__ __nv_bfloat16 g_wot  [D_ * 2 * D_];

// attention operands (written directly by GEMM epilogues)
__device__ __nv_bfloat16 g_qb[B_ * H_   * S_ * 128];  // [b,h][m][hi64|lo64] bf16
__device__ __nv_bfloat16 g_kb[B_ * HKV_ * S_ * 128];  // [b,kvh][n][hi64|lo64] bf16
__device__ __half        g_vt[B_ * HKV_ * 64 * S_];   // [b,kvh][d][n] fp16 (V^T)

__device__ __forceinline__ uint32_t smem_u32_of(const void* p) {
    uint32_t a;
    asm("{ .reg .u64 t; cvta.to.shared.u64 t, %1; cvt.u32.u64 %0, t; }" : "=r"(a) : "l"(p));
    return a;
}
__device__ __forceinline__ void ldsm_x4(uint32_t (&r)[4], uint32_t addr) {
    asm volatile("ldmatrix.sync.aligned.m8n8.x4.shared.b16 {%0,%1,%2,%3}, [%4];"
                 : "=r"(r[0]), "=r"(r[1]), "=r"(r[2]), "=r"(r[3]) : "r"(addr));
}
__device__ __forceinline__ void mma16816(float (&c)[4], const uint32_t (&a)[4],
                                         uint32_t b0, uint32_t b1) {
    asm volatile(
        "mma.sync.aligned.m16n8k16.row.col.f32.bf16.bf16.f32 "
        "{%0,%1,%2,%3}, {%4,%5,%6,%7}, {%8,%9}, {%0,%1,%2,%3};"
        : "+f"(c[0]), "+f"(c[1]), "+f"(c[2]), "+f"(c[3])
        : "r"(a[0]), "r"(a[1]), "r"(a[2]), "r"(a[3]), "r"(b0), "r"(b1));
}
__device__ __forceinline__ void mma16816h(float (&c)[4], const uint32_t (&a)[4],
                                          uint32_t b0, uint32_t b1) {
    asm volatile(
        "mma.sync.aligned.m16n8k16.row.col.f32.f16.f16.f32 "
        "{%0,%1,%2,%3}, {%4,%5,%6,%7}, {%8,%9}, {%0,%1,%2,%3};"
        : "+f"(c[0]), "+f"(c[1]), "+f"(c[2]), "+f"(c[3])
        : "r"(a[0]), "r"(a[1]), "r"(a[2]), "r"(a[3]), "r"(b0), "r"(b1));
}
__device__ __forceinline__ void cp16(uint32_t dst, const void* src) {
    asm volatile("cp.async.cg.shared.global [%0], [%1], 16;" :: "r"(dst), "l"(src));
}
__device__ __forceinline__ __nv_bfloat162 bf16_pair_hi(float a, float b,
                                                       float& la, float& lb) {
    __nv_bfloat16 ha = __float2bfloat16(a), hb = __float2bfloat16(b);
    la = a - __bfloat162float(ha);
    lb = b - __bfloat162float(hb);
    return __nv_bfloat162(ha, hb);
}

// ---------------------------------------------------------------------------
// Conversion kernels (inputs only)
// ---------------------------------------------------------------------------
__global__ void convert_rows_kernel(const float* __restrict__ src,
                                    __nv_bfloat16* __restrict__ dst, int total, int K)
{
    for (int i = blockIdx.x * blockDim.x + threadIdx.x; i < total;
         i += gridDim.x * blockDim.x) {
        int m = i / K, k = i - m * K;
        float x = src[i];
        __nv_bfloat16 h = __float2bfloat16(x);
        float lo = x - __bfloat162float(h);
        dst[(size_t)m * 2 * K + k]     = h;
        dst[(size_t)m * 2 * K + K + k] = __float2bfloat16(lo);
    }
}

__global__ void convert_transpose_kernel(const float* __restrict__ W,
                                         __nv_bfloat16* __restrict__ Wt, int K, int N)
{
    __shared__ float tile[32][33];
    int k0 = blockIdx.y * 32, n0 = blockIdx.x * 32;
    int tx = threadIdx.x, ty = threadIdx.y;
    #pragma unroll
    for (int dy = 0; dy < 32; dy += 8)
        tile[ty + dy][tx] = W[(size_t)(k0 + ty + dy) * N + n0 + tx];
    __syncthreads();
    #pragma unroll
    for (int dy = 0; dy < 32; dy += 8) {
        int n = n0 + ty + dy;
        float x = tile[tx][ty + dy];
        __nv_bfloat16 h = __float2bfloat16(x);
        Wt[(size_t)n * 2 * K + k0 + tx]     = h;
        Wt[(size_t)n * 2 * K + K + k0 + tx] = __float2bfloat16(x - __bfloat162float(h));
    }
}

// ---------------------------------------------------------------------------
// HMMA GEMM, BK=64 per stage, 3-stage cp.async, fused epilogues.
// MODE: 0 = f32+bias -> C ; 4 = fused QKV routing -> g_qb / g_kb / g_vt
// ---------------------------------------------------------------------------
constexpr int A_ROW_B  = 144;                 // 128B data + 16B pad
constexpr int A_TILE_B = 128 * A_ROW_B;       // 18432
constexpr int GEMM_NKC = 96;                  // 6144 / 64

template<int BN, int MODE>
__global__ __launch_bounds__(256, 1)
void gemm_mma_kernel(const __nv_bfloat16* __restrict__ A,
                     const __nv_bfloat16* __restrict__ Bt,
                     const float* __restrict__ bias,
                     const float* __restrict__ bias2,
                     const float* __restrict__ bias3,
                     float* __restrict__ C, int Ndim)
{
    constexpr int COLS_W = BN / 4;
    constexpr int NF2    = COLS_W / 16;
    constexpr int B_TILE = BN * A_ROW_B;
    constexpr int STAGE  = A_TILE_B + B_TILE;

    extern __shared__ __align__(128) char smem[];
    const uint32_t smem_b = smem_u32_of(smem);
    const int tid  = threadIdx.x;
    const int lane = tid & 31, wid = tid >> 5;
    const int warp_m = wid & 1;
    const int warp_n = wid >> 1;
    const int bm = blockIdx.y * 128;
    const int bn = blockIdx.x * BN;

    float acc[4][2 * NF2][4];
    #pragma unroll
    for (int i = 0; i < 4; i++)
        #pragma unroll
        for (int j = 0; j < 2 * NF2; j++)
            #pragma unroll
            for (int e = 0; e < 4; e++) acc[i][j][e] = 0.0f;

    auto load_stage = [&](int kc) {
        int slot = kc % 3;
        int seg = kc >> 5, within = (kc & 31) * 64;
        int a_col = within + ((seg == 1) ? 2048 : 0);
        int w_col = within + ((seg == 2) ? 2048 : 0);
        uint32_t sA = smem_b + slot * STAGE;
        uint32_t sB = sA + A_TILE_B;
        #pragma unroll
        for (int it = 0; it < 4; it++) {
            int idx = tid + it * 256;
            int r = idx >> 3, c = idx & 7;
            cp16(sA + r * A_ROW_B + c * 16, A + (size_t)(bm + r) * 4096 + a_col + c * 8);
        }
        #pragma unroll
        for (int it = 0; it < BN / 32; it++) {
            int idx = tid + it * 256;
            int r = idx >> 3, c = idx & 7;
            cp16(sB + r * A_ROW_B + c * 16, Bt + (size_t)(bn + r) * 4096 + w_col + c * 8);
        }
    };

    load_stage(0); asm volatile("cp.async.commit_group;");
    load_stage(1); asm volatile("cp.async.commit_group;");

    const int a_row_in = lane & 15;
    const int a_ksel   = (lane >> 4) * 16;
    const int b_sel    = (lane >> 3) & 3;
    const int b_row_in = ((b_sel >> 1) << 3) + (lane & 7);
    const int b_ksel   = (b_sel & 1) * 16;

    for (int kc = 0; kc < GEMM_NKC; kc++) {
        asm volatile("cp.async.wait_group 1;");
        __syncthreads();
        if (kc + 2 < GEMM_NKC) {
            load_stage(kc + 2);
            asm volatile("cp.async.commit_group;");
        }

        int slot = kc % 3;
        uint32_t sA = smem_b + slot * STAGE + (warp_m * 64) * A_ROW_B;
        uint32_t sB = smem_b + slot * STAGE + A_TILE_B + (warp_n * COLS_W) * A_ROW_B;

        #pragma unroll
        for (int kk = 0; kk < 4; kk++) {
            uint32_t kbyte = kk * 32;
            uint32_t afr[4][4];
            #pragma unroll
            for (int fm = 0; fm < 4; fm++)
                ldsm_x4(afr[fm], sA + (fm * 16 + a_row_in) * A_ROW_B + kbyte + a_ksel);
            #pragma unroll
            for (int fn2 = 0; fn2 < NF2; fn2++) {
                uint32_t bfr[4];
                ldsm_x4(bfr, sB + (fn2 * 16 + b_row_in) * A_ROW_B + kbyte + b_ksel);
                #pragma unroll
                for (int fm = 0; fm < 4; fm++) {
                    mma16816(acc[fm][fn2 * 2 + 0], afr[fm], bfr[0], bfr[1]);
                    mma16816(acc[fm][fn2 * 2 + 1], afr[fm], bfr[2], bfr[3]);
                }
            }
        }
    }

    // ---- fused epilogue ----
    const int row0 = bm + warp_m * 64 + (lane >> 2);
    const int col0 = bn + warp_n * COLS_W + (lane & 3) * 2;
    #pragma unroll
    for (int fm = 0; fm < 4; fm++) {
        #pragma unroll
        for (int fn = 0; fn < 2 * NF2; fn++) {
            const int c = col0 + fn * 8;
            const int r0 = row0 + fm * 16;
            if (MODE == 0) {
                const float b0 = bias[c], b1 = bias[c + 1];
                float2 v0 = make_float2(acc[fm][fn][0] + b0, acc[fm][fn][1] + b1);
                float2 v1 = make_float2(acc[fm][fn][2] + b0, acc[fm][fn][3] + b1);
                *(float2*)(C + (size_t)r0 * Ndim + c)       = v0;
                *(float2*)(C + (size_t)(r0 + 8) * Ndim + c) = v1;
            } else {  // MODE 4: route by section
                float b0, b1;
                if (c < 2048)      { b0 = bias [c];        b1 = bias [c + 1]; }
                else if (c < 2560) { b0 = bias2[c - 2048]; b1 = bias2[c - 2047]; }
                else               { b0 = bias3[c - 2560]; b1 = bias3[c - 2559]; }
                float w[2][2] = {{acc[fm][fn][0] + b0, acc[fm][fn][1] + b1},
                                 {acc[fm][fn][2] + b0, acc[fm][fn][3] + b1}};
                if (c < 2560) {
                    // Q (c<2048) -> g_qb ; K -> g_kb. Both bf16 hi/lo layouts.
                    const bool isQ = (c < 2048);
                    const int cc   = isQ ? c : (c - 2048);
                    const int NH   = isQ ? 32 : 8;
                    __nv_bfloat16* dst = isQ ? g_qb : g_kb;
                    const int hh = cc >> 6, d = cc & 63;
                    #pragma unroll
                    for (int rr = 0; rr < 2; rr++) {
                        int r = r0 + rr * 8;
                        int b = r >> 11, mm = r & 2047;
                        float l0, l1;
                        __nv_bfloat162 hi = bf16_pair_hi(w[rr][0], w[rr][1], l0, l1);
                        size_t base = ((size_t)(b * NH + hh) * 2048 + mm) * 128 + d;
                        *(__nv_bfloat162*)(dst + base)      = hi;
                        *(__nv_bfloat162*)(dst + base + 64) = __nv_bfloat162(
                            __float2bfloat16(l0), __float2bfloat16(l1));
                    }
                } else {
                    // V -> g_vt fp16 transposed
                    const int cc = c - 2560;
                    const int kvh = cc >> 6, d = cc & 63;
                    #pragma unroll
                    for (int rr = 0; rr < 2; rr++) {
                        int r = r0 + rr * 8;
                        int b = r >> 11, mm = r & 2047;
                        size_t base = ((size_t)(b * 8 + kvh) * 64 + d) * 2048 + mm;
                        g_vt[base]        = __float2half_rn(w[rr][0]);
                        g_vt[base + 2048] = __float2half_rn(w[rr][1]);
                    }
                }
            }
        }
    }
}

constexpr int GEMM_SMEM_256 = 3 * (A_TILE_B + 256 * A_ROW_B);  // 165888

// ---------------------------------------------------------------------------
// Flash attention on mma.sync (validated R8/R9), epilogue fused to ctxc hi/lo.
// ---------------------------------------------------------------------------
constexpr int ANB     = S_ / 64;
constexpr int QROW    = 272;
constexpr int KROW    = 272;
constexpr int VROW    = 144;
constexpr int QBYTES  = 128 * QROW;
constexpr int KTILE   = 64 * KROW;
constexpr int VTILE   = 64 * VROW;
constexpr int ASTG    = KTILE + VTILE;
constexpr int ATT_SMEM = QBYTES + 3 * ASTG;  // 114688

__global__ __launch_bounds__(256)
void attn_mma_kernel()
{
    extern __shared__ __align__(128) char smem[];
    const uint32_t sb = smem_u32_of(smem);
    const int tid  = threadIdx.x;
    const int lane = tid & 31, wid = tid >> 5;

    const int bh  = blockIdx.y;
    const int b   = bh >> 5;
    const int h   = bh & 31;
    const int kvh = h >> 2;
    const int bk  = b * HKV_ + kvh;
    const int m0  = blockIdx.x * 128;

    const __nv_bfloat16* qbase = g_qb + ((size_t)bh * S_ + m0) * 128;
    const __nv_bfloat16* kbase = g_kb + ((size_t)bk * S_) * 128;
    const __half*        vbase = g_vt + ((size_t)bk * 64) * (size_t)S_;

    #pragma unroll
    for (int it = 0; it < 8; it++) {
        int idx = tid + it * 256;
        int r = idx >> 4, c = idx & 15;
        cp16(sb + r * QROW + c * 16, qbase + (size_t)r * 128 + c * 8);
    }
    asm volatile("cp.async.commit_group;");

    auto load_stage = [&](int kbi) {
        int slot = kbi % 3;
        int n0 = kbi * 64;
        uint32_t sK = sb + QBYTES + slot * ASTG;
        uint32_t sV = sK + KTILE;
        #pragma unroll
        for (int it = 0; it < 4; it++) {
            int idx = tid + it * 256;
            int r = idx >> 4, c = idx & 15;
            cp16(sK + r * KROW + c * 16, kbase + (size_t)(n0 + r) * 128 + c * 8);
        }
        #pragma unroll
        for (int it = 0; it < 2; it++) {
            int idx = tid + it * 256;
            int r = idx >> 3, c = idx & 7;
            cp16(sV + r * VROW + c * 16, vbase + (size_t)r * S_ + n0 + c * 8);
        }
    };
    load_stage(0); asm volatile("cp.async.commit_group;");
    load_stage(1); asm volatile("cp.async.commit_group;");

    asm volatile("cp.async.wait_group 2;");
    __syncthreads();

    const int a_row_in = lane & 15;
    const int a_ksel   = (lane >> 4) * 16;
    const int b_sel    = (lane >> 3) & 3;
    const int b_row_in = ((b_sel >> 1) << 3) + (lane & 7);
    const int b_ksel   = (b_sel & 1) * 16;

    uint32_t qhi[4][4], qlo[4][4];
    {
        uint32_t qa = sb + (wid * 16 + a_row_in) * QROW + a_ksel;
        #pragma unroll
        for (int kf = 0; kf < 4; kf++) {
            ldsm_x4(qhi[kf], qa + kf * 32);
            ldsm_x4(qlo[kf], qa + 128 + kf * 32);
        }
    }

    float o[8][4];
    #pragma unroll
    for (int f = 0; f < 8; f++)
        #pragma unroll
        for (int e = 0; e < 4; e++) o[f][e] = 0.0f;
    float m0r = -INFINITY, m1r = -INFINITY, l0r = 0.0f, l1r = 0.0f;

    const float sscale = 0.125f * 1.44269504088896f;

    for (int kbi = 0; kbi < ANB; kbi++) {
        if (kbi == ANB - 1) { asm volatile("cp.async.wait_group 0;"); }
        else                { asm volatile("cp.async.wait_group 1;"); }
        __syncthreads();
        if (kbi + 2 < ANB) {
            load_stage(kbi + 2);
            asm volatile("cp.async.commit_group;");
        }

        const uint32_t sK = sb + QBYTES + (kbi % 3) * ASTG;
        const uint32_t sV = sK + KTILE;

        float sc[8][4];
        #pragma unroll
        for (int f = 0; f < 8; f++)
            #pragma unroll
            for (int e = 0; e < 4; e++) sc[f][e] = 0.0f;

        #pragma unroll
        for (int kf = 0; kf < 4; kf++) {
            #pragma unroll
            for (int fn2 = 0; fn2 < 4; fn2++) {
                uint32_t bfr[4];
                ldsm_x4(bfr, sK + (fn2 * 16 + b_row_in) * KROW + kf * 32 + b_ksel);
                mma16816(sc[fn2 * 2 + 0], qhi[kf], bfr[0], bfr[1]);
                mma16816(sc[fn2 * 2 + 1], qhi[kf], bfr[2], bfr[3]);
                mma16816(sc[fn2 * 2 + 0], qlo[kf], bfr[0], bfr[1]);
                mma16816(sc[fn2 * 2 + 1], qlo[kf], bfr[2], bfr[3]);
            }
            #pragma unroll
            for (int fn2 = 0; fn2 < 4; fn2++) {
                uint32_t bfr[4];
                ldsm_x4(bfr, sK + (fn2 * 16 + b_row_in) * KROW + 128 + kf * 32 + b_ksel);
                mma16816(sc[fn2 * 2 + 0], qhi[kf], bfr[0], bfr[1]);
                mma16816(sc[fn2 * 2 + 1], qhi[kf], bfr[2], bfr[3]);
            }
        }

        #pragma unroll
        for (int f = 0; f < 8; f++)
            #pragma unroll
            for (int e = 0; e < 4; e++) sc[f][e] *= sscale;

        float mx0 = -INFINITY, mx1 = -INFINITY;
        #pragma unroll
        for (int f = 0; f < 8; f++) {
            mx0 = fmaxf(mx0, fmaxf(sc[f][0], sc[f][1]));
            mx1 = fmaxf(mx1, fmaxf(sc[f][2], sc[f][3]));
        }
        mx0 = fmaxf(mx0, __shfl_xor_sync(0xffffffffu, mx0, 1));
        mx0 = fmaxf(mx0, __shfl_xor_sync(0xffffffffu, mx0, 2));
        mx1 = fmaxf(mx1, __shfl_xor_sync(0xffffffffu, mx1, 1));
        mx1 = fmaxf(mx1, __shfl_xor_sync(0xffffffffu, mx1, 2));

        float mn0 = fmaxf(m0r, mx0), mn1 = fmaxf(m1r, mx1);
        float c0 = exp2f(m0r - mn0), c1 = exp2f(m1r - mn1);

        float rs0 = 0.0f, rs1 = 0.0f;
        #pragma unroll
        for (int f = 0; f < 8; f++) {
            sc[f][0] = exp2f(sc[f][0] - mn0); rs0 += sc[f][0];
            sc[f][1] = exp2f(sc[f][1] - mn0); rs0 += sc[f][1];
            sc[f][2] = exp2f(sc[f][2] - mn1); rs1 += sc[f][2];
            sc[f][3] = exp2f(sc[f][3] - mn1); rs1 += sc[f][3];
        }
        rs0 += __shfl_xor_sync(0xffffffffu, rs0, 1);
        rs0 += __shfl_xor_sync(0xffffffffu, rs0, 2);
        rs1 += __shfl_xor_sync(0xffffffffu, rs1, 1);
        rs1 += __shfl_xor_sync(0xffffffffu, rs1, 2);

        l0r = l0r * c0 + rs0;
        l1r = l1r * c1 + rs1;
        m0r = mn0; m1r = mn1;
        #pragma unroll
        for (int f = 0; f < 8; f++) {
            o[f][0] *= c0; o[f][1] *= c0;
            o[f][2] *= c1; o[f][3] *= c1;
        }

        #pragma unroll
        for (int j = 0; j < 4; j++) {
            uint32_t a[4];
            __half2 t;
            t = __floats2half2_rn(sc[2 * j][0],     sc[2 * j][1]);     a[0] = *(uint32_t*)&t;
            t = __floats2half2_rn(sc[2 * j][2],     sc[2 * j][3]);     a[1] = *(uint32_t*)&t;
            t = __floats2half2_rn(sc[2 * j + 1][0], sc[2 * j + 1][1]); a[2] = *(uint32_t*)&t;
            t = __floats2half2_rn(sc[2 * j + 1][2], sc[2 * j + 1][3]); a[3] = *(uint32_t*)&t;
            #pragma unroll
            for (int fn2 = 0; fn2 < 4; fn2++) {
                uint32_t bfr[4];
                ldsm_x4(bfr, sV + (fn2 * 16 + b_row_in) * VROW + j * 32 + b_ksel);
                mma16816h(o[fn2 * 2 + 0], a, bfr[0], bfr[1]);
                mma16816h(o[fn2 * 2 + 1], a, bfr[2], bfr[3]);
            }
        }
    }

    // ---- epilogue: write ctxc bf16 hi/lo directly ----
    const float inv0 = 1.0f / l0r, inv1 = 1.0f / l1r;
    const int rowg = b * S_ + m0 + wid * 16 + (lane >> 2);
    const int colb = h * 64 + 2 * (lane & 3);
    #pragma unroll
    for (int f = 0; f < 8; f++) {
        int col = colb + 8 * f;
        float v0 = o[f][0] * inv0, v1 = o[f][1] * inv0;
        float v2 = o[f][2] * inv1, v3 = o[f][3] * inv1;
        float l0, l1;
        __nv_bfloat162 hi0 = bf16_pair_hi(v0, v1, l0, l1);
        *(__nv_bfloat162*)(g_ctxc + (size_t)rowg * 4096 + col) = hi0;
        *(__nv_bfloat162*)(g_ctxc + (size_t)rowg * 4096 + 2048 + col) =
            __nv_bfloat162(__float2bfloat16(l0), __float2bfloat16(l1));
        __nv_bfloat162 hi1 = bf16_pair_hi(v2, v3, l0, l1);
        *(__nv_bfloat162*)(g_ctxc + (size_t)(rowg + 8) * 4096 + col) = hi1;
        *(__nv_bfloat162*)(g_ctxc + (size_t)(rowg + 8) * 4096 + 2048 + col) =
            __nv_bfloat162(__float2bfloat16(l0), __float2bfloat16(l1));
    }
}

// ---------------------------------------------------------------------------
// Launch
// ---------------------------------------------------------------------------
extern "C" void kernel_launch(void* const* d_in, const int* in_sizes, int n_in,
                              void* d_out, int out_size)
{
    const float* x  = (const float*)d_in[0];
    const float* Wq = (const float*)d_in[1];
    const float* bq = (const float*)d_in[2];
    const float* Wk = (const float*)d_in[3];
    const float* bk = (const float*)d_in[4];
    const float* Wv = (const float*)d_in[5];
    const float* bv = (const float*)d_in[6];
    const float* Wo = (const float*)d_in[7];
    const float* bo = (const float*)d_in[8];
    float* out = (float*)d_out;

    __nv_bfloat16 *xc, *ctxc, *wqkvt, *wot;
    cudaGetSymbolAddress((void**)&xc,    g_xc);
    cudaGetSymbolAddress((void**)&ctxc,  g_ctxc);
    cudaGetSymbolAddress((void**)&wqkvt, g_wqkvt);
    cudaGetSymbolAddress((void**)&wot,   g_wot);

    cudaFuncSetAttribute(gemm_mma_kernel<256, 4>,
                         cudaFuncAttributeMaxDynamicSharedMemorySize, GEMM_SMEM_256);
    cudaFuncSetAttribute(gemm_mma_kernel<256, 0>,
                         cudaFuncAttributeMaxDynamicSharedMemorySize, GEMM_SMEM_256);
    cudaFuncSetAttribute(attn_mma_kernel,
                         cudaFuncAttributeMaxDynamicSharedMemorySize, ATT_SMEM);

    // input conversions (weights concatenated into one [3072, 4096] buffer)
    convert_rows_kernel<<<2048, 256>>>(x, xc, M_ * D_, D_);
    convert_transpose_kernel<<<dim3(D_ / 32,   D_ / 32), dim3(32, 8)>>>(
        Wq, wqkvt, D_, D_);
    convert_transpose_kernel<<<dim3(KVD_ / 32, D_ / 32), dim3(32, 8)>>>(
        Wk, wqkvt + (size_t)D_ * 2 * D_, D_, KVD_);
    convert_transpose_kernel<<<dim3(KVD_ / 32, D_ / 32), dim3(32, 8)>>>(
        Wv, wqkvt + (size_t)(D_ + KVD_) * 2 * D_, D_, KVD_);
    convert_transpose_kernel<<<dim3(D_ / 32,   D_ / 32), dim3(32, 8)>>>(
        Wo, wot, D_, D_);

    // fused QKV projection (one launch, 384 CTAs)
    gemm_mma_kernel<256, 4><<<dim3(NQKV / 256, M_ / 128), 256, GEMM_SMEM_256>>>(
        xc, wqkvt, bq, bk, bv, nullptr, NQKV);

    // attention (writes ctxc hi/lo directly)
    attn_mma_kernel<<<dim3(S_ / 128, B_ * H_), 256, ATT_SMEM>>>();

    // output projection
    gemm_mma_kernel<256, 0><<<dim3(D_ / 256, M_ / 128), 256, GEMM_SMEM_256>>>(
        ctxc, wot, bo, nullptr, nullptr, out, D_);
}

// round 11
// speedup vs baseline: 4.3192x; 1.2485x over previous
#include <cuda_runtime.h>
#include <cuda_bf16.h>
#include <cuda_fp16.h>
#include <cstdint>
#include <math.h>

// Problem constants
constexpr int B_   = 2;
constexpr int S_   = 2048;
constexpr int D_   = 2048;
constexpr int H_   = 32;
constexpr int HKV_ = 8;
constexpr int DH_  = 64;
constexpr int M_   = B_ * S_;       // 4096 rows
constexpr int KVD_ = HKV_ * DH_;    // 512
constexpr int NQKV = D_ + 2 * KVD_; // 3072

// GEMM operands (__device__ globals: allocation-free rule)
__device__ __nv_bfloat16 g_xc   [M_ * 2 * D_];     // x bf16 hi|lo
__device__ __half        g_ctxc [M_ * 2 * D_];     // ctx fp16 hi|lo (split-2, exact)
__device__ __nv_bfloat16 g_wqkvt[NQKV * 2 * D_];   // Wq|Wk|Wv bf16 hi|lo, N-major
__device__ __half        g_woth [D_ * D_];         // Wo fp16 single, N-major [2048][2048]

// attention operands (written directly by GEMM epilogues)
__device__ __half g_qb[B_ * H_   * S_ * 64];   // [b,h][m][d] fp16 (exact-proj, rounded)
__device__ __half g_kb[B_ * HKV_ * S_ * 64];   // [b,kvh][n][d] fp16
__device__ __half g_vt[B_ * HKV_ * 64 * S_];   // [b,kvh][d][n] fp16 (V^T)

__device__ __forceinline__ uint32_t smem_u32_of(const void* p) {
    uint32_t a;
    asm("{ .reg .u64 t; cvta.to.shared.u64 t, %1; cvt.u32.u64 %0, t; }" : "=r"(a) : "l"(p));
    return a;
}
__device__ __forceinline__ void ldsm_x4(uint32_t (&r)[4], uint32_t addr) {
    asm volatile("ldmatrix.sync.aligned.m8n8.x4.shared.b16 {%0,%1,%2,%3}, [%4];"
                 : "=r"(r[0]), "=r"(r[1]), "=r"(r[2]), "=r"(r[3]) : "r"(addr));
}
__device__ __forceinline__ void mma16816(float (&c)[4], const uint32_t (&a)[4],
                                         uint32_t b0, uint32_t b1) {
    asm volatile(
        "mma.sync.aligned.m16n8k16.row.col.f32.bf16.bf16.f32 "
        "{%0,%1,%2,%3}, {%4,%5,%6,%7}, {%8,%9}, {%0,%1,%2,%3};"
        : "+f"(c[0]), "+f"(c[1]), "+f"(c[2]), "+f"(c[3])
        : "r"(a[0]), "r"(a[1]), "r"(a[2]), "r"(a[3]), "r"(b0), "r"(b1));
}
__device__ __forceinline__ void mma16816h(float (&c)[4], const uint32_t (&a)[4],
                                          uint32_t b0, uint32_t b1) {
    asm volatile(
        "mma.sync.aligned.m16n8k16.row.col.f32.f16.f16.f32 "
        "{%0,%1,%2,%3}, {%4,%5,%6,%7}, {%8,%9}, {%0,%1,%2,%3};"
        : "+f"(c[0]), "+f"(c[1]), "+f"(c[2]), "+f"(c[3])
        : "r"(a[0]), "r"(a[1]), "r"(a[2]), "r"(a[3]), "r"(b0), "r"(b1));
}
__device__ __forceinline__ void cp16(uint32_t dst, const void* src) {
    asm volatile("cp.async.cg.shared.global [%0], [%1], 16;" :: "r"(dst), "l"(src));
}

// ---------------------------------------------------------------------------
// Conversion kernels (inputs only)
// ---------------------------------------------------------------------------
__global__ void convert_rows_kernel(const float* __restrict__ src,
                                    __nv_bfloat16* __restrict__ dst, int total, int K)
{
    for (int i = blockIdx.x * blockDim.x + threadIdx.x; i < total;
         i += gridDim.x * blockDim.x) {
        int m = i / K, k = i - m * K;
        float x = src[i];
        __nv_bfloat16 h = __float2bfloat16(x);
        float lo = x - __bfloat162float(h);
        dst[(size_t)m * 2 * K + k]     = h;
        dst[(size_t)m * 2 * K + K + k] = __float2bfloat16(lo);
    }
}

__global__ void convert_transpose_kernel(const float* __restrict__ W,
                                         __nv_bfloat16* __restrict__ Wt, int K, int N)
{
    __shared__ float tile[32][33];
    int k0 = blockIdx.y * 32, n0 = blockIdx.x * 32;
    int tx = threadIdx.x, ty = threadIdx.y;
    #pragma unroll
    for (int dy = 0; dy < 32; dy += 8)
        tile[ty + dy][tx] = W[(size_t)(k0 + ty + dy) * N + n0 + tx];
    __syncthreads();
    #pragma unroll
    for (int dy = 0; dy < 32; dy += 8) {
        int n = n0 + ty + dy;
        float x = tile[tx][ty + dy];
        __nv_bfloat16 h = __float2bfloat16(x);
        Wt[(size_t)n * 2 * K + k0 + tx]     = h;
        Wt[(size_t)n * 2 * K + K + k0 + tx] = __float2bfloat16(x - __bfloat162float(h));
    }
}

// Wo [K=2048][N=2048] f32 -> g_woth fp16 [N][K]
__global__ void convert_transpose_h_kernel(const float* __restrict__ W,
                                           __half* __restrict__ Wt)
{
    __shared__ float tile[32][33];
    int k0 = blockIdx.y * 32, n0 = blockIdx.x * 32;
    int tx = threadIdx.x, ty = threadIdx.y;
    #pragma unroll
    for (int dy = 0; dy < 32; dy += 8)
        tile[ty + dy][tx] = W[(size_t)(k0 + ty + dy) * D_ + n0 + tx];
    __syncthreads();
    #pragma unroll
    for (int dy = 0; dy < 32; dy += 8) {
        int n = n0 + ty + dy;
        Wt[(size_t)n * D_ + k0 + tx] = __float2half_rn(tile[tx][ty + dy]);
    }
}

// ---------------------------------------------------------------------------
// HMMA GEMM, BK=64 per stage, 3-stage cp.async, fused epilogues.
// MODE 4 = QKV (bf16 split-3 in; routes Q/K fp16, V fp16^T)
// MODE 5 = O   (fp16 split-2 A x fp16-single B; f32+bias out)
// ---------------------------------------------------------------------------
constexpr int A_ROW_B  = 144;                 // 128B data + 16B pad
constexpr int A_TILE_B = 128 * A_ROW_B;       // 18432

template<int BN, int MODE>
__global__ __launch_bounds__(256, 1)
void gemm_mma_kernel(const void* __restrict__ Ap,
                     const void* __restrict__ Btp,
                     const float* __restrict__ bias,
                     const float* __restrict__ bias2,
                     const float* __restrict__ bias3,
                     float* __restrict__ C, int Ndim)
{
    constexpr int NKC    = (MODE == 4) ? 96 : 64;
    constexpr int B_RS   = (MODE == 4) ? 4096 : 2048;   // B row stride (elements)
    constexpr int COLS_W = BN / 4;
    constexpr int NF2    = COLS_W / 16;
    constexpr int B_TILE = BN * A_ROW_B;
    constexpr int STAGE  = A_TILE_B + B_TILE;

    const uint16_t* A  = (const uint16_t*)Ap;
    const uint16_t* Bt = (const uint16_t*)Btp;

    extern __shared__ __align__(128) char smem[];
    const uint32_t smem_b = smem_u32_of(smem);
    const int tid  = threadIdx.x;
    const int lane = tid & 31, wid = tid >> 5;
    const int warp_m = wid & 1;
    const int warp_n = wid >> 1;
    const int bm = blockIdx.y * 128;
    const int bn = blockIdx.x * BN;

    float acc[4][2 * NF2][4];
    #pragma unroll
    for (int i = 0; i < 4; i++)
        #pragma unroll
        for (int j = 0; j < 2 * NF2; j++)
            #pragma unroll
            for (int e = 0; e < 4; e++) acc[i][j][e] = 0.0f;

    auto load_stage = [&](int kc) {
        int slot = kc % 3;
        int seg = kc >> 5, within = (kc & 31) * 64;
        int a_col, w_col;
        if (MODE == 4) {
            a_col = within + ((seg == 1) ? 2048 : 0);
            w_col = within + ((seg == 2) ? 2048 : 0);
        } else {
            a_col = within + seg * 2048;
            w_col = within;
        }
        uint32_t sA = smem_b + slot * STAGE;
        uint32_t sB = sA + A_TILE_B;
        #pragma unroll
        for (int it = 0; it < 4; it++) {
            int idx = tid + it * 256;
            int r = idx >> 3, c = idx & 7;
            cp16(sA + r * A_ROW_B + c * 16, A + (size_t)(bm + r) * 4096 + a_col + c * 8);
        }
        #pragma unroll
        for (int it = 0; it < BN / 32; it++) {
            int idx = tid + it * 256;
            int r = idx >> 3, c = idx & 7;
            cp16(sB + r * A_ROW_B + c * 16, Bt + (size_t)(bn + r) * B_RS + w_col + c * 8);
        }
    };

    load_stage(0); asm volatile("cp.async.commit_group;");
    load_stage(1); asm volatile("cp.async.commit_group;");

    const int a_row_in = lane & 15;
    const int a_ksel   = (lane >> 4) * 16;
    const int b_sel    = (lane >> 3) & 3;
    const int b_row_in = ((b_sel >> 1) << 3) + (lane & 7);
    const int b_ksel   = (b_sel & 1) * 16;

    for (int kc = 0; kc < NKC; kc++) {
        asm volatile("cp.async.wait_group 1;");
        __syncthreads();
        if (kc + 2 < NKC) {
            load_stage(kc + 2);
            asm volatile("cp.async.commit_group;");
        }

        int slot = kc % 3;
        uint32_t sA = smem_b + slot * STAGE + (warp_m * 64) * A_ROW_B;
        uint32_t sB = smem_b + slot * STAGE + A_TILE_B + (warp_n * COLS_W) * A_ROW_B;

        #pragma unroll
        for (int kk = 0; kk < 4; kk++) {
            uint32_t kbyte = kk * 32;
            uint32_t afr[4][4];
            #pragma unroll
            for (int fm = 0; fm < 4; fm++)
                ldsm_x4(afr[fm], sA + (fm * 16 + a_row_in) * A_ROW_B + kbyte + a_ksel);
            #pragma unroll
            for (int fn2 = 0; fn2 < NF2; fn2++) {
                uint32_t bfr[4];
                ldsm_x4(bfr, sB + (fn2 * 16 + b_row_in) * A_ROW_B + kbyte + b_ksel);
                #pragma unroll
                for (int fm = 0; fm < 4; fm++) {
                    if (MODE == 4) {
                        mma16816(acc[fm][fn2 * 2 + 0], afr[fm], bfr[0], bfr[1]);
                        mma16816(acc[fm][fn2 * 2 + 1], afr[fm], bfr[2], bfr[3]);
                    } else {
                        mma16816h(acc[fm][fn2 * 2 + 0], afr[fm], bfr[0], bfr[1]);
                        mma16816h(acc[fm][fn2 * 2 + 1], afr[fm], bfr[2], bfr[3]);
                    }
                }
            }
        }
    }

    // ---- fused epilogue ----
    const int row0 = bm + warp_m * 64 + (lane >> 2);
    const int col0 = bn + warp_n * COLS_W + (lane & 3) * 2;
    #pragma unroll
    for (int fm = 0; fm < 4; fm++) {
        #pragma unroll
        for (int fn = 0; fn < 2 * NF2; fn++) {
            const int c = col0 + fn * 8;
            const int r0 = row0 + fm * 16;
            if (MODE == 5) {
                const float b0 = bias[c], b1 = bias[c + 1];
                *(float2*)(C + (size_t)r0 * Ndim + c) =
                    make_float2(acc[fm][fn][0] + b0, acc[fm][fn][1] + b1);
                *(float2*)(C + (size_t)(r0 + 8) * Ndim + c) =
                    make_float2(acc[fm][fn][2] + b0, acc[fm][fn][3] + b1);
            } else {  // MODE 4: route by section
                float b0, b1;
                if (c < 2048)      { b0 = bias [c];        b1 = bias [c + 1]; }
                else if (c < 2560) { b0 = bias2[c - 2048]; b1 = bias2[c - 2047]; }
                else               { b0 = bias3[c - 2560]; b1 = bias3[c - 2559]; }
                float w[2][2] = {{acc[fm][fn][0] + b0, acc[fm][fn][1] + b1},
                                 {acc[fm][fn][2] + b0, acc[fm][fn][3] + b1}};
                if (c < 2560) {
                    // Q / K -> fp16 single, [.,64] layouts
                    const bool isQ = (c < 2048);
                    const int cc   = isQ ? c : (c - 2048);
                    const int NH   = isQ ? 32 : 8;
                    __half* dst = isQ ? g_qb : g_kb;
                    const int hh = cc >> 6, d = cc & 63;
                    #pragma unroll
                    for (int rr = 0; rr < 2; rr++) {
                        int r = r0 + rr * 8;
                        int b = r >> 11, mm = r & 2047;
                        size_t base = ((size_t)(b * NH + hh) * 2048 + mm) * 64 + d;
                        *(__half2*)(dst + base) = __floats2half2_rn(w[rr][0], w[rr][1]);
                    }
                } else {
                    // V -> g_vt fp16 transposed
                    const int cc = c - 2560;
                    const int kvh = cc >> 6, d = cc & 63;
                    #pragma unroll
                    for (int rr = 0; rr < 2; rr++) {
                        int r = r0 + rr * 8;
                        int b = r >> 11, mm = r & 2047;
                        size_t base = ((size_t)(b * 8 + kvh) * 64 + d) * 2048 + mm;
                        g_vt[base]        = __float2half_rn(w[rr][0]);
                        g_vt[base + 2048] = __float2half_rn(w[rr][1]);
                    }
                }
            }
        }
    }
}

constexpr int GEMM_SMEM_256 = 3 * (A_TILE_B + 256 * A_ROW_B);  // 165888

// ---------------------------------------------------------------------------
// Flash attention: Q,K fp16 single (scores = Qh.Kh), P fp16, V fp16.
// CTA = 128 q-rows x (b,h); 8 warps x 16 rows; 3-stage K/V cp.async.
// ---------------------------------------------------------------------------
constexpr int ANB     = S_ / 64;
constexpr int QROW    = 144;            // 128B data + 16 pad
constexpr int KROW    = 144;
constexpr int VROW    = 144;
constexpr int QBYTES  = 128 * QROW;     // 18432
constexpr int KTILE   = 64 * KROW;      // 9216
constexpr int VTILE   = 64 * VROW;      // 9216
constexpr int ASTG    = KTILE + VTILE;  // 18432
constexpr int ATT_SMEM = QBYTES + 3 * ASTG;  // 73728

__global__ __launch_bounds__(256)
void attn_mma_kernel()
{
    extern __shared__ __align__(128) char smem[];
    const uint32_t sb = smem_u32_of(smem);
    const int tid  = threadIdx.x;
    const int lane = tid & 31, wid = tid >> 5;

    const int bh  = blockIdx.y;
    const int b   = bh >> 5;
    const int h   = bh & 31;
    const int kvh = h >> 2;
    const int bk  = b * HKV_ + kvh;
    const int m0  = blockIdx.x * 128;

    const __half* qbase = g_qb + ((size_t)bh * S_ + m0) * 64;
    const __half* kbase = g_kb + ((size_t)bk * S_) * 64;
    const __half* vbase = g_vt + ((size_t)bk * 64) * (size_t)S_;

    #pragma unroll
    for (int it = 0; it < 4; it++) {
        int idx = tid + it * 256;
        int r = idx >> 3, c = idx & 7;
        cp16(sb + r * QROW + c * 16, qbase + (size_t)r * 64 + c * 8);
    }
    asm volatile("cp.async.commit_group;");

    auto load_stage = [&](int kbi) {
        int slot = kbi % 3;
        int n0 = kbi * 64;
        uint32_t sK = sb + QBYTES + slot * ASTG;
        uint32_t sV = sK + KTILE;
        #pragma unroll
        for (int it = 0; it < 2; it++) {
            int idx = tid + it * 256;
            int r = idx >> 3, c = idx & 7;
            cp16(sK + r * KROW + c * 16, kbase + (size_t)(n0 + r) * 64 + c * 8);
        }
        #pragma unroll
        for (int it = 0; it < 2; it++) {
            int idx = tid + it * 256;
            int r = idx >> 3, c = idx & 7;
            cp16(sV + r * VROW + c * 16, vbase + (size_t)r * S_ + n0 + c * 8);
        }
    };
    load_stage(0); asm volatile("cp.async.commit_group;");
    load_stage(1); asm volatile("cp.async.commit_group;");

    asm volatile("cp.async.wait_group 2;");
    __syncthreads();

    const int a_row_in = lane & 15;
    const int a_ksel   = (lane >> 4) * 16;
    const int b_sel    = (lane >> 3) & 3;
    const int b_row_in = ((b_sel >> 1) << 3) + (lane & 7);
    const int b_ksel   = (b_sel & 1) * 16;

    uint32_t qh[4][4];
    {
        uint32_t qa = sb + (wid * 16 + a_row_in) * QROW + a_ksel;
        #pragma unroll
        for (int kf = 0; kf < 4; kf++)
            ldsm_x4(qh[kf], qa + kf * 32);
    }

    float o[8][4];
    #pragma unroll
    for (int f = 0; f < 8; f++)
        #pragma unroll
        for (int e = 0; e < 4; e++) o[f][e] = 0.0f;
    float m0r = -INFINITY, m1r = -INFINITY, l0r = 0.0f, l1r = 0.0f;

    const float sscale = 0.125f * 1.44269504088896f;

    for (int kbi = 0; kbi < ANB; kbi++) {
        if (kbi == ANB - 1) { asm volatile("cp.async.wait_group 0;"); }
        else                { asm volatile("cp.async.wait_group 1;"); }
        __syncthreads();
        if (kbi + 2 < ANB) {
            load_stage(kbi + 2);
            asm volatile("cp.async.commit_group;");
        }

        const uint32_t sK = sb + QBYTES + (kbi % 3) * ASTG;
        const uint32_t sV = sK + KTILE;

        // ---- scores: S = Qh . Kh (fp16, fp32 accum) ----
        float sc[8][4];
        #pragma unroll
        for (int f = 0; f < 8; f++)
            #pragma unroll
            for (int e = 0; e < 4; e++) sc[f][e] = 0.0f;

        #pragma unroll
        for (int kf = 0; kf < 4; kf++) {
            #pragma unroll
            for (int fn2 = 0; fn2 < 4; fn2++) {
                uint32_t bfr[4];
                ldsm_x4(bfr, sK + (fn2 * 16 + b_row_in) * KROW + kf * 32 + b_ksel);
                mma16816h(sc[fn2 * 2 + 0], qh[kf], bfr[0], bfr[1]);
                mma16816h(sc[fn2 * 2 + 1], qh[kf], bfr[2], bfr[3]);
            }
        }

        // ---- online softmax ----
        #pragma unroll
        for (int f = 0; f < 8; f++)
            #pragma unroll
            for (int e = 0; e < 4; e++) sc[f][e] *= sscale;

        float mx0 = -INFINITY, mx1 = -INFINITY;
        #pragma unroll
        for (int f = 0; f < 8; f++) {
            mx0 = fmaxf(mx0, fmaxf(sc[f][0], sc[f][1]));
            mx1 = fmaxf(mx1, fmaxf(sc[f][2], sc[f][3]));
        }
        mx0 = fmaxf(mx0, __shfl_xor_sync(0xffffffffu, mx0, 1));
        mx0 = fmaxf(mx0, __shfl_xor_sync(0xffffffffu, mx0, 2));
        mx1 = fmaxf(mx1, __shfl_xor_sync(0xffffffffu, mx1, 1));
        mx1 = fmaxf(mx1, __shfl_xor_sync(0xffffffffu, mx1, 2));

        float mn0 = fmaxf(m0r, mx0), mn1 = fmaxf(m1r, mx1);
        float c0 = exp2f(m0r - mn0), c1 = exp2f(m1r - mn1);

        float rs0 = 0.0f, rs1 = 0.0f;
        #pragma unroll
        for (int f = 0; f < 8; f++) {
            sc[f][0] = exp2f(sc[f][0] - mn0); rs0 += sc[f][0];
            sc[f][1] = exp2f(sc[f][1] - mn0); rs0 += sc[f][1];
            sc[f][2] = exp2f(sc[f][2] - mn1); rs1 += sc[f][2];
            sc[f][3] = exp2f(sc[f][3] - mn1); rs1 += sc[f][3];
        }
        rs0 += __shfl_xor_sync(0xffffffffu, rs0, 1);
        rs0 += __shfl_xor_sync(0xffffffffu, rs0, 2);
        rs1 += __shfl_xor_sync(0xffffffffu, rs1, 1);
        rs1 += __shfl_xor_sync(0xffffffffu, rs1, 2);

        l0r = l0r * c0 + rs0;
        l1r = l1r * c1 + rs1;
        m0r = mn0; m1r = mn1;
        #pragma unroll
        for (int f = 0; f < 8; f++) {
            o[f][0] *= c0; o[f][1] *= c0;
            o[f][2] *= c1; o[f][3] *= c1;
        }

        // ---- PV: P fp16, V fp16 ----
        #pragma unroll
        for (int j = 0; j < 4; j++) {
            uint32_t a[4];
            __half2 t;
            t = __floats2half2_rn(sc[2 * j][0],     sc[2 * j][1]);     a[0] = *(uint32_t*)&t;
            t = __floats2half2_rn(sc[2 * j][2],     sc[2 * j][3]);     a[1] = *(uint32_t*)&t;
            t = __floats2half2_rn(sc[2 * j + 1][0], sc[2 * j + 1][1]); a[2] = *(uint32_t*)&t;
            t = __floats2half2_rn(sc[2 * j + 1][2], sc[2 * j + 1][3]); a[3] = *(uint32_t*)&t;
            #pragma unroll
            for (int fn2 = 0; fn2 < 4; fn2++) {
                uint32_t bfr[4];
                ldsm_x4(bfr, sV + (fn2 * 16 + b_row_in) * VROW + j * 32 + b_ksel);
                mma16816h(o[fn2 * 2 + 0], a, bfr[0], bfr[1]);
                mma16816h(o[fn2 * 2 + 1], a, bfr[2], bfr[3]);
            }
        }
    }

    // ---- epilogue: write ctxc fp16 hi/lo (split-2, exact to 2^-22) ----
    const float inv0 = 1.0f / l0r, inv1 = 1.0f / l1r;
    const int rowg = b * S_ + m0 + wid * 16 + (lane >> 2);
    const int colb = h * 64 + 2 * (lane & 3);
    #pragma unroll
    for (int f = 0; f < 8; f++) {
        int col = colb + 8 * f;
        float v[2][2] = {{o[f][0] * inv0, o[f][1] * inv0},
                         {o[f][2] * inv1, o[f][3] * inv1}};
        #pragma unroll
        for (int rr = 0; rr < 2; rr++) {
            __half h0 = __float2half_rn(v[rr][0]);
            __half h1 = __float2half_rn(v[rr][1]);
            float l0 = v[rr][0] - __half2float(h0);
            float l1 = v[rr][1] - __half2float(h1);
            size_t base = (size_t)(rowg + rr * 8) * 4096 + col;
            *(__half2*)(g_ctxc + base)        = __half2(h0, h1);
            *(__half2*)(g_ctxc + base + 2048) = __floats2half2_rn(l0, l1);
        }
    }
}

// ---------------------------------------------------------------------------
// Launch
// ---------------------------------------------------------------------------
extern "C" void kernel_launch(void* const* d_in, const int* in_sizes, int n_in,
                              void* d_out, int out_size)
{
    const float* x  = (const float*)d_in[0];
    const float* Wq = (const float*)d_in[1];
    const float* bq = (const float*)d_in[2];
    const float* Wk = (const float*)d_in[3];
    const float* bk = (const float*)d_in[4];
    const float* Wv = (const float*)d_in[5];
    const float* bv = (const float*)d_in[6];
    const float* Wo = (const float*)d_in[7];
    const float* bo = (const float*)d_in[8];
    float* out = (float*)d_out;

    __nv_bfloat16 *xc, *wqkvt;
    __half *ctxc, *woth;
    cudaGetSymbolAddress((void**)&xc,    g_xc);
    cudaGetSymbolAddress((void**)&ctxc,  g_ctxc);
    cudaGetSymbolAddress((void**)&wqkvt, g_wqkvt);
    cudaGetSymbolAddress((void**)&woth,  g_woth);

    cudaFuncSetAttribute(gemm_mma_kernel<256, 4>,
                         cudaFuncAttributeMaxDynamicSharedMemorySize, GEMM_SMEM_256);
    cudaFuncSetAttribute(gemm_mma_kernel<256, 5>,
                         cudaFuncAttributeMaxDynamicSharedMemorySize, GEMM_SMEM_256);
    cudaFuncSetAttribute(attn_mma_kernel,
                         cudaFuncAttributeMaxDynamicSharedMemorySize, ATT_SMEM);

    // input conversions
    convert_rows_kernel<<<2048, 256>>>(x, xc, M_ * D_, D_);
    convert_transpose_kernel<<<dim3(D_ / 32,   D_ / 32), dim3(32, 8)>>>(
        Wq, wqkvt, D_, D_);
    convert_transpose_kernel<<<dim3(KVD_ / 32, D_ / 32), dim3(32, 8)>>>(
        Wk, wqkvt + (size_t)D_ * 2 * D_, D_, KVD_);
    convert_transpose_kernel<<<dim3(KVD_ / 32, D_ / 32), dim3(32, 8)>>>(
        Wv, wqkvt + (size_t)(D_ + KVD_) * 2 * D_, D_, KVD_);
    convert_transpose_h_kernel<<<dim3(D_ / 32, D_ / 32), dim3(32, 8)>>>(Wo, woth);

    // fused QKV projection (bf16 split-3 exact; epilogue rounds to fp16 layouts)
    gemm_mma_kernel<256, 4><<<dim3(NQKV / 256, M_ / 128), 256, GEMM_SMEM_256>>>(
        xc, wqkvt, bq, bk, bv, nullptr, NQKV);

    // attention (fp16 QK single-term, fp16 PV; writes ctxc fp16 hi/lo)
    attn_mma_kernel<<<dim3(S_ / 128, B_ * H_), 256, ATT_SMEM>>>();

    // output projection (fp16 split-2 ctx x fp16 Wo)
    gemm_mma_kernel<256, 5><<<dim3(D_ / 256, M_ / 128), 256, GEMM_SMEM_256>>>(
        ctxc, woth, bo, nullptr, nullptr, out, D_);
}

// round 13
// speedup vs baseline: 5.2097x; 1.2062x over previous
#include <cuda_runtime.h>
#include <cuda_bf16.h>
#include <cuda_fp16.h>
#include <cstdint>
#include <math.h>

// Problem constants
constexpr int B_   = 2;
constexpr int S_   = 2048;
constexpr int D_   = 2048;
constexpr int H_   = 32;
constexpr int HKV_ = 8;
constexpr int DH_  = 64;
constexpr int M_   = B_ * S_;       // 4096 rows
constexpr int KVD_ = HKV_ * DH_;    // 512
constexpr int NQKV = D_ + 2 * KVD_; // 3072

// GEMM operands (__device__ globals: allocation-free rule)
__device__ __half g_xch  [M_ * 2 * D_];    // x fp16 hi|lo (split-2, exact)
__device__ __half g_ctxc [M_ * 2 * D_];    // ctx fp16 hi|lo (split-2, exact)
__device__ __half g_wqkvh[NQKV * D_];      // Wq|Wk|Wv fp16 single, N-major [3072][2048]
__device__ __half g_woth [D_ * D_];        // Wo fp16 single, N-major [2048][2048]

// attention operands (written directly by GEMM epilogues)
__device__ __half g_qb[B_ * H_   * S_ * 64];   // [b,h][m][d] fp16
__device__ __half g_kb[B_ * HKV_ * S_ * 64];   // [b,kvh][n][d] fp16
__device__ __half g_vt[B_ * HKV_ * 64 * S_];   // [b,kvh][d][n] fp16 (V^T)

__device__ __forceinline__ uint32_t smem_u32_of(const void* p) {
    uint32_t a;
    asm("{ .reg .u64 t; cvta.to.shared.u64 t, %1; cvt.u32.u64 %0, t; }" : "=r"(a) : "l"(p));
    return a;
}
__device__ __forceinline__ void ldsm_x4(uint32_t (&r)[4], uint32_t addr) {
    asm volatile("ldmatrix.sync.aligned.m8n8.x4.shared.b16 {%0,%1,%2,%3}, [%4];"
                 : "=r"(r[0]), "=r"(r[1]), "=r"(r[2]), "=r"(r[3]) : "r"(addr));
}
__device__ __forceinline__ void mma16816h(float (&c)[4], const uint32_t (&a)[4],
                                          uint32_t b0, uint32_t b1) {
    asm volatile(
        "mma.sync.aligned.m16n8k16.row.col.f32.f16.f16.f32 "
        "{%0,%1,%2,%3}, {%4,%5,%6,%7}, {%8,%9}, {%0,%1,%2,%3};"
        : "+f"(c[0]), "+f"(c[1]), "+f"(c[2]), "+f"(c[3])
        : "r"(a[0]), "r"(a[1]), "r"(a[2]), "r"(a[3]), "r"(b0), "r"(b1));
}
__device__ __forceinline__ void cp16(uint32_t dst, const void* src) {
    asm volatile("cp.async.cg.shared.global [%0], [%1], 16;" :: "r"(dst), "l"(src));
}

// ---------------------------------------------------------------------------
// Conversion kernels (inputs only)
// ---------------------------------------------------------------------------
// x f32 [m][k] -> fp16 hi|lo [m][K | K+k]  (split-2, exact to ~2^-22)
__global__ void convert_rows_h_kernel(const float* __restrict__ src,
                                      __half* __restrict__ dst, int total, int K)
{
    for (int i = blockIdx.x * blockDim.x + threadIdx.x; i < total;
         i += gridDim.x * blockDim.x) {
        int m = i / K, k = i - m * K;
        float x = src[i];
        __half h = __float2half_rn(x);
        float lo = x - __half2float(h);
        dst[(size_t)m * 2 * K + k]     = h;
        dst[(size_t)m * 2 * K + K + k] = __float2half_rn(lo);
    }
}

// W [K=2048][N] f32 -> Wt fp16 [N][2048]
__global__ void convert_transpose_h_kernel(const float* __restrict__ W,
                                           __half* __restrict__ Wt, int N)
{
    __shared__ float tile[32][33];
    int k0 = blockIdx.y * 32, n0 = blockIdx.x * 32;
    int tx = threadIdx.x, ty = threadIdx.y;
    #pragma unroll
    for (int dy = 0; dy < 32; dy += 8)
        tile[ty + dy][tx] = W[(size_t)(k0 + ty + dy) * N + n0 + tx];
    __syncthreads();
    #pragma unroll
    for (int dy = 0; dy < 32; dy += 8) {
        int n = n0 + ty + dy;
        Wt[(size_t)n * D_ + k0 + tx] = __float2half_rn(tile[tx][ty + dy]);
    }
}

// ---------------------------------------------------------------------------
// HMMA GEMM (all fp16): C = (Ah + Al) @ B^T, A fp16 [M][2*2048] hi|lo,
// B fp16 [N][2048]. K'=4096, BK=64/stage, 64 iters, 3-stage cp.async.
// MODE 4 = fused QKV routing -> g_qb/g_kb/g_vt ; MODE 5 = f32+bias -> C
// ---------------------------------------------------------------------------
constexpr int A_ROW_B  = 144;                 // 128B data + 16B pad
constexpr int A_TILE_B = 128 * A_ROW_B;       // 18432
constexpr int GEMM_NKC = 64;                  // 4096 / 64

template<int BN, int MODE>
__global__ __launch_bounds__(256, 1)
void gemm_mma_kernel(const __half* __restrict__ A,
                     const __half* __restrict__ Bt,
                     const float* __restrict__ bias,
                     const float* __restrict__ bias2,
                     const float* __restrict__ bias3,
                     float* __restrict__ C, int Ndim)
{
    constexpr int COLS_W = BN / 4;
    constexpr int NF2    = COLS_W / 16;
    constexpr int B_TILE = BN * A_ROW_B;
    constexpr int STAGE  = A_TILE_B + B_TILE;

    extern __shared__ __align__(128) char smem[];
    const uint32_t smem_b = smem_u32_of(smem);
    const int tid  = threadIdx.x;
    const int lane = tid & 31, wid = tid >> 5;
    const int warp_m = wid & 1;
    const int warp_n = wid >> 1;
    const int bm = blockIdx.y * 128;
    const int bn = blockIdx.x * BN;

    float acc[4][2 * NF2][4];
    #pragma unroll
    for (int i = 0; i < 4; i++)
        #pragma unroll
        for (int j = 0; j < 2 * NF2; j++)
            #pragma unroll
            for (int e = 0; e < 4; e++) acc[i][j][e] = 0.0f;

    auto load_stage = [&](int kc) {
        int slot = kc % 3;
        int seg = kc >> 5, within = (kc & 31) * 64;
        int a_col = within + seg * 2048;      // seg0: hi, seg1: lo
        int w_col = within;                   // B reused across segments
        uint32_t sA = smem_b + slot * STAGE;
        uint32_t sB = sA + A_TILE_B;
        #pragma unroll
        for (int it = 0; it < 4; it++) {
            int idx = tid + it * 256;
            int r = idx >> 3, c = idx & 7;
            cp16(sA + r * A_ROW_B + c * 16, A + (size_t)(bm + r) * 4096 + a_col + c * 8);
        }
        #pragma unroll
        for (int it = 0; it < BN / 32; it++) {
            int idx = tid + it * 256;
            int r = idx >> 3, c = idx & 7;
            cp16(sB + r * A_ROW_B + c * 16, Bt + (size_t)(bn + r) * 2048 + w_col + c * 8);
        }
    };

    load_stage(0); asm volatile("cp.async.commit_group;");
    load_stage(1); asm volatile("cp.async.commit_group;");

    const int a_row_in = lane & 15;
    const int a_ksel   = (lane >> 4) * 16;
    const int b_sel    = (lane >> 3) & 3;
    const int b_row_in = ((b_sel >> 1) << 3) + (lane & 7);
    const int b_ksel   = (b_sel & 1) * 16;

    for (int kc = 0; kc < GEMM_NKC; kc++) {
        asm volatile("cp.async.wait_group 1;");
        __syncthreads();
        if (kc + 2 < GEMM_NKC) {
            load_stage(kc + 2);
            asm volatile("cp.async.commit_group;");
        }

        int slot = kc % 3;
        uint32_t sA = smem_b + slot * STAGE + (warp_m * 64) * A_ROW_B;
        uint32_t sB = smem_b + slot * STAGE + A_TILE_B + (warp_n * COLS_W) * A_ROW_B;

        #pragma unroll
        for (int kk = 0; kk < 4; kk++) {
            uint32_t kbyte = kk * 32;
            uint32_t afr[4][4];
            #pragma unroll
            for (int fm = 0; fm < 4; fm++)
                ldsm_x4(afr[fm], sA + (fm * 16 + a_row_in) * A_ROW_B + kbyte + a_ksel);
            #pragma unroll
            for (int fn2 = 0; fn2 < NF2; fn2++) {
                uint32_t bfr[4];
                ldsm_x4(bfr, sB + (fn2 * 16 + b_row_in) * A_ROW_B + kbyte + b_ksel);
                #pragma unroll
                for (int fm = 0; fm < 4; fm++) {
                    mma16816h(acc[fm][fn2 * 2 + 0], afr[fm], bfr[0], bfr[1]);
                    mma16816h(acc[fm][fn2 * 2 + 1], afr[fm], bfr[2], bfr[3]);
                }
            }
        }
    }

    // ---- fused epilogue ----
    const int row0 = bm + warp_m * 64 + (lane >> 2);
    const int col0 = bn + warp_n * COLS_W + (lane & 3) * 2;
    #pragma unroll
    for (int fm = 0; fm < 4; fm++) {
        #pragma unroll
        for (int fn = 0; fn < 2 * NF2; fn++) {
            const int c = col0 + fn * 8;
            const int r0 = row0 + fm * 16;
            if (MODE == 5) {
                const float b0 = bias[c], b1 = bias[c + 1];
                *(float2*)(C + (size_t)r0 * Ndim + c) =
                    make_float2(acc[fm][fn][0] + b0, acc[fm][fn][1] + b1);
                *(float2*)(C + (size_t)(r0 + 8) * Ndim + c) =
                    make_float2(acc[fm][fn][2] + b0, acc[fm][fn][3] + b1);
            } else {  // MODE 4: route by section
                float b0, b1;
                if (c < 2048)      { b0 = bias [c];        b1 = bias [c + 1]; }
                else if (c < 2560) { b0 = bias2[c - 2048]; b1 = bias2[c - 2047]; }
                else               { b0 = bias3[c - 2560]; b1 = bias3[c - 2559]; }
                float w[2][2] = {{acc[fm][fn][0] + b0, acc[fm][fn][1] + b1},
                                 {acc[fm][fn][2] + b0, acc[fm][fn][3] + b1}};
                if (c < 2560) {
                    // Q / K -> fp16 single, [.,64] layouts
                    const bool isQ = (c < 2048);
                    const int cc   = isQ ? c : (c - 2048);
                    const int NH   = isQ ? 32 : 8;
                    __half* dst = isQ ? g_qb : g_kb;
                    const int hh = cc >> 6, d = cc & 63;
                    #pragma unroll
                    for (int rr = 0; rr < 2; rr++) {
                        int r = r0 + rr * 8;
                        int b = r >> 11, mm = r & 2047;
                        size_t base = ((size_t)(b * NH + hh) * 2048 + mm) * 64 + d;
                        *(__half2*)(dst + base) = __floats2half2_rn(w[rr][0], w[rr][1]);
                    }
                } else {
                    // V -> g_vt fp16 transposed
                    const int cc = c - 2560;
                    const int kvh = cc >> 6, d = cc & 63;
                    #pragma unroll
                    for (int rr = 0; rr < 2; rr++) {
                        int r = r0 + rr * 8;
                        int b = r >> 11, mm = r & 2047;
                        size_t base = ((size_t)(b * 8 + kvh) * 64 + d) * 2048 + mm;
                        g_vt[base]        = __float2half_rn(w[rr][0]);
                        g_vt[base + 2048] = __float2half_rn(w[rr][1]);
                    }
                }
            }
        }
    }
}

constexpr int GEMM_SMEM_256 = 3 * (A_TILE_B + 256 * A_ROW_B);  // 165888

// ---------------------------------------------------------------------------
// Flash attention (validated R11): Q,K fp16 single, P fp16, V fp16.
// CTA = 128 q-rows x (b,h); 8 warps x 16 rows; 3-stage K/V cp.async.
// ---------------------------------------------------------------------------
constexpr int ANB     = S_ / 64;
constexpr int QROW    = 144;
constexpr int KROW    = 144;
constexpr int VROW    = 144;
constexpr int QBYTES  = 128 * QROW;     // 18432
constexpr int KTILE   = 64 * KROW;
constexpr int VTILE   = 64 * VROW;
constexpr int ASTG    = KTILE + VTILE;  // 18432
constexpr int ATT_SMEM = QBYTES + 3 * ASTG;  // 73728

__global__ __launch_bounds__(256)
void attn_mma_kernel()
{
    extern __shared__ __align__(128) char smem[];
    const uint32_t sb = smem_u32_of(smem);
    const int tid  = threadIdx.x;
    const int lane = tid & 31, wid = tid >> 5;

    const int bh  = blockIdx.y;
    const int b   = bh >> 5;
    const int h   = bh & 31;
    const int kvh = h >> 2;
    const int bk  = b * HKV_ + kvh;
    const int m0  = blockIdx.x * 128;

    const __half* qbase = g_qb + ((size_t)bh * S_ + m0) * 64;
    const __half* kbase = g_kb + ((size_t)bk * S_) * 64;
    const __half* vbase = g_vt + ((size_t)bk * 64) * (size_t)S_;

    #pragma unroll
    for (int it = 0; it < 4; it++) {
        int idx = tid + it * 256;
        int r = idx >> 3, c = idx & 7;
        cp16(sb + r * QROW + c * 16, qbase + (size_t)r * 64 + c * 8);
    }
    asm volatile("cp.async.commit_group;");

    auto load_stage = [&](int kbi) {
        int slot = kbi % 3;
        int n0 = kbi * 64;
        uint32_t sK = sb + QBYTES + slot * ASTG;
        uint32_t sV = sK + KTILE;
        #pragma unroll
        for (int it = 0; it < 2; it++) {
            int idx = tid + it * 256;
            int r = idx >> 3, c = idx & 7;
            cp16(sK + r * KROW + c * 16, kbase + (size_t)(n0 + r) * 64 + c * 8);
        }
        #pragma unroll
        for (int it = 0; it < 2; it++) {
            int idx = tid + it * 256;
            int r = idx >> 3, c = idx & 7;
            cp16(sV + r * VROW + c * 16, vbase + (size_t)r * S_ + n0 + c * 8);
        }
    };
    load_stage(0); asm volatile("cp.async.commit_group;");
    load_stage(1); asm volatile("cp.async.commit_group;");

    asm volatile("cp.async.wait_group 2;");
    __syncthreads();

    const int a_row_in = lane & 15;
    const int a_ksel   = (lane >> 4) * 16;
    const int b_sel    = (lane >> 3) & 3;
    const int b_row_in = ((b_sel >> 1) << 3) + (lane & 7);
    const int b_ksel   = (b_sel & 1) * 16;

    uint32_t qh[4][4];
    {
        uint32_t qa = sb + (wid * 16 + a_row_in) * QROW + a_ksel;
        #pragma unroll
        for (int kf = 0; kf < 4; kf++)
            ldsm_x4(qh[kf], qa + kf * 32);
    }

    float o[8][4];
    #pragma unroll
    for (int f = 0; f < 8; f++)
        #pragma unroll
        for (int e = 0; e < 4; e++) o[f][e] = 0.0f;
    float m0r = -INFINITY, m1r = -INFINITY, l0r = 0.0f, l1r = 0.0f;

    const float sscale = 0.125f * 1.44269504088896f;

    for (int kbi = 0; kbi < ANB; kbi++) {
        if (kbi == ANB - 1) { asm volatile("cp.async.wait_group 0;"); }
        else                { asm volatile("cp.async.wait_group 1;"); }
        __syncthreads();
        if (kbi + 2 < ANB) {
            load_stage(kbi + 2);
            asm volatile("cp.async.commit_group;");
        }

        const uint32_t sK = sb + QBYTES + (kbi % 3) * ASTG;
        const uint32_t sV = sK + KTILE;

        // ---- scores ----
        float sc[8][4];
        #pragma unroll
        for (int f = 0; f < 8; f++)
            #pragma unroll
            for (int e = 0; e < 4; e++) sc[f][e] = 0.0f;

        #pragma unroll
        for (int kf = 0; kf < 4; kf++) {
            #pragma unroll
            for (int fn2 = 0; fn2 < 4; fn2++) {
                uint32_t bfr[4];
                ldsm_x4(bfr, sK + (fn2 * 16 + b_row_in) * KROW + kf * 32 + b_ksel);
                mma16816h(sc[fn2 * 2 + 0], qh[kf], bfr[0], bfr[1]);
                mma16816h(sc[fn2 * 2 + 1], qh[kf], bfr[2], bfr[3]);
            }
        }

        // ---- online softmax ----
        #pragma unroll
        for (int f = 0; f < 8; f++)
            #pragma unroll
            for (int e = 0; e < 4; e++) sc[f][e] *= sscale;

        float mx0 = -INFINITY, mx1 = -INFINITY;
        #pragma unroll
        for (int f = 0; f < 8; f++) {
            mx0 = fmaxf(mx0, fmaxf(sc[f][0], sc[f][1]));
            mx1 = fmaxf(mx1, fmaxf(sc[f][2], sc[f][3]));
        }
        mx0 = fmaxf(mx0, __shfl_xor_sync(0xffffffffu, mx0, 1));
        mx0 = fmaxf(mx0, __shfl_xor_sync(0xffffffffu, mx0, 2));
        mx1 = fmaxf(mx1, __shfl_xor_sync(0xffffffffu, mx1, 1));
        mx1 = fmaxf(mx1, __shfl_xor_sync(0xffffffffu, mx1, 2));

        float mn0 = fmaxf(m0r, mx0), mn1 = fmaxf(m1r, mx1);
        float c0 = exp2f(m0r - mn0), c1 = exp2f(m1r - mn1);

        float rs0 = 0.0f, rs1 = 0.0f;
        #pragma unroll
        for (int f = 0; f < 8; f++) {
            sc[f][0] = exp2f(sc[f][0] - mn0); rs0 += sc[f][0];
            sc[f][1] = exp2f(sc[f][1] - mn0); rs0 += sc[f][1];
            sc[f][2] = exp2f(sc[f][2] - mn1); rs1 += sc[f][2];
            sc[f][3] = exp2f(sc[f][3] - mn1); rs1 += sc[f][3];
        }
        rs0 += __shfl_xor_sync(0xffffffffu, rs0, 1);
        rs0 += __shfl_xor_sync(0xffffffffu, rs0, 2);
        rs1 += __shfl_xor_sync(0xffffffffu, rs1, 1);
        rs1 += __shfl_xor_sync(0xffffffffu, rs1, 2);

        l0r = l0r * c0 + rs0;
        l1r = l1r * c1 + rs1;
        m0r = mn0; m1r = mn1;
        #pragma unroll
        for (int f = 0; f < 8; f++) {
            o[f][0] *= c0; o[f][1] *= c0;
            o[f][2] *= c1; o[f][3] *= c1;
        }

        // ---- PV ----
        #pragma unroll
        for (int j = 0; j < 4; j++) {
            uint32_t a[4];
            __half2 t;
            t = __floats2half2_rn(sc[2 * j][0],     sc[2 * j][1]);     a[0] = *(uint32_t*)&t;
            t = __floats2half2_rn(sc[2 * j][2],     sc[2 * j][3]);     a[1] = *(uint32_t*)&t;
            t = __floats2half2_rn(sc[2 * j + 1][0], sc[2 * j + 1][1]); a[2] = *(uint32_t*)&t;
            t = __floats2half2_rn(sc[2 * j + 1][2], sc[2 * j + 1][3]); a[3] = *(uint32_t*)&t;
            #pragma unroll
            for (int fn2 = 0; fn2 < 4; fn2++) {
                uint32_t bfr[4];
                ldsm_x4(bfr, sV + (fn2 * 16 + b_row_in) * VROW + j * 32 + b_ksel);
                mma16816h(o[fn2 * 2 + 0], a, bfr[0], bfr[1]);
                mma16816h(o[fn2 * 2 + 1], a, bfr[2], bfr[3]);
            }
        }
    }

    // ---- epilogue: write ctxc fp16 hi/lo (split-2, exact) ----
    const float inv0 = 1.0f / l0r, inv1 = 1.0f / l1r;
    const int rowg = b * S_ + m0 + wid * 16 + (lane >> 2);
    const int colb = h * 64 + 2 * (lane & 3);
    #pragma unroll
    for (int f = 0; f < 8; f++) {
        int col = colb + 8 * f;
        float v[2][2] = {{o[f][0] * inv0, o[f][1] * inv0},
                         {o[f][2] * inv1, o[f][3] * inv1}};
        #pragma unroll
        for (int rr = 0; rr < 2; rr++) {
            __half h0 = __float2half_rn(v[rr][0]);
            __half h1 = __float2half_rn(v[rr][1]);
            float l0 = v[rr][0] - __half2float(h0);
            float l1 = v[rr][1] - __half2float(h1);
            size_t base = (size_t)(rowg + rr * 8) * 4096 + col;
            *(__half2*)(g_ctxc + base)        = __half2(h0, h1);
            *(__half2*)(g_ctxc + base + 2048) = __floats2half2_rn(l0, l1);
        }
    }
}

// ---------------------------------------------------------------------------
// Launch
// ---------------------------------------------------------------------------
extern "C" void kernel_launch(void* const* d_in, const int* in_sizes, int n_in,
                              void* d_out, int out_size)
{
    const float* x  = (const float*)d_in[0];
    const float* Wq = (const float*)d_in[1];
    const float* bq = (const float*)d_in[2];
    const float* Wk = (const float*)d_in[3];
    const float* bk = (const float*)d_in[4];
    const float* Wv = (const float*)d_in[5];
    const float* bv = (const float*)d_in[6];
    const float* Wo = (const float*)d_in[7];
    const float* bo = (const float*)d_in[8];
    float* out = (float*)d_out;

    __half *xch, *ctxc, *wqkvh, *woth;
    cudaGetSymbolAddress((void**)&xch,   g_xch);
    cudaGetSymbolAddress((void**)&ctxc,  g_ctxc);
    cudaGetSymbolAddress((void**)&wqkvh, g_wqkvh);
    cudaGetSymbolAddress((void**)&woth,  g_woth);

    cudaFuncSetAttribute(gemm_mma_kernel<256, 4>,
                         cudaFuncAttributeMaxDynamicSharedMemorySize, GEMM_SMEM_256);
    cudaFuncSetAttribute(gemm_mma_kernel<256, 5>,
                         cudaFuncAttributeMaxDynamicSharedMemorySize, GEMM_SMEM_256);
    cudaFuncSetAttribute(attn_mma_kernel,
                         cudaFuncAttributeMaxDynamicSharedMemorySize, ATT_SMEM);

    // input conversions (all fp16)
    convert_rows_h_kernel<<<2048, 256>>>(x, xch, M_ * D_, D_);
    convert_transpose_h_kernel<<<dim3(D_ / 32,   D_ / 32), dim3(32, 8)>>>(
        Wq, wqkvh, D_);
    convert_transpose_h_kernel<<<dim3(KVD_ / 32, D_ / 32), dim3(32, 8)>>>(
        Wk, wqkvh + (size_t)D_ * D_, KVD_);
    convert_transpose_h_kernel<<<dim3(KVD_ / 32, D_ / 32), dim3(32, 8)>>>(
        Wv, wqkvh + (size_t)(D_ + KVD_) * D_, KVD_);
    convert_transpose_h_kernel<<<dim3(D_ / 32,   D_ / 32), dim3(32, 8)>>>(
        Wo, woth, D_);

    // fused QKV projection (fp16 split-2 x, fp16 weights; routes to attn layouts)
    gemm_mma_kernel<256, 4><<<dim3(NQKV / 256, M_ / 128), 256, GEMM_SMEM_256>>>(
        xch, wqkvh, bq, bk, bv, nullptr, NQKV);

    // attention (fp16 throughout; writes ctxc fp16 hi/lo)
    attn_mma_kernel<<<dim3(S_ / 128, B_ * H_), 256, ATT_SMEM>>>();

    // output projection (fp16 split-2 ctx x fp16 Wo)
    gemm_mma_kernel<256, 5><<<dim3(D_ / 256, M_ / 128), 256, GEMM_SMEM_256>>>(
        ctxc, woth, bo, nullptr, nullptr, out, D_);
}

// round 15
// speedup vs baseline: 6.0594x; 1.1631x over previous
#include <cuda_runtime.h>
#include <cuda_bf16.h>
#include <cuda_fp16.h>
#include <cstdint>
#include <math.h>

// Problem constants
constexpr int B_   = 2;
constexpr int S_   = 2048;
constexpr int D_   = 2048;
constexpr int H_   = 32;
constexpr int HKV_ = 8;
constexpr int DH_  = 64;
constexpr int M_   = B_ * S_;       // 4096 rows
constexpr int KVD_ = HKV_ * DH_;    // 512
constexpr int NQKV = D_ + 2 * KVD_; // 3072

// GEMM operands (__device__ globals: allocation-free rule)
__device__ __half g_xch  [M_ * 2 * D_];    // x fp16 hi|lo (split-2, exact)
__device__ __half g_ctxh [M_ * D_];        // ctx fp16 single
__device__ __half g_wqkvh[NQKV * D_];      // Wq|Wk|Wv fp16 single, N-major [3072][2048]
__device__ __half g_woth [D_ * D_];        // Wo fp16 single, N-major [2048][2048]

// attention operands (written directly by GEMM epilogues)
__device__ __half g_qb[B_ * H_   * S_ * 64];   // [b,h][m][d] fp16
__device__ __half g_kb[B_ * HKV_ * S_ * 64];   // [b,kvh][n][d] fp16
__device__ __half g_vt[B_ * HKV_ * 64 * S_];   // [b,kvh][d][n] fp16 (V^T)

__device__ __forceinline__ uint32_t smem_u32_of(const void* p) {
    uint32_t a;
    asm("{ .reg .u64 t; cvta.to.shared.u64 t, %1; cvt.u32.u64 %0, t; }" : "=r"(a) : "l"(p));
    return a;
}
__device__ __forceinline__ void ldsm_x4(uint32_t (&r)[4], uint32_t addr) {
    asm volatile("ldmatrix.sync.aligned.m8n8.x4.shared.b16 {%0,%1,%2,%3}, [%4];"
                 : "=r"(r[0]), "=r"(r[1]), "=r"(r[2]), "=r"(r[3]) : "r"(addr));
}
__device__ __forceinline__ void mma16816h(float (&c)[4], const uint32_t (&a)[4],
                                          uint32_t b0, uint32_t b1) {
    asm volatile(
        "mma.sync.aligned.m16n8k16.row.col.f32.f16.f16.f32 "
        "{%0,%1,%2,%3}, {%4,%5,%6,%7}, {%8,%9}, {%0,%1,%2,%3};"
        : "+f"(c[0]), "+f"(c[1]), "+f"(c[2]), "+f"(c[3])
        : "r"(a[0]), "r"(a[1]), "r"(a[2]), "r"(a[3]), "r"(b0), "r"(b1));
}
__device__ __forceinline__ void cp16(uint32_t dst, const void* src) {
    asm volatile("cp.async.cg.shared.global [%0], [%1], 16;" :: "r"(dst), "l"(src));
}

// ---------------------------------------------------------------------------
// Conversion kernels (inputs only)
// ---------------------------------------------------------------------------
__global__ void convert_rows_h_kernel(const float* __restrict__ src,
                                      __half* __restrict__ dst, int total, int K)
{
    for (int i = blockIdx.x * blockDim.x + threadIdx.x; i < total;
         i += gridDim.x * blockDim.x) {
        int m = i / K, k = i - m * K;
        float x = src[i];
        __half h = __float2half_rn(x);
        float lo = x - __half2float(h);
        dst[(size_t)m * 2 * K + k]     = h;
        dst[(size_t)m * 2 * K + K + k] = __float2half_rn(lo);
    }
}

// W [K=2048][N] f32 -> Wt fp16 [N][2048]
__global__ void convert_transpose_h_kernel(const float* __restrict__ W,
                                           __half* __restrict__ Wt, int N)
{
    __shared__ float tile[32][33];
    int k0 = blockIdx.y * 32, n0 = blockIdx.x * 32;
    int tx = threadIdx.x, ty = threadIdx.y;
    #pragma unroll
    for (int dy = 0; dy < 32; dy += 8)
        tile[ty + dy][tx] = W[(size_t)(k0 + ty + dy) * N + n0 + tx];
    __syncthreads();
    #pragma unroll
    for (int dy = 0; dy < 32; dy += 8) {
        int n = n0 + ty + dy;
        Wt[(size_t)n * D_ + k0 + tx] = __float2half_rn(tile[tx][ty + dy]);
    }
}

// ---------------------------------------------------------------------------
// HMMA GEMM (all fp16), BK=64/stage, 3-stage cp.async, fused epilogues.
// MODE 4 = QKV: A = xch [M][4096] hi|lo (K'=4096), routes -> g_qb/g_kb/g_vt
// MODE 5 = O:   A = ctxh [M][2048] single (K'=2048), f32+bias -> C
// ---------------------------------------------------------------------------
constexpr int A_ROW_B  = 144;                 // 128B data + 16B pad
constexpr int A_TILE_B = 128 * A_ROW_B;       // 18432

template<int BN, int MODE>
__global__ __launch_bounds__(256, 1)
void gemm_mma_kernel(const __half* __restrict__ A,
                     const __half* __restrict__ Bt,
                     const float* __restrict__ bias,
                     const float* __restrict__ bias2,
                     const float* __restrict__ bias3,
                     float* __restrict__ C, int Ndim)
{
    constexpr int NKC    = (MODE == 4) ? 64 : 32;
    constexpr int A_RS   = (MODE == 4) ? 4096 : 2048;   // A row stride (elements)
    constexpr int COLS_W = BN / 4;
    constexpr int NF2    = COLS_W / 16;
    constexpr int B_TILE = BN * A_ROW_B;
    constexpr int STAGE  = A_TILE_B + B_TILE;

    extern __shared__ __align__(128) char smem[];
    const uint32_t smem_b = smem_u32_of(smem);
    const int tid  = threadIdx.x;
    const int lane = tid & 31, wid = tid >> 5;
    const int warp_m = wid & 1;
    const int warp_n = wid >> 1;
    const int bm = blockIdx.y * 128;
    const int bn = blockIdx.x * BN;

    float acc[4][2 * NF2][4];
    #pragma unroll
    for (int i = 0; i < 4; i++)
        #pragma unroll
        for (int j = 0; j < 2 * NF2; j++)
            #pragma unroll
            for (int e = 0; e < 4; e++) acc[i][j][e] = 0.0f;

    auto load_stage = [&](int kc) {
        int slot = kc % 3;
        int seg = kc >> 5, within = (kc & 31) * 64;
        int a_col = (MODE == 4) ? (within + seg * 2048) : within;
        int w_col = within;
        uint32_t sA = smem_b + slot * STAGE;
        uint32_t sB = sA + A_TILE_B;
        #pragma unroll
        for (int it = 0; it < 4; it++) {
            int idx = tid + it * 256;
            int r = idx >> 3, c = idx & 7;
            cp16(sA + r * A_ROW_B + c * 16, A + (size_t)(bm + r) * A_RS + a_col + c * 8);
        }
        #pragma unroll
        for (int it = 0; it < BN / 32; it++) {
            int idx = tid + it * 256;
            int r = idx >> 3, c = idx & 7;
            cp16(sB + r * A_ROW_B + c * 16, Bt + (size_t)(bn + r) * 2048 + w_col + c * 8);
        }
    };

    load_stage(0); asm volatile("cp.async.commit_group;");
    load_stage(1); asm volatile("cp.async.commit_group;");

    const int a_row_in = lane & 15;
    const int a_ksel   = (lane >> 4) * 16;
    const int b_sel    = (lane >> 3) & 3;
    const int b_row_in = ((b_sel >> 1) << 3) + (lane & 7);
    const int b_ksel   = (b_sel & 1) * 16;

    for (int kc = 0; kc < NKC; kc++) {
        asm volatile("cp.async.wait_group 1;");
        __syncthreads();
        if (kc + 2 < NKC) {
            load_stage(kc + 2);
            asm volatile("cp.async.commit_group;");
        }

        int slot = kc % 3;
        uint32_t sA = smem_b + slot * STAGE + (warp_m * 64) * A_ROW_B;
        uint32_t sB = smem_b + slot * STAGE + A_TILE_B + (warp_n * COLS_W) * A_ROW_B;

        #pragma unroll
        for (int kk = 0; kk < 4; kk++) {
            uint32_t kbyte = kk * 32;
            uint32_t afr[4][4];
            #pragma unroll
            for (int fm = 0; fm < 4; fm++)
                ldsm_x4(afr[fm], sA + (fm * 16 + a_row_in) * A_ROW_B + kbyte + a_ksel);
            #pragma unroll
            for (int fn2 = 0; fn2 < NF2; fn2++) {
                uint32_t bfr[4];
                ldsm_x4(bfr, sB + (fn2 * 16 + b_row_in) * A_ROW_B + kbyte + b_ksel);
                #pragma unroll
                for (int fm = 0; fm < 4; fm++) {
                    mma16816h(acc[fm][fn2 * 2 + 0], afr[fm], bfr[0], bfr[1]);
                    mma16816h(acc[fm][fn2 * 2 + 1], afr[fm], bfr[2], bfr[3]);
                }
            }
        }
    }

    // ---- fused epilogue ----
    const int row0 = bm + warp_m * 64 + (lane >> 2);
    const int col0 = bn + warp_n * COLS_W + (lane & 3) * 2;
    #pragma unroll
    for (int fm = 0; fm < 4; fm++) {
        #pragma unroll
        for (int fn = 0; fn < 2 * NF2; fn++) {
            const int c = col0 + fn * 8;
            const int r0 = row0 + fm * 16;
            if (MODE == 5) {
                const float b0 = bias[c], b1 = bias[c + 1];
                *(float2*)(C + (size_t)r0 * Ndim + c) =
                    make_float2(acc[fm][fn][0] + b0, acc[fm][fn][1] + b1);
                *(float2*)(C + (size_t)(r0 + 8) * Ndim + c) =
                    make_float2(acc[fm][fn][2] + b0, acc[fm][fn][3] + b1);
            } else {  // MODE 4: route by section
                float b0, b1;
                if (c < 2048)      { b0 = bias [c];        b1 = bias [c + 1]; }
                else if (c < 2560) { b0 = bias2[c - 2048]; b1 = bias2[c - 2047]; }
                else               { b0 = bias3[c - 2560]; b1 = bias3[c - 2559]; }
                float w[2][2] = {{acc[fm][fn][0] + b0, acc[fm][fn][1] + b1},
                                 {acc[fm][fn][2] + b0, acc[fm][fn][3] + b1}};
                if (c < 2560) {
                    const bool isQ = (c < 2048);
                    const int cc   = isQ ? c : (c - 2048);
                    const int NH   = isQ ? 32 : 8;
                    __half* dst = isQ ? g_qb : g_kb;
                    const int hh = cc >> 6, d = cc & 63;
                    #pragma unroll
                    for (int rr = 0; rr < 2; rr++) {
                        int r = r0 + rr * 8;
                        int b = r >> 11, mm = r & 2047;
                        size_t base = ((size_t)(b * NH + hh) * 2048 + mm) * 64 + d;
                        *(__half2*)(dst + base) = __floats2half2_rn(w[rr][0], w[rr][1]);
                    }
                } else {
                    const int cc = c - 2560;
                    const int kvh = cc >> 6, d = cc & 63;
                    #pragma unroll
                    for (int rr = 0; rr < 2; rr++) {
                        int r = r0 + rr * 8;
                        int b = r >> 11, mm = r & 2047;
                        size_t base = ((size_t)(b * 8 + kvh) * 64 + d) * 2048 + mm;
                        g_vt[base]        = __float2half_rn(w[rr][0]);
                        g_vt[base + 2048] = __float2half_rn(w[rr][1]);
                    }
                }
            }
        }
    }
}

constexpr int GEMM_SMEM_256 = 3 * (A_TILE_B + 256 * A_ROW_B);  // 165888

// ---------------------------------------------------------------------------
// Flash attention (validated R11/R13): Q,K,P,V fp16. 2 CTAs/SM.
// ---------------------------------------------------------------------------
constexpr int ANB     = S_ / 64;
constexpr int QROW    = 144;
constexpr int KROW    = 144;
constexpr int VROW    = 144;
constexpr int QBYTES  = 128 * QROW;     // 18432
constexpr int KTILE   = 64 * KROW;
constexpr int VTILE   = 64 * VROW;
constexpr int ASTG    = KTILE + VTILE;  // 18432
constexpr int ATT_SMEM = QBYTES + 3 * ASTG;  // 73728

__global__ __launch_bounds__(256, 2)
void attn_mma_kernel()
{
    extern __shared__ __align__(128) char smem[];
    const uint32_t sb = smem_u32_of(smem);
    const int tid  = threadIdx.x;
    const int lane = tid & 31, wid = tid >> 5;

    const int bh  = blockIdx.y;
    const int b   = bh >> 5;
    const int h   = bh & 31;
    const int kvh = h >> 2;
    const int bk  = b * HKV_ + kvh;
    const int m0  = blockIdx.x * 128;

    const __half* qbase = g_qb + ((size_t)bh * S_ + m0) * 64;
    const __half* kbase = g_kb + ((size_t)bk * S_) * 64;
    const __half* vbase = g_vt + ((size_t)bk * 64) * (size_t)S_;

    #pragma unroll
    for (int it = 0; it < 4; it++) {
        int idx = tid + it * 256;
        int r = idx >> 3, c = idx & 7;
        cp16(sb + r * QROW + c * 16, qbase + (size_t)r * 64 + c * 8);
    }
    asm volatile("cp.async.commit_group;");

    auto load_stage = [&](int kbi) {
        int slot = kbi % 3;
        int n0 = kbi * 64;
        uint32_t sK = sb + QBYTES + slot * ASTG;
        uint32_t sV = sK + KTILE;
        #pragma unroll
        for (int it = 0; it < 2; it++) {
            int idx = tid + it * 256;
            int r = idx >> 3, c = idx & 7;
            cp16(sK + r * KROW + c * 16, kbase + (size_t)(n0 + r) * 64 + c * 8);
        }
        #pragma unroll
        for (int it = 0; it < 2; it++) {
            int idx = tid + it * 256;
            int r = idx >> 3, c = idx & 7;
            cp16(sV + r * VROW + c * 16, vbase + (size_t)r * S_ + n0 + c * 8);
        }
    };
    load_stage(0); asm volatile("cp.async.commit_group;");
    load_stage(1); asm volatile("cp.async.commit_group;");

    asm volatile("cp.async.wait_group 2;");
    __syncthreads();

    const int a_row_in = lane & 15;
    const int a_ksel   = (lane >> 4) * 16;
    const int b_sel    = (lane >> 3) & 3;
    const int b_row_in = ((b_sel >> 1) << 3) + (lane & 7);
    const int b_ksel   = (b_sel & 1) * 16;

    uint32_t qh[4][4];
    {
        uint32_t qa = sb + (wid * 16 + a_row_in) * QROW + a_ksel;
        #pragma unroll
        for (int kf = 0; kf < 4; kf++)
            ldsm_x4(qh[kf], qa + kf * 32);
    }

    float o[8][4];
    #pragma unroll
    for (int f = 0; f < 8; f++)
        #pragma unroll
        for (int e = 0; e < 4; e++) o[f][e] = 0.0f;
    float m0r = -INFINITY, m1r = -INFINITY, l0r = 0.0f, l1r = 0.0f;

    const float sscale = 0.125f * 1.44269504088896f;

    for (int kbi = 0; kbi < ANB; kbi++) {
        if (kbi == ANB - 1) { asm volatile("cp.async.wait_group 0;"); }
        else                { asm volatile("cp.async.wait_group 1;"); }
        __syncthreads();
        if (kbi + 2 < ANB) {
            load_stage(kbi + 2);
            asm volatile("cp.async.commit_group;");
        }

        const uint32_t sK = sb + QBYTES + (kbi % 3) * ASTG;
        const uint32_t sV = sK + KTILE;

        // ---- scores ----
        float sc[8][4];
        #pragma unroll
        for (int f = 0; f < 8; f++)
            #pragma unroll
            for (int e = 0; e < 4; e++) sc[f][e] = 0.0f;

        #pragma unroll
        for (int kf = 0; kf < 4; kf++) {
            #pragma unroll
            for (int fn2 = 0; fn2 < 4; fn2++) {
                uint32_t bfr[4];
                ldsm_x4(bfr, sK + (fn2 * 16 + b_row_in) * KROW + kf * 32 + b_ksel);
                mma16816h(sc[fn2 * 2 + 0], qh[kf], bfr[0], bfr[1]);
                mma16816h(sc[fn2 * 2 + 1], qh[kf], bfr[2], bfr[3]);
            }
        }

        // ---- online softmax ----
        #pragma unroll
        for (int f = 0; f < 8; f++)
            #pragma unroll
            for (int e = 0; e < 4; e++) sc[f][e] *= sscale;

        float mx0 = -INFINITY, mx1 = -INFINITY;
        #pragma unroll
        for (int f = 0; f < 8; f++) {
            mx0 = fmaxf(mx0, fmaxf(sc[f][0], sc[f][1]));
            mx1 = fmaxf(mx1, fmaxf(sc[f][2], sc[f][3]));
        }
        mx0 = fmaxf(mx0, __shfl_xor_sync(0xffffffffu, mx0, 1));
        mx0 = fmaxf(mx0, __shfl_xor_sync(0xffffffffu, mx0, 2));
        mx1 = fmaxf(mx1, __shfl_xor_sync(0xffffffffu, mx1, 1));
        mx1 = fmaxf(mx1, __shfl_xor_sync(0xffffffffu, mx1, 2));

        float mn0 = fmaxf(m0r, mx0), mn1 = fmaxf(m1r, mx1);
        float c0 = exp2f(m0r - mn0), c1 = exp2f(m1r - mn1);

        float rs0 = 0.0f, rs1 = 0.0f;
        #pragma unroll
        for (int f = 0; f < 8; f++) {
            sc[f][0] = exp2f(sc[f][0] - mn0); rs0 += sc[f][0];
            sc[f][1] = exp2f(sc[f][1] - mn0); rs0 += sc[f][1];
            sc[f][2] = exp2f(sc[f][2] - mn1); rs1 += sc[f][2];
            sc[f][3] = exp2f(sc[f][3] - mn1); rs1 += sc[f][3];
        }
        rs0 += __shfl_xor_sync(0xffffffffu, rs0, 1);
        rs0 += __shfl_xor_sync(0xffffffffu, rs0, 2);
        rs1 += __shfl_xor_sync(0xffffffffu, rs1, 1);
        rs1 += __shfl_xor_sync(0xffffffffu, rs1, 2);

        l0r = l0r * c0 + rs0;
        l1r = l1r * c1 + rs1;
        m0r = mn0; m1r = mn1;
        #pragma unroll
        for (int f = 0; f < 8; f++) {
            o[f][0] *= c0; o[f][1] *= c0;
            o[f][2] *= c1; o[f][3] *= c1;
        }

        // ---- PV ----
        #pragma unroll
        for (int j = 0; j < 4; j++) {
            uint32_t a[4];
            __half2 t;
            t = __floats2half2_rn(sc[2 * j][0],     sc[2 * j][1]);     a[0] = *(uint32_t*)&t;
            t = __floats2half2_rn(sc[2 * j][2],     sc[2 * j][3]);     a[1] = *(uint32_t*)&t;
            t = __floats2half2_rn(sc[2 * j + 1][0], sc[2 * j + 1][1]); a[2] = *(uint32_t*)&t;
            t = __floats2half2_rn(sc[2 * j + 1][2], sc[2 * j + 1][3]); a[3] = *(uint32_t*)&t;
            #pragma unroll
            for (int fn2 = 0; fn2 < 4; fn2++) {
                uint32_t bfr[4];
                ldsm_x4(bfr, sV + (fn2 * 16 + b_row_in) * VROW + j * 32 + b_ksel);
                mma16816h(o[fn2 * 2 + 0], a, bfr[0], bfr[1]);
                mma16816h(o[fn2 * 2 + 1], a, bfr[2], bfr[3]);
            }
        }
    }

    // ---- epilogue: write ctx fp16 single ----
    const float inv0 = 1.0f / l0r, inv1 = 1.0f / l1r;
    const int rowg = b * S_ + m0 + wid * 16 + (lane >> 2);
    const int colb = h * 64 + 2 * (lane & 3);
    #pragma unroll
    for (int f = 0; f < 8; f++) {
        int col = colb + 8 * f;
        *(__half2*)(g_ctxh + (size_t)rowg * 2048 + col) =
            __floats2half2_rn(o[f][0] * inv0, o[f][1] * inv0);
        *(__half2*)(g_ctxh + (size_t)(rowg + 8) * 2048 + col) =
            __floats2half2_rn(o[f][2] * inv1, o[f][3] * inv1);
    }
}

// ---------------------------------------------------------------------------
// Launch
// ---------------------------------------------------------------------------
extern "C" void kernel_launch(void* const* d_in, const int* in_sizes, int n_in,
                              void* d_out, int out_size)
{
    const float* x  = (const float*)d_in[0];
    const float* Wq = (const float*)d_in[1];
    const float* bq = (const float*)d_in[2];
    const float* Wk = (const float*)d_in[3];
    const float* bk = (const float*)d_in[4];
    const float* Wv = (const float*)d_in[5];
    const float* bv = (const float*)d_in[6];
    const float* Wo = (const float*)d_in[7];
    const float* bo = (const float*)d_in[8];
    float* out = (float*)d_out;

    __half *xch, *ctxh, *wqkvh, *woth;
    cudaGetSymbolAddress((void**)&xch,   g_xch);
    cudaGetSymbolAddress((void**)&ctxh,  g_ctxh);
    cudaGetSymbolAddress((void**)&wqkvh, g_wqkvh);
    cudaGetSymbolAddress((void**)&woth,  g_woth);

    cudaFuncSetAttribute(gemm_mma_kernel<256, 4>,
                         cudaFuncAttributeMaxDynamicSharedMemorySize, GEMM_SMEM_256);
    cudaFuncSetAttribute(gemm_mma_kernel<256, 5>,
                         cudaFuncAttributeMaxDynamicSharedMemorySize, GEMM_SMEM_256);
    cudaFuncSetAttribute(attn_mma_kernel,
                         cudaFuncAttributeMaxDynamicSharedMemorySize, ATT_SMEM);

    // input conversions (all fp16)
    convert_rows_h_kernel<<<2048, 256>>>(x, xch, M_ * D_, D_);
    convert_transpose_h_kernel<<<dim3(D_ / 32,   D_ / 32), dim3(32, 8)>>>(
        Wq, wqkvh, D_);
    convert_transpose_h_kernel<<<dim3(KVD_ / 32, D_ / 32), dim3(32, 8)>>>(
        Wk, wqkvh + (size_t)D_ * D_, KVD_);
    convert_transpose_h_kernel<<<dim3(KVD_ / 32, D_ / 32), dim3(32, 8)>>>(
        Wv, wqkvh + (size_t)(D_ + KVD_) * D_, KVD_);
    convert_transpose_h_kernel<<<dim3(D_ / 32,   D_ / 32), dim3(32, 8)>>>(
        Wo, woth, D_);

    // fused QKV projection (fp16 split-2 x, fp16 weights; routes to attn layouts)
    gemm_mma_kernel<256, 4><<<dim3(NQKV / 256, M_ / 128), 256, GEMM_SMEM_256>>>(
        xch, wqkvh, bq, bk, bv, nullptr, NQKV);

    // attention (fp16 throughout; writes ctx fp16 single; 2 CTAs/SM)
    attn_mma_kernel<<<dim3(S_ / 128, B_ * H_), 256, ATT_SMEM>>>();

    // output projection (fp16 single ctx x fp16 Wo, K'=2048)
    gemm_mma_kernel<256, 5><<<dim3(D_ / 256, M_ / 128), 256, GEMM_SMEM_256>>>(
        ctxh, woth, bo, nullptr, nullptr, out, D_);
}

// round 17
// speedup vs baseline: 7.9361x; 1.3097x over previous
#include <cuda_runtime.h>
#include <cuda_bf16.h>
#include <cuda_fp16.h>
#include <cstdint>
#include <math.h>

// Problem constants
constexpr int B_   = 2;
constexpr int S_   = 2048;
constexpr int D_   = 2048;
constexpr int H_   = 32;
constexpr int HKV_ = 8;
constexpr int DH_  = 64;
constexpr int M_   = B_ * S_;       // 4096 rows
constexpr int KVD_ = HKV_ * DH_;    // 512
constexpr int NQKV = D_ + 2 * KVD_; // 3072

// GEMM operands (__device__ globals: allocation-free rule)
__device__ __half g_xh   [M_ * D_];        // x fp16 single
__device__ __half g_ctxh [M_ * D_];        // ctx fp16 single
__device__ __half g_wqkvh[NQKV * D_];      // Wq|Wk|Wv fp16 single, N-major [3072][2048]
__device__ __half g_woth [D_ * D_];        // Wo fp16 single, N-major [2048][2048]

// attention operands (written directly by GEMM epilogues)
__device__ __half g_qb[B_ * H_   * S_ * 64];   // [b,h][m][d] fp16
__device__ __half g_kb[B_ * HKV_ * S_ * 64];   // [b,kvh][n][d] fp16
__device__ __half g_vt[B_ * HKV_ * 64 * S_];   // [b,kvh][d][n] fp16 (V^T)

__device__ __forceinline__ uint32_t smem_u32_of(const void* p) {
    uint32_t a;
    asm("{ .reg .u64 t; cvta.to.shared.u64 t, %1; cvt.u32.u64 %0, t; }" : "=r"(a) : "l"(p));
    return a;
}
__device__ __forceinline__ void ldsm_x4(uint32_t (&r)[4], uint32_t addr) {
    asm volatile("ldmatrix.sync.aligned.m8n8.x4.shared.b16 {%0,%1,%2,%3}, [%4];"
                 : "=r"(r[0]), "=r"(r[1]), "=r"(r[2]), "=r"(r[3]) : "r"(addr));
}
__device__ __forceinline__ void mma16816h(float (&c)[4], const uint32_t (&a)[4],
                                          uint32_t b0, uint32_t b1) {
    asm volatile(
        "mma.sync.aligned.m16n8k16.row.col.f32.f16.f16.f32 "
        "{%0,%1,%2,%3}, {%4,%5,%6,%7}, {%8,%9}, {%0,%1,%2,%3};"
        : "+f"(c[0]), "+f"(c[1]), "+f"(c[2]), "+f"(c[3])
        : "r"(a[0]), "r"(a[1]), "r"(a[2]), "r"(a[3]), "r"(b0), "r"(b1));
}
__device__ __forceinline__ void cp16(uint32_t dst, const void* src) {
    asm volatile("cp.async.cg.shared.global [%0], [%1], 16;" :: "r"(dst), "l"(src));
}

// ---------------------------------------------------------------------------
// Conversion kernels (inputs only)
// ---------------------------------------------------------------------------
// f32 -> fp16 single (vectorized)
__global__ void convert_h_kernel(const float* __restrict__ src,
                                 __half* __restrict__ dst, int total)
{
    for (int i = blockIdx.x * blockDim.x + threadIdx.x; i * 4 < total;
         i += gridDim.x * blockDim.x) {
        float4 v = *(const float4*)(src + i * 4);
        __half2 h0 = __floats2half2_rn(v.x, v.y);
        __half2 h1 = __floats2half2_rn(v.z, v.w);
        *(__half2*)(dst + i * 4)     = h0;
        *(__half2*)(dst + i * 4 + 2) = h1;
    }
}

// W [K=2048][N] f32 -> Wt fp16 [N][2048]
__global__ void convert_transpose_h_kernel(const float* __restrict__ W,
                                           __half* __restrict__ Wt, int N)
{
    __shared__ float tile[32][33];
    int k0 = blockIdx.y * 32, n0 = blockIdx.x * 32;
    int tx = threadIdx.x, ty = threadIdx.y;
    #pragma unroll
    for (int dy = 0; dy < 32; dy += 8)
        tile[ty + dy][tx] = W[(size_t)(k0 + ty + dy) * N + n0 + tx];
    __syncthreads();
    #pragma unroll
    for (int dy = 0; dy < 32; dy += 8) {
        int n = n0 + ty + dy;
        Wt[(size_t)n * D_ + k0 + tx] = __float2half_rn(tile[tx][ty + dy]);
    }
}

// ---------------------------------------------------------------------------
// HMMA GEMM (all fp16 single), K'=2048, BK=64/stage, 32 iters, 3-stage
// cp.async. MODE 4 = fused QKV routing -> g_qb/g_kb/g_vt ; MODE 5 = f32+bias
// ---------------------------------------------------------------------------
constexpr int A_ROW_B  = 144;                 // 128B data + 16B pad
constexpr int A_TILE_B = 128 * A_ROW_B;       // 18432
constexpr int GEMM_NKC = 32;                  // 2048 / 64

template<int BN, int MODE>
__global__ __launch_bounds__(256, 1)
void gemm_mma_kernel(const __half* __restrict__ A,
                     const __half* __restrict__ Bt,
                     const float* __restrict__ bias,
                     const float* __restrict__ bias2,
                     const float* __restrict__ bias3,
                     float* __restrict__ C, int Ndim)
{
    constexpr int COLS_W = BN / 4;
    constexpr int NF2    = COLS_W / 16;
    constexpr int B_TILE = BN * A_ROW_B;
    constexpr int STAGE  = A_TILE_B + B_TILE;

    extern __shared__ __align__(128) char smem[];
    const uint32_t smem_b = smem_u32_of(smem);
    const int tid  = threadIdx.x;
    const int lane = tid & 31, wid = tid >> 5;
    const int warp_m = wid & 1;
    const int warp_n = wid >> 1;
    const int bm = blockIdx.y * 128;
    const int bn = blockIdx.x * BN;

    float acc[4][2 * NF2][4];
    #pragma unroll
    for (int i = 0; i < 4; i++)
        #pragma unroll
        for (int j = 0; j < 2 * NF2; j++)
            #pragma unroll
            for (int e = 0; e < 4; e++) acc[i][j][e] = 0.0f;

    auto load_stage = [&](int kc) {
        int slot = kc % 3;
        int col = kc * 64;
        uint32_t sA = smem_b + slot * STAGE;
        uint32_t sB = sA + A_TILE_B;
        #pragma unroll
        for (int it = 0; it < 4; it++) {
            int idx = tid + it * 256;
            int r = idx >> 3, c = idx & 7;
            cp16(sA + r * A_ROW_B + c * 16, A + (size_t)(bm + r) * 2048 + col + c * 8);
        }
        #pragma unroll
        for (int it = 0; it < BN / 32; it++) {
            int idx = tid + it * 256;
            int r = idx >> 3, c = idx & 7;
            cp16(sB + r * A_ROW_B + c * 16, Bt + (size_t)(bn + r) * 2048 + col + c * 8);
        }
    };

    load_stage(0); asm volatile("cp.async.commit_group;");
    load_stage(1); asm volatile("cp.async.commit_group;");

    const int a_row_in = lane & 15;
    const int a_ksel   = (lane >> 4) * 16;
    const int b_sel    = (lane >> 3) & 3;
    const int b_row_in = ((b_sel >> 1) << 3) + (lane & 7);
    const int b_ksel   = (b_sel & 1) * 16;

    for (int kc = 0; kc < GEMM_NKC; kc++) {
        asm volatile("cp.async.wait_group 1;");
        __syncthreads();
        if (kc + 2 < GEMM_NKC) {
            load_stage(kc + 2);
            asm volatile("cp.async.commit_group;");
        }

        int slot = kc % 3;
        uint32_t sA = smem_b + slot * STAGE + (warp_m * 64) * A_ROW_B;
        uint32_t sB = smem_b + slot * STAGE + A_TILE_B + (warp_n * COLS_W) * A_ROW_B;

        #pragma unroll
        for (int kk = 0; kk < 4; kk++) {
            uint32_t kbyte = kk * 32;
            uint32_t afr[4][4];
            #pragma unroll
            for (int fm = 0; fm < 4; fm++)
                ldsm_x4(afr[fm], sA + (fm * 16 + a_row_in) * A_ROW_B + kbyte + a_ksel);
            #pragma unroll
            for (int fn2 = 0; fn2 < NF2; fn2++) {
                uint32_t bfr[4];
                ldsm_x4(bfr, sB + (fn2 * 16 + b_row_in) * A_ROW_B + kbyte + b_ksel);
                #pragma unroll
                for (int fm = 0; fm < 4; fm++) {
                    mma16816h(acc[fm][fn2 * 2 + 0], afr[fm], bfr[0], bfr[1]);
                    mma16816h(acc[fm][fn2 * 2 + 1], afr[fm], bfr[2], bfr[3]);
                }
            }
        }
    }

    // ---- fused epilogue ----
    const int row0 = bm + warp_m * 64 + (lane >> 2);
    const int col0 = bn + warp_n * COLS_W + (lane & 3) * 2;
    #pragma unroll
    for (int fm = 0; fm < 4; fm++) {
        #pragma unroll
        for (int fn = 0; fn < 2 * NF2; fn++) {
            const int c = col0 + fn * 8;
            const int r0 = row0 + fm * 16;
            if (MODE == 5) {
                const float b0 = bias[c], b1 = bias[c + 1];
                *(float2*)(C + (size_t)r0 * Ndim + c) =
                    make_float2(acc[fm][fn][0] + b0, acc[fm][fn][1] + b1);
                *(float2*)(C + (size_t)(r0 + 8) * Ndim + c) =
                    make_float2(acc[fm][fn][2] + b0, acc[fm][fn][3] + b1);
            } else {  // MODE 4: route by section
                float b0, b1;
                if (c < 2048)      { b0 = bias [c];        b1 = bias [c + 1]; }
                else if (c < 2560) { b0 = bias2[c - 2048]; b1 = bias2[c - 2047]; }
                else               { b0 = bias3[c - 2560]; b1 = bias3[c - 2559]; }
                float w[2][2] = {{acc[fm][fn][0] + b0, acc[fm][fn][1] + b1},
                                 {acc[fm][fn][2] + b0, acc[fm][fn][3] + b1}};
                if (c < 2560) {
                    const bool isQ = (c < 2048);
                    const int cc   = isQ ? c : (c - 2048);
                    const int NH   = isQ ? 32 : 8;
                    __half* dst = isQ ? g_qb : g_kb;
                    const int hh = cc >> 6, d = cc & 63;
                    #pragma unroll
                    for (int rr = 0; rr < 2; rr++) {
                        int r = r0 + rr * 8;
                        int b = r >> 11, mm = r & 2047;
                        size_t base = ((size_t)(b * NH + hh) * 2048 + mm) * 64 + d;
                        *(__half2*)(dst + base) = __floats2half2_rn(w[rr][0], w[rr][1]);
                    }
                } else {
                    const int cc = c - 2560;
                    const int kvh = cc >> 6, d = cc & 63;
                    #pragma unroll
                    for (int rr = 0; rr < 2; rr++) {
                        int r = r0 + rr * 8;
                        int b = r >> 11, mm = r & 2047;
                        size_t base = ((size_t)(b * 8 + kvh) * 64 + d) * 2048 + mm;
                        g_vt[base]        = __float2half_rn(w[rr][0]);
                        g_vt[base + 2048] = __float2half_rn(w[rr][1]);
                    }
                }
            }
        }
    }
}

constexpr int GEMM_SMEM_256 = 3 * (A_TILE_B + 256 * A_ROW_B);  // 165888

// ---------------------------------------------------------------------------
// Flash attention (validated R11/R13/R15): Q,K,P,V fp16. 2 CTAs/SM.
// ---------------------------------------------------------------------------
constexpr int ANB     = S_ / 64;
constexpr int QROW    = 144;
constexpr int KROW    = 144;
constexpr int VROW    = 144;
constexpr int QBYTES  = 128 * QROW;     // 18432
constexpr int KTILE   = 64 * KROW;
constexpr int VTILE   = 64 * VROW;
constexpr int ASTG    = KTILE + VTILE;  // 18432
constexpr int ATT_SMEM = QBYTES + 3 * ASTG;  // 73728

__global__ __launch_bounds__(256, 2)
void attn_mma_kernel()
{
    extern __shared__ __align__(128) char smem[];
    const uint32_t sb = smem_u32_of(smem);
    const int tid  = threadIdx.x;
    const int lane = tid & 31, wid = tid >> 5;

    const int bh  = blockIdx.y;
    const int b   = bh >> 5;
    const int h   = bh & 31;
    const int kvh = h >> 2;
    const int bk  = b * HKV_ + kvh;
    const int m0  = blockIdx.x * 128;

    const __half* qbase = g_qb + ((size_t)bh * S_ + m0) * 64;
    const __half* kbase = g_kb + ((size_t)bk * S_) * 64;
    const __half* vbase = g_vt + ((size_t)bk * 64) * (size_t)S_;

    #pragma unroll
    for (int it = 0; it < 4; it++) {
        int idx = tid + it * 256;
        int r = idx >> 3, c = idx & 7;
        cp16(sb + r * QROW + c * 16, qbase + (size_t)r * 64 + c * 8);
    }
    asm volatile("cp.async.commit_group;");

    auto load_stage = [&](int kbi) {
        int slot = kbi % 3;
        int n0 = kbi * 64;
        uint32_t sK = sb + QBYTES + slot * ASTG;
        uint32_t sV = sK + KTILE;
        #pragma unroll
        for (int it = 0; it < 2; it++) {
            int idx = tid + it * 256;
            int r = idx >> 3, c = idx & 7;
            cp16(sK + r * KROW + c * 16, kbase + (size_t)(n0 + r) * 64 + c * 8);
        }
        #pragma unroll
        for (int it = 0; it < 2; it++) {
            int idx = tid + it * 256;
            int r = idx >> 3, c = idx & 7;
            cp16(sV + r * VROW + c * 16, vbase + (size_t)r * S_ + n0 + c * 8);
        }
    };
    load_stage(0); asm volatile("cp.async.commit_group;");
    load_stage(1); asm volatile("cp.async.commit_group;");

    asm volatile("cp.async.wait_group 2;");
    __syncthreads();

    const int a_row_in = lane & 15;
    const int a_ksel   = (lane >> 4) * 16;
    const int b_sel    = (lane >> 3) & 3;
    const int b_row_in = ((b_sel >> 1) << 3) + (lane & 7);
    const int b_ksel   = (b_sel & 1) * 16;

    uint32_t qh[4][4];
    {
        uint32_t qa = sb + (wid * 16 + a_row_in) * QROW + a_ksel;
        #pragma unroll
        for (int kf = 0; kf < 4; kf++)
            ldsm_x4(qh[kf], qa + kf * 32);
    }

    float o[8][4];
    #pragma unroll
    for (int f = 0; f < 8; f++)
        #pragma unroll
        for (int e = 0; e < 4; e++) o[f][e] = 0.0f;
    float m0r = -INFINITY, m1r = -INFINITY, l0r = 0.0f, l1r = 0.0f;

    const float sscale = 0.125f * 1.44269504088896f;

    for (int kbi = 0; kbi < ANB; kbi++) {
        if (kbi == ANB - 1) { asm volatile("cp.async.wait_group 0;"); }
        else                { asm volatile("cp.async.wait_group 1;"); }
        __syncthreads();
        if (kbi + 2 < ANB) {
            load_stage(kbi + 2);
            asm volatile("cp.async.commit_group;");
        }

        const uint32_t sK = sb + QBYTES + (kbi % 3) * ASTG;
        const uint32_t sV = sK + KTILE;

        // ---- scores ----
        float sc[8][4];
        #pragma unroll
        for (int f = 0; f < 8; f++)
            #pragma unroll
            for (int e = 0; e < 4; e++) sc[f][e] = 0.0f;

        #pragma unroll
        for (int kf = 0; kf < 4; kf++) {
            #pragma unroll
            for (int fn2 = 0; fn2 < 4; fn2++) {
                uint32_t bfr[4];
                ldsm_x4(bfr, sK + (fn2 * 16 + b_row_in) * KROW + kf * 32 + b_ksel);
                mma16816h(sc[fn2 * 2 + 0], qh[kf], bfr[0], bfr[1]);
                mma16816h(sc[fn2 * 2 + 1], qh[kf], bfr[2], bfr[3]);
            }
        }

        // ---- online softmax ----
        #pragma unroll
        for (int f = 0; f < 8; f++)
            #pragma unroll
            for (int e = 0; e < 4; e++) sc[f][e] *= sscale;

        float mx0 = -INFINITY, mx1 = -INFINITY;
        #pragma unroll
        for (int f = 0; f < 8; f++) {
            mx0 = fmaxf(mx0, fmaxf(sc[f][0], sc[f][1]));
            mx1 = fmaxf(mx1, fmaxf(sc[f][2], sc[f][3]));
        }
        mx0 = fmaxf(mx0, __shfl_xor_sync(0xffffffffu, mx0, 1));
        mx0 = fmaxf(mx0, __shfl_xor_sync(0xffffffffu, mx0, 2));
        mx1 = fmaxf(mx1, __shfl_xor_sync(0xffffffffu, mx1, 1));
        mx1 = fmaxf(mx1, __shfl_xor_sync(0xffffffffu, mx1, 2));

        float mn0 = fmaxf(m0r, mx0), mn1 = fmaxf(m1r, mx1);
        float c0 = exp2f(m0r - mn0), c1 = exp2f(m1r - mn1);

        float rs0 = 0.0f, rs1 = 0.0f;
        #pragma unroll
        for (int f = 0; f < 8; f++) {
            sc[f][0] = exp2f(sc[f][0] - mn0); rs0 += sc[f][0];
            sc[f][1] = exp2f(sc[f][1] - mn0); rs0 += sc[f][1];
            sc[f][2] = exp2f(sc[f][2] - mn1); rs1 += sc[f][2];
            sc[f][3] = exp2f(sc[f][3] - mn1); rs1 += sc[f][3];
        }
        rs0 += __shfl_xor_sync(0xffffffffu, rs0, 1);
        rs0 += __shfl_xor_sync(0xffffffffu, rs0, 2);
        rs1 += __shfl_xor_sync(0xffffffffu, rs1, 1);
        rs1 += __shfl_xor_sync(0xffffffffu, rs1, 2);

        l0r = l0r * c0 + rs0;
        l1r = l1r * c1 + rs1;
        m0r = mn0; m1r = mn1;
        #pragma unroll
        for (int f = 0; f < 8; f++) {
            o[f][0] *= c0; o[f][1] *= c0;
            o[f][2] *= c1; o[f][3] *= c1;
        }

        // ---- PV ----
        #pragma unroll
        for (int j = 0; j < 4; j++) {
            uint32_t a[4];
            __half2 t;
            t = __floats2half2_rn(sc[2 * j][0],     sc[2 * j][1]);     a[0] = *(uint32_t*)&t;
            t = __floats2half2_rn(sc[2 * j][2],     sc[2 * j][3]);     a[1] = *(uint32_t*)&t;
            t = __floats2half2_rn(sc[2 * j + 1][0], sc[2 * j + 1][1]); a[2] = *(uint32_t*)&t;
            t = __floats2half2_rn(sc[2 * j + 1][2], sc[2 * j + 1][3]); a[3] = *(uint32_t*)&t;
            #pragma unroll
            for (int fn2 = 0; fn2 < 4; fn2++) {
                uint32_t bfr[4];
                ldsm_x4(bfr, sV + (fn2 * 16 + b_row_in) * VROW + j * 32 + b_ksel);
                mma16816h(o[fn2 * 2 + 0], a, bfr[0], bfr[1]);
                mma16816h(o[fn2 * 2 + 1], a, bfr[2], bfr[3]);
            }
        }
    }

    // ---- epilogue: write ctx fp16 single ----
    const float inv0 = 1.0f / l0r, inv1 = 1.0f / l1r;
    const int rowg = b * S_ + m0 + wid * 16 + (lane >> 2);
    const int colb = h * 64 + 2 * (lane & 3);
    #pragma unroll
    for (int f = 0; f < 8; f++) {
        int col = colb + 8 * f;
        *(__half2*)(g_ctxh + (size_t)rowg * 2048 + col) =
            __floats2half2_rn(o[f][0] * inv0, o[f][1] * inv0);
        *(__half2*)(g_ctxh + (size_t)(rowg + 8) * 2048 + col) =
            __floats2half2_rn(o[f][2] * inv1, o[f][3] * inv1);
    }
}

// ---------------------------------------------------------------------------
// Launch
// ---------------------------------------------------------------------------
extern "C" void kernel_launch(void* const* d_in, const int* in_sizes, int n_in,
                              void* d_out, int out_size)
{
    const float* x  = (const float*)d_in[0];
    const float* Wq = (const float*)d_in[1];
    const float* bq = (const float*)d_in[2];
    const float* Wk = (const float*)d_in[3];
    const float* bk = (const float*)d_in[4];
    const float* Wv = (const float*)d_in[5];
    const float* bv = (const float*)d_in[6];
    const float* Wo = (const float*)d_in[7];
    const float* bo = (const float*)d_in[8];
    float* out = (float*)d_out;

    __half *xh, *ctxh, *wqkvh, *woth;
    cudaGetSymbolAddress((void**)&xh,    g_xh);
    cudaGetSymbolAddress((void**)&ctxh,  g_ctxh);
    cudaGetSymbolAddress((void**)&wqkvh, g_wqkvh);
    cudaGetSymbolAddress((void**)&woth,  g_woth);

    cudaFuncSetAttribute(gemm_mma_kernel<256, 4>,
                         cudaFuncAttributeMaxDynamicSharedMemorySize, GEMM_SMEM_256);
    cudaFuncSetAttribute(gemm_mma_kernel<256, 5>,
                         cudaFuncAttributeMaxDynamicSharedMemorySize, GEMM_SMEM_256);
    cudaFuncSetAttribute(attn_mma_kernel,
                         cudaFuncAttributeMaxDynamicSharedMemorySize, ATT_SMEM);

    // input conversions (all fp16 single)
    convert_h_kernel<<<1024, 256>>>(x, xh, M_ * D_);
    convert_transpose_h_kernel<<<dim3(D_ / 32,   D_ / 32), dim3(32, 8)>>>(
        Wq, wqkvh, D_);
    convert_transpose_h_kernel<<<dim3(KVD_ / 32, D_ / 32), dim3(32, 8)>>>(
        Wk, wqkvh + (size_t)D_ * D_, KVD_);
    convert_transpose_h_kernel<<<dim3(KVD_ / 32, D_ / 32), dim3(32, 8)>>>(
        Wv, wqkvh + (size_t)(D_ + KVD_) * D_, KVD_);
    convert_transpose_h_kernel<<<dim3(D_ / 32,   D_ / 32), dim3(32, 8)>>>(
        Wo, woth, D_);

    // fused QKV projection (fp16 x fp16, K'=2048; routes to attn layouts)
    gemm_mma_kernel<256, 4><<<dim3(NQKV / 256, M_ / 128), 256, GEMM_SMEM_256>>>(
        xh, wqkvh, bq, bk, bv, nullptr, NQKV);

    // attention (fp16 throughout; writes ctx fp16 single; 2 CTAs/SM)
    attn_mma_kernel<<<dim3(S_ / 128, B_ * H_), 256, ATT_SMEM>>>();

    // output projection (fp16 ctx x fp16 Wo, K'=2048)
    gemm_mma_kernel<256, 5><<<dim3(D_ / 256, M_ / 128), 256, GEMM_SMEM_256>>>(
        ctxh, woth, bo, nullptr, nullptr, out, D_);
}